// round 5
// baseline (speedup 1.0000x reference)
#include <cuda_runtime.h>
#include <cuda_bf16.h>
#include <math.h>
#include <stdint.h>

// Problem constants
#define BB 2
#define TT 2048
#define CC 1024
#define HH 16
#define HS 64
#define MM (BB*TT)       // 4096

// GEMM tiling (mma.sync bf16)
#define CTA_M 128
#define CTA_N 128
#define KSTG  32                 // K elems per smem stage
#define NS    (CC/KSTG)          // 32 stages
#define GSTGB 40960              // bytes per pipeline stage (4 tiles x 128x40 bf16)
#define GSMEM (2*GSTGB)

// Flash tiling
#define FBM 128                  // q rows per CTA
#define FBN 64                   // kv rows per tile
#define FSTR 72                  // padded smem row stride (bf16)
#define FQB  36864               // Q region bytes (2 x 128 x 72 bf16)
#define FKVB 36864               // KV stage bytes (4 x 64 x 72 bf16)
#define FSMEM (FQB + 2*FKVB)     // 110592

// Scratch (device globals: allocation-free)
__device__ float g_q[BB*HH*TT*HS];     // [B,H,T,HS] fp32 (pre-RoPE)
__device__ float g_k[BB*HH*TT*HS];
__device__ float g_v[BB*HH*TT*HS];
__device__ float g_cos[TT*32];
__device__ float g_sin[TT*32];

// bf16 hi/lo split staging
__device__ __nv_bfloat16 g_xhi[MM*CC];
__device__ __nv_bfloat16 g_xlo[MM*CC];
__device__ __nv_bfloat16 g_yhi[MM*CC];
__device__ __nv_bfloat16 g_ylo[MM*CC];
__device__ __nv_bfloat16 g_wthi[4*CC*CC];   // transposed [n][k]: wq,wk,wv,wc
__device__ __nv_bfloat16 g_wtlo[4*CC*CC];
// attention operand splits [B,H,T,HS]
__device__ __nv_bfloat16 g_qhi[BB*HH*TT*HS];
__device__ __nv_bfloat16 g_qlo[BB*HH*TT*HS];
__device__ __nv_bfloat16 g_khi[BB*HH*TT*HS];
__device__ __nv_bfloat16 g_klo[BB*HH*TT*HS];
__device__ __nv_bfloat16 g_vhi[BB*HH*TT*HS];
__device__ __nv_bfloat16 g_vlo[BB*HH*TT*HS];

// ---------------------------------------------------------------------------
// PTX helpers (family-wide sm_80+ only)
// ---------------------------------------------------------------------------
__device__ __forceinline__ uint32_t smem_u32(const void* p) {
    uint32_t a;
    asm("{ .reg .u64 t; cvta.to.shared.u64 t, %1; cvt.u32.u64 %0, t; }" : "=r"(a) : "l"(p));
    return a;
}
__device__ __forceinline__ void ldsm_x4(uint32_t* r, uint32_t addr) {
    asm volatile("ldmatrix.sync.aligned.m8n8.x4.shared.b16 {%0,%1,%2,%3}, [%4];"
        : "=r"(r[0]), "=r"(r[1]), "=r"(r[2]), "=r"(r[3]) : "r"(addr));
}
__device__ __forceinline__ void ldsm_x2t(uint32_t* r, uint32_t addr) {
    asm volatile("ldmatrix.sync.aligned.m8n8.x2.trans.shared.b16 {%0,%1}, [%2];"
        : "=r"(r[0]), "=r"(r[1]) : "r"(addr));
}
__device__ __forceinline__ void mma_bf16(float* c, const uint32_t* a, const uint32_t* b) {
    asm volatile(
        "mma.sync.aligned.m16n8k16.row.col.f32.bf16.bf16.f32 "
        "{%0,%1,%2,%3}, {%4,%5,%6,%7}, {%8,%9}, {%0,%1,%2,%3};"
        : "+f"(c[0]), "+f"(c[1]), "+f"(c[2]), "+f"(c[3])
        : "r"(a[0]), "r"(a[1]), "r"(a[2]), "r"(a[3]), "r"(b[0]), "r"(b[1]));
}
__device__ __forceinline__ uint32_t pack_bf16x2(float lo, float hi) {
    __nv_bfloat162 v = __floats2bfloat162_rn(lo, hi);
    return *(uint32_t*)&v;
}
__device__ __forceinline__ void cp_async16(uint32_t dst, const void* src) {
    asm volatile("cp.async.cg.shared.global [%0], [%1], 16;" :: "r"(dst), "l"(src));
}
__device__ __forceinline__ void cp_commit() {
    asm volatile("cp.async.commit_group;" ::: "memory");
}
__device__ __forceinline__ void cp_wait(int more) {
    if (more) asm volatile("cp.async.wait_group 1;" ::: "memory");
    else      asm volatile("cp.async.wait_group 0;" ::: "memory");
}

// ---------------------------------------------------------------------------
// RoPE tables
// ---------------------------------------------------------------------------
__global__ void rope_tables_kernel() {
    int idx = blockIdx.x * blockDim.x + threadIdx.x;   // t*32 + i
    if (idx >= TT * 32) return;
    int i = idx & 31;
    int t = idx >> 5;
    double invf_d = exp(-(double)i * (log(10000.0) / 32.0));
    float invf = (float)invf_d;
    float arg_f = (float)t * invf;
    double s, c;
    sincos((double)arg_f, &s, &c);
    g_cos[idx] = (float)c;
    g_sin[idx] = (float)s;
}

// ---------------------------------------------------------------------------
// fp32 -> bf16 hi/lo split, vectorized x4
// ---------------------------------------------------------------------------
__global__ void split_bf16_kernel(const float* __restrict__ src,
                                  __nv_bfloat16* __restrict__ hi,
                                  __nv_bfloat16* __restrict__ lo, int n4) {
    int i = blockIdx.x * blockDim.x + threadIdx.x;
    if (i >= n4) return;
    float4 v = ((const float4*)src)[i];
    float vv[4] = {v.x, v.y, v.z, v.w};
    __nv_bfloat162 h01, h23, l01, l23;
    __nv_bfloat16 h[4], l[4];
    #pragma unroll
    for (int j = 0; j < 4; j++) {
        h[j] = __float2bfloat16(vv[j]);
        l[j] = __float2bfloat16(vv[j] - __bfloat162float(h[j]));
    }
    h01.x = h[0]; h01.y = h[1]; h23.x = h[2]; h23.y = h[3];
    l01.x = l[0]; l01.y = l[1]; l23.x = l[2]; l23.y = l[3];
    ((__nv_bfloat162*)hi)[2*i]   = h01;
    ((__nv_bfloat162*)hi)[2*i+1] = h23;
    ((__nv_bfloat162*)lo)[2*i]   = l01;
    ((__nv_bfloat162*)lo)[2*i+1] = l23;
}

// ---------------------------------------------------------------------------
// Weight transpose + split: Wt[n][k] = split(W[k][n]); grid.z selects matrix
// ---------------------------------------------------------------------------
__global__ void wt_split_kernel(const float* __restrict__ wq, const float* __restrict__ wk,
                                const float* __restrict__ wv, const float* __restrict__ wc) {
    __shared__ float tile[32][33];
    int wsel = blockIdx.z;
    const float* W = (wsel == 0) ? wq : (wsel == 1) ? wk : (wsel == 2) ? wv : wc;
    __nv_bfloat16* Whi = g_wthi + (size_t)wsel * CC * CC;
    __nv_bfloat16* Wlo = g_wtlo + (size_t)wsel * CC * CC;
    int k0 = blockIdx.x * 32, n0 = blockIdx.y * 32;
    int tx = threadIdx.x, ty = threadIdx.y;   // (32,8)
    #pragma unroll
    for (int j = 0; j < 4; j++)
        tile[ty + 8*j][tx] = W[(size_t)(k0 + ty + 8*j) * CC + n0 + tx];
    __syncthreads();
    #pragma unroll
    for (int j = 0; j < 4; j++) {
        float v = tile[tx][ty + 8*j];
        __nv_bfloat16 h = __float2bfloat16(v);
        __nv_bfloat16 l = __float2bfloat16(v - __bfloat162float(h));
        size_t o = (size_t)(n0 + ty + 8*j) * CC + k0 + tx;
        Whi[o] = h;
        Wlo[o] = l;
    }
}

// ---------------------------------------------------------------------------
// cp.async-pipelined mma.sync bf16 GEMM with 3-MMA split.
// D = A @ B^T (+bias), B stored [n][k]. CTA 128x128, 8 warps 2x4,
// 2-stage cp.async ring, K staged 32.
// Stage layout (bytes): Ah @0, Al @10240, Bh @20480, Bl @30720 (row stride 80B)
// ---------------------------------------------------------------------------
__global__ void __launch_bounds__(256, 1) gemm_mma_kernel(
    const __nv_bfloat16* __restrict__ Ahi, const __nv_bfloat16* __restrict__ Alo,
    const __nv_bfloat16* __restrict__ Bhi_all, const __nv_bfloat16* __restrict__ Blo_all,
    const float* __restrict__ bias_q, const float* __restrict__ bias_k,
    const float* __restrict__ bias_v,
    float* __restrict__ o_direct, int qkv_mode)
{
    extern __shared__ __nv_bfloat16 gsm[];
    uint32_t smbase = smem_u32(gsm);

    int tid = threadIdx.x;
    int wid = tid >> 5, lane = tid & 31;
    int wm = wid >> 2, wn = wid & 3;
    int m0 = blockIdx.x * CTA_M;
    int n0 = blockIdx.y * CTA_N;
    int which = blockIdx.z;
    const __nv_bfloat16* Bhi = Bhi_all + (size_t)which * CC * CC;
    const __nv_bfloat16* Blo = Blo_all + (size_t)which * CC * CC;
    const float* bias = qkv_mode ? ((which == 0) ? bias_q : (which == 1) ? bias_k : bias_v)
                                 : bias_q;

    // Per-thread copy slots: 8 x 16B per stage
    const __nv_bfloat16* gsrc[8];
    uint32_t soff[8];                          // byte offset within a stage
    #pragma unroll
    for (int j = 0; j < 8; j++) {
        int sel = j >> 1;                      // 0 Ah, 1 Al, 2 Bh, 3 Bl
        int idx = ((j & 1) << 8) + tid;        // 0..511
        int row = idx >> 2;
        int c16 = (idx & 3) * 8;               // bf16 offset of 16B chunk
        const __nv_bfloat16* base =
            (sel == 0) ? Ahi + (size_t)m0 * CC :
            (sel == 1) ? Alo + (size_t)m0 * CC :
            (sel == 2) ? Bhi + (size_t)n0 * CC :
                         Blo + (size_t)n0 * CC;
        gsrc[j] = base + (size_t)row * CC + c16;
        soff[j] = sel * 10240u + row * 80u + c16 * 2u;
    }

    // ldmatrix base addresses within stage 0
    uint32_t aAh[4], aAl[4], bBh[2], bBl[2];
    {
        int ra = lane & 15;
        int ca8 = ((lane >> 4) & 1) * 8;
        #pragma unroll
        for (int mf = 0; mf < 4; mf++) {
            aAh[mf] = smbase + (wm * 64 + mf * 16 + ra) * 80u + ca8 * 2u;
            aAl[mf] = aAh[mf] + 10240u;
        }
        int rb = ((lane >> 4) & 1) * 8 + (lane & 7);
        int cb8 = ((lane >> 3) & 1) * 8;
        #pragma unroll
        for (int np = 0; np < 2; np++) {
            bBh[np] = smbase + 20480u + (wn * 32 + np * 16 + rb) * 80u + cb8 * 2u;
            bBl[np] = bBh[np] + 10240u;
        }
    }

    float acc[4][4][4] = {};

    // Preload stages 0,1
    #pragma unroll
    for (int j = 0; j < 8; j++) cp_async16(smbase + soff[j], gsrc[j]);
    cp_commit();
    #pragma unroll
    for (int j = 0; j < 8; j++) cp_async16(smbase + GSTGB + soff[j], gsrc[j] + KSTG);
    cp_commit();

    for (int s = 0; s < NS; s++) {
        cp_wait(s < NS - 1);
        __syncthreads();

        uint32_t sb = (s & 1) * GSTGB;
        #pragma unroll
        for (int kk = 0; kk < 2; kk++) {
            uint32_t ah[4][4], al[4][4], bh[2][4], bl[2][4];
            #pragma unroll
            for (int mf = 0; mf < 4; mf++) {
                ldsm_x4(ah[mf], aAh[mf] + sb + kk * 32);
                ldsm_x4(al[mf], aAl[mf] + sb + kk * 32);
            }
            #pragma unroll
            for (int np = 0; np < 2; np++) {
                ldsm_x4(bh[np], bBh[np] + sb + kk * 32);
                ldsm_x4(bl[np], bBl[np] + sb + kk * 32);
            }
            #pragma unroll
            for (int mf = 0; mf < 4; mf++)
                #pragma unroll
                for (int nf = 0; nf < 4; nf++) {
                    const uint32_t* bhf = &bh[nf >> 1][(nf & 1) * 2];
                    const uint32_t* blf = &bl[nf >> 1][(nf & 1) * 2];
                    mma_bf16(acc[mf][nf], ah[mf], bhf);
                    mma_bf16(acc[mf][nf], ah[mf], blf);
                    mma_bf16(acc[mf][nf], al[mf], bhf);
                }
        }
        __syncthreads();
        if (s + 2 < NS) {
            uint32_t db = smbase + (s & 1) * GSTGB;
            #pragma unroll
            for (int j = 0; j < 8; j++)
                cp_async16(db + soff[j], gsrc[j] + (s + 2) * KSTG);
            cp_commit();
        }
    }

    int group = lane >> 2, tig = lane & 3;
    #pragma unroll
    for (int mf = 0; mf < 4; mf++) {
        #pragma unroll
        for (int nf = 0; nf < 4; nf++) {
            int ncol = n0 + wn * 32 + nf * 8 + tig * 2;
            float2 bv = *(const float2*)&bias[ncol];
            #pragma unroll
            for (int half = 0; half < 2; half++) {
                int m = m0 + wm * 64 + mf * 16 + group + half * 8;
                float2 o;
                o.x = acc[mf][nf][half * 2 + 0] + bv.x;
                o.y = acc[mf][nf][half * 2 + 1] + bv.y;
                if (qkv_mode) {
                    float* outp = (which == 0) ? g_q : (which == 1) ? g_k : g_v;
                    int b = m >> 11, t = m & (TT - 1);
                    int h = ncol >> 6, d = ncol & 63;
                    *(float2*)&outp[(((size_t)b * HH + h) * TT + t) * HS + d] = o;
                } else {
                    *(float2*)&o_direct[(size_t)m * CC + ncol] = o;
                }
            }
        }
    }
}

// ---------------------------------------------------------------------------
// RoPE apply + bf16 hi/lo split. Q scaled by 1/sqrt(HS)=0.125 before split.
// ---------------------------------------------------------------------------
__global__ void rope_split_kernel() {
    int idx = blockIdx.x * blockDim.x + threadIdx.x;
    if (idx >= BB * HH * TT * 32) return;
    int i  = idx & 31;
    int t  = (idx >> 5) & (TT - 1);
    int bh = idx >> 16;
    float c = g_cos[(t << 5) + i];
    float s = g_sin[(t << 5) + i];
    int base = (bh * TT + t) * HS + i;

    float q1 = g_q[base], q2 = g_q[base + 32];
    float qa = (q1 * c - q2 * s) * 0.125f;
    float qb = (q2 * c + q1 * s) * 0.125f;
    __nv_bfloat16 h;
    h = __float2bfloat16(qa); g_qhi[base]      = h; g_qlo[base]      = __float2bfloat16(qa - __bfloat162float(h));
    h = __float2bfloat16(qb); g_qhi[base + 32] = h; g_qlo[base + 32] = __float2bfloat16(qb - __bfloat162float(h));

    float k1 = g_k[base], k2 = g_k[base + 32];
    float ka = k1 * c - k2 * s;
    float kb = k2 * c + k1 * s;
    h = __float2bfloat16(ka); g_khi[base]      = h; g_klo[base]      = __float2bfloat16(ka - __bfloat162float(h));
    h = __float2bfloat16(kb); g_khi[base + 32] = h; g_klo[base + 32] = __float2bfloat16(kb - __bfloat162float(h));
}

// ---------------------------------------------------------------------------
// Tensor-core flash attention (causal), cp.async-pipelined KV tiles.
// Smem: Q (Qh@0, Ql@18432B), KV stage p @ FQB + p*FKVB:
//   Kh@0, Kl@9216, Vh@18432, Vl@27648 (row stride 144B)
// ---------------------------------------------------------------------------
__global__ void __launch_bounds__(256) flash_tc_kernel() {
    extern __shared__ __nv_bfloat16 fsm[];
    uint32_t smbase = smem_u32(fsm);

    int qb = blockIdx.x;
    int bh = blockIdx.y;
    int q0 = qb * FBM;
    size_t hbase = (size_t)bh * TT * HS;

    int tid = threadIdx.x;
    int wid = tid >> 5, lane = tid & 31;
    int g = lane >> 2, tig = lane & 3;

    // K/V copy slots: 8 x 16B per tile
    const __nv_bfloat16* kvsrc[8];
    uint32_t koff[8];                          // byte offset within KV stage
    {
        const __nv_bfloat16* bases[4] = {
            g_khi + hbase, g_klo + hbase, g_vhi + hbase, g_vlo + hbase };
        #pragma unroll
        for (int j = 0; j < 8; j++) {
            int c = tid + j * 256;             // 0..2047
            int sel = c >> 9;
            int cc = c & 511;
            int row = cc >> 3;
            int col8 = (cc & 7) * 8;
            kvsrc[j] = bases[sel] + row * HS + col8;
            koff[j] = sel * 9216u + row * 144u + col8 * 2u;
        }
    }

    // Preload KV stages 0,1 (ktmax >= 1 always since FBM=128 covers 2 tiles)
    {
        uint32_t s0 = smbase + FQB, s1 = smbase + FQB + FKVB;
        #pragma unroll
        for (int j = 0; j < 8; j++) cp_async16(s0 + koff[j], kvsrc[j]);
        cp_commit();
        #pragma unroll
        for (int j = 0; j < 8; j++) cp_async16(s1 + koff[j], kvsrc[j] + FBN * HS);
        cp_commit();
    }

    // Stage Q tile (plain stores; covered by first __syncthreads in loop)
    {
        const __nv_bfloat16* Qh = g_qhi + hbase + (size_t)q0 * HS;
        const __nv_bfloat16* Ql = g_qlo + hbase + (size_t)q0 * HS;
        #pragma unroll
        for (int j = 0; j < 4; j++) {
            int c = tid + j * 256;             // 0..1023
            int row = c >> 3;
            int col8 = (c & 7) * 8;
            *(uint4*)&fsm[row * FSTR + col8] = *(const uint4*)&Qh[row * HS + col8];
            *(uint4*)&fsm[9216 + row * FSTR + col8] = *(const uint4*)&Ql[row * HS + col8];
        }
    }

    // ldmatrix base addresses
    uint32_t aQh = smbase + (wid * 16 + (lane & 15)) * 144u + ((lane >> 4) & 1) * 16u;
    uint32_t aQl = aQh + 18432u;
    uint32_t kvs0 = smbase + FQB;
    int rb = ((lane >> 4) & 1) * 8 + (lane & 7);
    int cb8 = ((lane >> 3) & 1) * 8;
    uint32_t aK[4];                            // K pair bases (np: nf pair)
    #pragma unroll
    for (int np = 0; np < 4; np++)
        aK[np] = kvs0 + (np * 16 + rb) * 144u + cb8 * 2u;
    uint32_t aVh = kvs0 + 18432u + (lane & 15) * 144u;

    float m0 = -1e30f, m1 = -1e30f, l0 = 0.f, l1 = 0.f;
    float acc_o[8][4] = {};
    int rw0 = q0 + wid * 16;
    int rq0 = rw0 + g, rq1 = rq0 + 8;

    int ktmax = (q0 + FBM - 1) >> 6;

    for (int kt = 0; kt <= ktmax; kt++) {
        cp_wait(kt < ktmax);
        __syncthreads();

        uint32_t sb = (kt & 1) * FKVB;
        int k0 = kt * FBN;

        // ---- S = Q K^T (3-MMA split) ----
        float s[8][4] = {};
        #pragma unroll
        for (int kc = 0; kc < 4; kc++) {
            uint32_t qh[4], ql[4];
            ldsm_x4(qh, aQh + kc * 32);
            ldsm_x4(ql, aQl + kc * 32);
            #pragma unroll
            for (int np = 0; np < 4; np++) {
                uint32_t kh4[4], kl4[4];
                ldsm_x4(kh4, aK[np] + sb + kc * 32);
                ldsm_x4(kl4, aK[np] + sb + 9216u + kc * 32);
                #pragma unroll
                for (int hf = 0; hf < 2; hf++) {
                    int nf = np * 2 + hf;
                    mma_bf16(s[nf], qh, &kh4[hf * 2]);
                    mma_bf16(s[nf], qh, &kl4[hf * 2]);
                    mma_bf16(s[nf], ql, &kh4[hf * 2]);
                }
            }
        }

        // ---- causal mask (diagonal tiles only) ----
        if (k0 + FBN - 1 > rw0) {
            #pragma unroll
            for (int nf = 0; nf < 8; nf++) {
                int c0 = k0 + nf * 8 + tig * 2;
                if (c0     > rq0) s[nf][0] = -1e30f;
                if (c0 + 1 > rq0) s[nf][1] = -1e30f;
                if (c0     > rq1) s[nf][2] = -1e30f;
                if (c0 + 1 > rq1) s[nf][3] = -1e30f;
            }
        }

        // ---- online softmax (fp32 on fragments) ----
        float mx0 = -1e30f, mx1 = -1e30f;
        #pragma unroll
        for (int nf = 0; nf < 8; nf++) {
            mx0 = fmaxf(mx0, fmaxf(s[nf][0], s[nf][1]));
            mx1 = fmaxf(mx1, fmaxf(s[nf][2], s[nf][3]));
        }
        #pragma unroll
        for (int off = 1; off <= 2; off <<= 1) {
            mx0 = fmaxf(mx0, __shfl_xor_sync(0xffffffffu, mx0, off));
            mx1 = fmaxf(mx1, __shfl_xor_sync(0xffffffffu, mx1, off));
        }
        float mn0 = fmaxf(m0, mx0), mn1 = fmaxf(m1, mx1);
        float sum0 = 0.f, sum1 = 0.f;
        #pragma unroll
        for (int nf = 0; nf < 8; nf++) {
            s[nf][0] = __expf(s[nf][0] - mn0);
            s[nf][1] = __expf(s[nf][1] - mn0);
            s[nf][2] = __expf(s[nf][2] - mn1);
            s[nf][3] = __expf(s[nf][3] - mn1);
            sum0 += s[nf][0] + s[nf][1];
            sum1 += s[nf][2] + s[nf][3];
        }
        #pragma unroll
        for (int off = 1; off <= 2; off <<= 1) {
            sum0 += __shfl_xor_sync(0xffffffffu, sum0, off);
            sum1 += __shfl_xor_sync(0xffffffffu, sum1, off);
        }
        float f0 = __expf(m0 - mn0), f1 = __expf(m1 - mn1);
        l0 = l0 * f0 + sum0; m0 = mn0;
        l1 = l1 * f1 + sum1; m1 = mn1;
        #pragma unroll
        for (int nf = 0; nf < 8; nf++) {
            acc_o[nf][0] *= f0; acc_o[nf][1] *= f0;
            acc_o[nf][2] *= f1; acc_o[nf][3] *= f1;
        }

        // ---- O += P V (split P = Ph + Pl; V pre-split) ----
        #pragma unroll
        for (int jc = 0; jc < 4; jc++) {
            uint32_t aPh[4], aPl[4];
            {
                float p00 = s[2*jc][0],   p01 = s[2*jc][1];
                float p10 = s[2*jc][2],   p11 = s[2*jc][3];
                float p20 = s[2*jc+1][0], p21 = s[2*jc+1][1];
                float p30 = s[2*jc+1][2], p31 = s[2*jc+1][3];
                aPh[0] = pack_bf16x2(p00, p01);
                aPh[1] = pack_bf16x2(p10, p11);
                aPh[2] = pack_bf16x2(p20, p21);
                aPh[3] = pack_bf16x2(p30, p31);
                __nv_bfloat162 b0 = *(__nv_bfloat162*)&aPh[0];
                __nv_bfloat162 b1 = *(__nv_bfloat162*)&aPh[1];
                __nv_bfloat162 b2 = *(__nv_bfloat162*)&aPh[2];
                __nv_bfloat162 b3 = *(__nv_bfloat162*)&aPh[3];
                aPl[0] = pack_bf16x2(p00 - __bfloat162float(b0.x), p01 - __bfloat162float(b0.y));
                aPl[1] = pack_bf16x2(p10 - __bfloat162float(b1.x), p11 - __bfloat162float(b1.y));
                aPl[2] = pack_bf16x2(p20 - __bfloat162float(b2.x), p21 - __bfloat162float(b2.y));
                aPl[3] = pack_bf16x2(p30 - __bfloat162float(b3.x), p31 - __bfloat162float(b3.y));
            }
            #pragma unroll
            for (int nf = 0; nf < 8; nf++) {
                uint32_t vh2[2], vl2[2];
                ldsm_x2t(vh2, aVh + sb + jc * 2304u + nf * 16u);
                ldsm_x2t(vl2, aVh + sb + 9216u + jc * 2304u + nf * 16u);
                mma_bf16(acc_o[nf], aPh, vh2);
                mma_bf16(acc_o[nf], aPh, vl2);
                mma_bf16(acc_o[nf], aPl, vh2);
            }
        }

        __syncthreads();
        if (kt + 2 <= ktmax) {
            uint32_t db = smbase + FQB + (kt & 1) * FKVB;
            #pragma unroll
            for (int j = 0; j < 8; j++)
                cp_async16(db + koff[j], kvsrc[j] + (size_t)(kt + 2) * FBN * HS);
            cp_commit();
        }
    }

    // ---- epilogue: O/l -> g_yhi/g_ylo bf16 split, [B,T,C] ----
    {
        float inv0 = 1.f / l0, inv1 = 1.f / l1;
        int b = bh >> 4, h = bh & 15;
        size_t rb0 = ((size_t)b * TT + rq0) * CC;
        size_t rb1 = ((size_t)b * TT + rq1) * CC;
        #pragma unroll
        for (int nf = 0; nf < 8; nf++) {
            int col = h * HS + nf * 8 + tig * 2;
            float v0 = acc_o[nf][0] * inv0, v1 = acc_o[nf][1] * inv0;
            float v2 = acc_o[nf][2] * inv1, v3 = acc_o[nf][3] * inv1;
            __nv_bfloat162 hh, ll;
            hh.x = __float2bfloat16(v0); hh.y = __float2bfloat16(v1);
            ll.x = __float2bfloat16(v0 - __bfloat162float(hh.x));
            ll.y = __float2bfloat16(v1 - __bfloat162float(hh.y));
            *(__nv_bfloat162*)&g_yhi[rb0 + col] = hh;
            *(__nv_bfloat162*)&g_ylo[rb0 + col] = ll;
            hh.x = __float2bfloat16(v2); hh.y = __float2bfloat16(v3);
            ll.x = __float2bfloat16(v2 - __bfloat162float(hh.x));
            ll.y = __float2bfloat16(v3 - __bfloat162float(hh.y));
            *(__nv_bfloat162*)&g_yhi[rb1 + col] = hh;
            *(__nv_bfloat162*)&g_ylo[rb1 + col] = ll;
        }
    }
}

// ---------------------------------------------------------------------------
extern "C" void kernel_launch(void* const* d_in, const int* in_sizes, int n_in,
                              void* d_out, int out_size) {
    const float* qx = (const float*)d_in[0];
    const float* wq = (const float*)d_in[1];
    const float* bq = (const float*)d_in[2];
    const float* wk = (const float*)d_in[3];
    const float* bk = (const float*)d_in[4];
    const float* wv = (const float*)d_in[5];
    const float* bv = (const float*)d_in[6];
    const float* wc = (const float*)d_in[7];
    const float* bc = (const float*)d_in[8];
    float* out = (float*)d_out;

    // device-global pointers
    float* p_v;            cudaGetSymbolAddress((void**)&p_v, g_v);
    __nv_bfloat16* p_xhi;  cudaGetSymbolAddress((void**)&p_xhi, g_xhi);
    __nv_bfloat16* p_xlo;  cudaGetSymbolAddress((void**)&p_xlo, g_xlo);
    __nv_bfloat16* p_yhi;  cudaGetSymbolAddress((void**)&p_yhi, g_yhi);
    __nv_bfloat16* p_ylo;  cudaGetSymbolAddress((void**)&p_ylo, g_ylo);
    __nv_bfloat16* p_wthi; cudaGetSymbolAddress((void**)&p_wthi, g_wthi);
    __nv_bfloat16* p_wtlo; cudaGetSymbolAddress((void**)&p_wtlo, g_wtlo);
    __nv_bfloat16* p_vhi;  cudaGetSymbolAddress((void**)&p_vhi, g_vhi);
    __nv_bfloat16* p_vlo;  cudaGetSymbolAddress((void**)&p_vlo, g_vlo);

    cudaFuncSetAttribute(gemm_mma_kernel,
                         cudaFuncAttributeMaxDynamicSharedMemorySize, GSMEM);
    cudaFuncSetAttribute(flash_tc_kernel,
                         cudaFuncAttributeMaxDynamicSharedMemorySize, FSMEM);

    rope_tables_kernel<<<(TT * 32 + 255) / 256, 256>>>();

    // Split inputs to bf16 hi/lo
    split_bf16_kernel<<<(MM * CC / 4 + 255) / 256, 256>>>(qx, p_xhi, p_xlo, MM * CC / 4);
    wt_split_kernel<<<dim3(32, 32, 4), dim3(32, 8)>>>(wq, wk, wv, wc);

    // QKV projections (fp32 out g_q/g_k/g_v in [B,H,T,HS] + bias)
    gemm_mma_kernel<<<dim3(MM / CTA_M, CC / CTA_N, 3), 256, GSMEM>>>(
        p_xhi, p_xlo, p_wthi, p_wtlo, bq, bk, bv, nullptr, 1);

    // RoPE + split Q/K; split V
    rope_split_kernel<<<(BB * HH * TT * 32 + 255) / 256, 256>>>();
    split_bf16_kernel<<<(BB * HH * TT * HS / 4 + 255) / 256, 256>>>(
        p_v, p_vhi, p_vlo, BB * HH * TT * HS / 4);

    // Tensor-core flash attention -> g_yhi/g_ylo
    flash_tc_kernel<<<dim3(TT / FBM, BB * HH), 256, FSMEM>>>();

    // Output projection -> d_out
    gemm_mma_kernel<<<dim3(MM / CTA_M, CC / CTA_N, 1), 256, GSMEM>>>(
        p_yhi, p_ylo, p_wthi + (size_t)3 * CC * CC, p_wtlo + (size_t)3 * CC * CC,
        bc, bc, bc, out, 0);
}

// round 6
// speedup vs baseline: 1.0141x; 1.0141x over previous
#include <cuda_runtime.h>
#include <cuda_bf16.h>
#include <math.h>
#include <stdint.h>

// Problem constants
#define BB 2
#define TT 2048
#define CC 1024
#define HH 16
#define HS 64
#define MM (BB*TT)       // 4096

// GEMM tiling (mma.sync bf16), 512 threads, 3-stage cp.async ring
#define CTA_M 128
#define CTA_N 128
#define KSTG  32                 // K elems per smem stage
#define NS    (CC/KSTG)          // 32 stages
#define GSTGB 40960              // bytes per pipeline stage (4 tiles x 128x40 bf16)
#define GSMEM (3*GSTGB)          // 122880

// Flash tiling (R4 version)
#define FBM 128                  // q rows per CTA
#define FBN 64                   // kv rows per tile
#define FSTR 72                  // padded smem row stride (bf16)
#define FSMEM (36864*2)          // bytes

// Scratch (device globals: allocation-free)
__device__ float g_q[BB*HH*TT*HS];     // [B,H,T,HS] fp32 (pre-RoPE)
__device__ float g_k[BB*HH*TT*HS];
__device__ float g_v[BB*HH*TT*HS];
__device__ float g_cos[TT*32];
__device__ float g_sin[TT*32];

// bf16 hi/lo split staging
__device__ __nv_bfloat16 g_xhi[MM*CC];
__device__ __nv_bfloat16 g_xlo[MM*CC];
__device__ __nv_bfloat16 g_yhi[MM*CC];
__device__ __nv_bfloat16 g_ylo[MM*CC];
__device__ __nv_bfloat16 g_wthi[4*CC*CC];   // transposed [n][k]: wq,wk,wv,wc
__device__ __nv_bfloat16 g_wtlo[4*CC*CC];
// attention operand splits [B,H,T,HS]
__device__ __nv_bfloat16 g_qhi[BB*HH*TT*HS];
__device__ __nv_bfloat16 g_qlo[BB*HH*TT*HS];
__device__ __nv_bfloat16 g_khi[BB*HH*TT*HS];
__device__ __nv_bfloat16 g_klo[BB*HH*TT*HS];
__device__ __nv_bfloat16 g_vhi[BB*HH*TT*HS];
__device__ __nv_bfloat16 g_vlo[BB*HH*TT*HS];

// ---------------------------------------------------------------------------
// PTX helpers (family-wide sm_80+ only)
// ---------------------------------------------------------------------------
__device__ __forceinline__ uint32_t smem_u32(const void* p) {
    uint32_t a;
    asm("{ .reg .u64 t; cvta.to.shared.u64 t, %1; cvt.u32.u64 %0, t; }" : "=r"(a) : "l"(p));
    return a;
}
__device__ __forceinline__ void ldsm_x4(uint32_t* r, uint32_t addr) {
    asm volatile("ldmatrix.sync.aligned.m8n8.x4.shared.b16 {%0,%1,%2,%3}, [%4];"
        : "=r"(r[0]), "=r"(r[1]), "=r"(r[2]), "=r"(r[3]) : "r"(addr));
}
__device__ __forceinline__ void ldsm_x2(uint32_t* r, uint32_t addr) {
    asm volatile("ldmatrix.sync.aligned.m8n8.x2.shared.b16 {%0,%1}, [%2];"
        : "=r"(r[0]), "=r"(r[1]) : "r"(addr));
}
__device__ __forceinline__ void ldsm_x2t(uint32_t* r, uint32_t addr) {
    asm volatile("ldmatrix.sync.aligned.m8n8.x2.trans.shared.b16 {%0,%1}, [%2];"
        : "=r"(r[0]), "=r"(r[1]) : "r"(addr));
}
__device__ __forceinline__ void mma_bf16(float* c, const uint32_t* a, const uint32_t* b) {
    asm volatile(
        "mma.sync.aligned.m16n8k16.row.col.f32.bf16.bf16.f32 "
        "{%0,%1,%2,%3}, {%4,%5,%6,%7}, {%8,%9}, {%0,%1,%2,%3};"
        : "+f"(c[0]), "+f"(c[1]), "+f"(c[2]), "+f"(c[3])
        : "r"(a[0]), "r"(a[1]), "r"(a[2]), "r"(a[3]), "r"(b[0]), "r"(b[1]));
}
__device__ __forceinline__ uint32_t pack_bf16x2(float lo, float hi) {
    __nv_bfloat162 v = __floats2bfloat162_rn(lo, hi);
    return *(uint32_t*)&v;
}
__device__ __forceinline__ void cp_async16(uint32_t dst, const void* src) {
    asm volatile("cp.async.cg.shared.global [%0], [%1], 16;" :: "r"(dst), "l"(src));
}
__device__ __forceinline__ void cp_commit() {
    asm volatile("cp.async.commit_group;" ::: "memory");
}
__device__ __forceinline__ void cp_wait(int more) {
    if (more) asm volatile("cp.async.wait_group 1;" ::: "memory");
    else      asm volatile("cp.async.wait_group 0;" ::: "memory");
}

// ---------------------------------------------------------------------------
// RoPE tables
// ---------------------------------------------------------------------------
__global__ void rope_tables_kernel() {
    int idx = blockIdx.x * blockDim.x + threadIdx.x;   // t*32 + i
    if (idx >= TT * 32) return;
    int i = idx & 31;
    int t = idx >> 5;
    double invf_d = exp(-(double)i * (log(10000.0) / 32.0));
    float invf = (float)invf_d;
    float arg_f = (float)t * invf;
    double s, c;
    sincos((double)arg_f, &s, &c);
    g_cos[idx] = (float)c;
    g_sin[idx] = (float)s;
}

// ---------------------------------------------------------------------------
// fp32 -> bf16 hi/lo split, vectorized x4
// ---------------------------------------------------------------------------
__global__ void split_bf16_kernel(const float* __restrict__ src,
                                  __nv_bfloat16* __restrict__ hi,
                                  __nv_bfloat16* __restrict__ lo, int n4) {
    int i = blockIdx.x * blockDim.x + threadIdx.x;
    if (i >= n4) return;
    float4 v = ((const float4*)src)[i];
    float vv[4] = {v.x, v.y, v.z, v.w};
    __nv_bfloat162 h01, h23, l01, l23;
    __nv_bfloat16 h[4], l[4];
    #pragma unroll
    for (int j = 0; j < 4; j++) {
        h[j] = __float2bfloat16(vv[j]);
        l[j] = __float2bfloat16(vv[j] - __bfloat162float(h[j]));
    }
    h01.x = h[0]; h01.y = h[1]; h23.x = h[2]; h23.y = h[3];
    l01.x = l[0]; l01.y = l[1]; l23.x = l[2]; l23.y = l[3];
    ((__nv_bfloat162*)hi)[2*i]   = h01;
    ((__nv_bfloat162*)hi)[2*i+1] = h23;
    ((__nv_bfloat162*)lo)[2*i]   = l01;
    ((__nv_bfloat162*)lo)[2*i+1] = l23;
}

// ---------------------------------------------------------------------------
// Weight transpose + split: Wt[n][k] = split(W[k][n]); grid.z selects matrix
// ---------------------------------------------------------------------------
__global__ void wt_split_kernel(const float* __restrict__ wq, const float* __restrict__ wk,
                                const float* __restrict__ wv, const float* __restrict__ wc) {
    __shared__ float tile[32][33];
    int wsel = blockIdx.z;
    const float* W = (wsel == 0) ? wq : (wsel == 1) ? wk : (wsel == 2) ? wv : wc;
    __nv_bfloat16* Whi = g_wthi + (size_t)wsel * CC * CC;
    __nv_bfloat16* Wlo = g_wtlo + (size_t)wsel * CC * CC;
    int k0 = blockIdx.x * 32, n0 = blockIdx.y * 32;
    int tx = threadIdx.x, ty = threadIdx.y;   // (32,8)
    #pragma unroll
    for (int j = 0; j < 4; j++)
        tile[ty + 8*j][tx] = W[(size_t)(k0 + ty + 8*j) * CC + n0 + tx];
    __syncthreads();
    #pragma unroll
    for (int j = 0; j < 4; j++) {
        float v = tile[tx][ty + 8*j];
        __nv_bfloat16 h = __float2bfloat16(v);
        __nv_bfloat16 l = __float2bfloat16(v - __bfloat162float(h));
        size_t o = (size_t)(n0 + ty + 8*j) * CC + k0 + tx;
        Whi[o] = h;
        Wlo[o] = l;
    }
}

// ---------------------------------------------------------------------------
// 512-thread cp.async-pipelined mma.sync bf16 GEMM with 3-MMA split.
// D = A @ B^T (+bias), B stored [n][k]. CTA 128x128, 16 warps 2(m)x8(n),
// warp tile 64x16, 3-stage ring, one barrier per stage.
// Stage layout (bytes): Ah @0, Al @10240, Bh @20480, Bl @30720 (row stride 80B)
// ---------------------------------------------------------------------------
__global__ void __launch_bounds__(512, 1) gemm_mma_kernel(
    const __nv_bfloat16* __restrict__ Ahi, const __nv_bfloat16* __restrict__ Alo,
    const __nv_bfloat16* __restrict__ Bhi_all, const __nv_bfloat16* __restrict__ Blo_all,
    const float* __restrict__ bias_q, const float* __restrict__ bias_k,
    const float* __restrict__ bias_v,
    float* __restrict__ o_direct, int qkv_mode)
{
    extern __shared__ __nv_bfloat16 gsm[];
    uint32_t smbase = smem_u32(gsm);

    int tid = threadIdx.x;
    int wid = tid >> 5, lane = tid & 31;
    int wm = wid >> 3, wn = wid & 7;           // warp grid 2x8
    int m0 = blockIdx.x * CTA_M;
    int n0 = blockIdx.y * CTA_N;
    int which = blockIdx.z;
    const __nv_bfloat16* Bhi = Bhi_all + (size_t)which * CC * CC;
    const __nv_bfloat16* Blo = Blo_all + (size_t)which * CC * CC;
    const float* bias = qkv_mode ? ((which == 0) ? bias_q : (which == 1) ? bias_k : bias_v)
                                 : bias_q;

    // Per-thread copy slots: 4 x 16B per stage
    const __nv_bfloat16* gsrc[4];
    uint32_t soff[4];
    #pragma unroll
    for (int j = 0; j < 4; j++) {
        int id = tid + j * 512;                // 0..2047
        int sel = id >> 9;                     // 0 Ah, 1 Al, 2 Bh, 3 Bl
        int cc = id & 511;
        int row = cc >> 2;                     // 0..127
        int c16 = (cc & 3) * 8;                // bf16 offset of 16B chunk
        const __nv_bfloat16* base =
            (sel == 0) ? Ahi + (size_t)m0 * CC :
            (sel == 1) ? Alo + (size_t)m0 * CC :
            (sel == 2) ? Bhi + (size_t)n0 * CC :
                         Blo + (size_t)n0 * CC;
        gsrc[j] = base + (size_t)row * CC + c16;
        soff[j] = sel * 10240u + row * 80u + c16 * 2u;
    }

    // ldmatrix base addresses within stage 0
    uint32_t aAh[4], bBh, bBl;
    {
        int ra = lane & 15;
        int ca8 = ((lane >> 4) & 1) * 8;
        #pragma unroll
        for (int mf = 0; mf < 4; mf++)
            aAh[mf] = smbase + (wm * 64 + mf * 16 + ra) * 80u + ca8 * 2u;
        int rb = ((lane >> 4) & 1) * 8 + (lane & 7);
        int cb8 = ((lane >> 3) & 1) * 8;
        bBh = smbase + 20480u + (wn * 16 + rb) * 80u + cb8 * 2u;
        bBl = bBh + 10240u;
    }

    float acc[4][2][4] = {};

    // Preload stages 0,1
    #pragma unroll
    for (int j = 0; j < 4; j++) cp_async16(smbase + soff[j], gsrc[j]);
    cp_commit();
    #pragma unroll
    for (int j = 0; j < 4; j++) cp_async16(smbase + GSTGB + soff[j], gsrc[j] + KSTG);
    cp_commit();

    int buf = 0;                               // stage s lives in buffer s%3
    for (int s = 0; s < NS; s++) {
        cp_wait(s < NS - 1);
        __syncthreads();

        // Prefetch s+2 into the buffer freed at stage s-1
        if (s + 2 < NS) {
            int nb = buf + 2; if (nb >= 3) nb -= 3;
            uint32_t db = smbase + nb * GSTGB;
            #pragma unroll
            for (int j = 0; j < 4; j++)
                cp_async16(db + soff[j], gsrc[j] + (s + 2) * KSTG);
            cp_commit();
        }

        uint32_t sb = buf * GSTGB;
        #pragma unroll
        for (int kk = 0; kk < 2; kk++) {
            uint32_t ah[4][4], al[4][4], bh4[4], bl4[4];
            #pragma unroll
            for (int mf = 0; mf < 4; mf++) {
                ldsm_x4(ah[mf], aAh[mf] + sb + kk * 32);
                ldsm_x4(al[mf], aAh[mf] + sb + 10240u + kk * 32);
            }
            ldsm_x4(bh4, bBh + sb + kk * 32);
            ldsm_x4(bl4, bBl + sb + kk * 32);
            #pragma unroll
            for (int mf = 0; mf < 4; mf++)
                #pragma unroll
                for (int nf = 0; nf < 2; nf++) {
                    mma_bf16(acc[mf][nf], ah[mf], &bh4[nf * 2]);
                    mma_bf16(acc[mf][nf], ah[mf], &bl4[nf * 2]);
                    mma_bf16(acc[mf][nf], al[mf], &bh4[nf * 2]);
                }
        }
        buf++; if (buf == 3) buf = 0;
    }

    int group = lane >> 2, tig = lane & 3;
    #pragma unroll
    for (int mf = 0; mf < 4; mf++) {
        #pragma unroll
        for (int nf = 0; nf < 2; nf++) {
            int ncol = n0 + wn * 16 + nf * 8 + tig * 2;
            float2 bv = *(const float2*)&bias[ncol];
            #pragma unroll
            for (int half = 0; half < 2; half++) {
                int m = m0 + wm * 64 + mf * 16 + group + half * 8;
                float2 o;
                o.x = acc[mf][nf][half * 2 + 0] + bv.x;
                o.y = acc[mf][nf][half * 2 + 1] + bv.y;
                if (qkv_mode) {
                    float* outp = (which == 0) ? g_q : (which == 1) ? g_k : g_v;
                    int b = m >> 11, t = m & (TT - 1);
                    int h = ncol >> 6, d = ncol & 63;
                    *(float2*)&outp[(((size_t)b * HH + h) * TT + t) * HS + d] = o;
                } else {
                    *(float2*)&o_direct[(size_t)m * CC + ncol] = o;
                }
            }
        }
    }
}

// ---------------------------------------------------------------------------
// RoPE apply + bf16 hi/lo split. Q scaled by 1/sqrt(HS)=0.125 before split.
// ---------------------------------------------------------------------------
__global__ void rope_split_kernel() {
    int idx = blockIdx.x * blockDim.x + threadIdx.x;
    if (idx >= BB * HH * TT * 32) return;
    int i  = idx & 31;
    int t  = (idx >> 5) & (TT - 1);
    int bh = idx >> 16;
    float c = g_cos[(t << 5) + i];
    float s = g_sin[(t << 5) + i];
    int base = (bh * TT + t) * HS + i;

    float q1 = g_q[base], q2 = g_q[base + 32];
    float qa = (q1 * c - q2 * s) * 0.125f;
    float qb = (q2 * c + q1 * s) * 0.125f;
    __nv_bfloat16 h;
    h = __float2bfloat16(qa); g_qhi[base]      = h; g_qlo[base]      = __float2bfloat16(qa - __bfloat162float(h));
    h = __float2bfloat16(qb); g_qhi[base + 32] = h; g_qlo[base + 32] = __float2bfloat16(qb - __bfloat162float(h));

    float k1 = g_k[base], k2 = g_k[base + 32];
    float ka = k1 * c - k2 * s;
    float kb = k2 * c + k1 * s;
    h = __float2bfloat16(ka); g_khi[base]      = h; g_klo[base]      = __float2bfloat16(ka - __bfloat162float(h));
    h = __float2bfloat16(kb); g_khi[base + 32] = h; g_klo[base + 32] = __float2bfloat16(kb - __bfloat162float(h));
}

// ---------------------------------------------------------------------------
// Tensor-core flash attention (R4 passing version, unchanged).
// ---------------------------------------------------------------------------
__global__ void __launch_bounds__(256) flash_tc_kernel() {
    extern __shared__ __nv_bfloat16 fsm[];
    __nv_bfloat16* sQh = fsm;                 // 128 x 72
    __nv_bfloat16* sQl = fsm + 9216;
    __nv_bfloat16* sKh = fsm + 18432;         // 64 x 72
    __nv_bfloat16* sKl = fsm + 23040;
    __nv_bfloat16* sVh = fsm + 27648;
    __nv_bfloat16* sVl = fsm + 32256;

    int qb = blockIdx.x;
    int bh = blockIdx.y;
    int q0 = qb * FBM;
    size_t hbase = (size_t)bh * TT * HS;

    int tid = threadIdx.x;
    int wid = tid >> 5, lane = tid & 31;
    int g = lane >> 2, tig = lane & 3;

    // ---- stage Q tile (128x64 x hi/lo) ----
    {
        const __nv_bfloat16* Qh = g_qhi + hbase + (size_t)q0 * HS;
        const __nv_bfloat16* Ql = g_qlo + hbase + (size_t)q0 * HS;
        #pragma unroll
        for (int j = 0; j < 4; j++) {
            int c = tid + j * 256;            // 0..1023
            int row = c >> 3;
            int col8 = (c & 7) * 8;
            *(uint4*)&sQh[row * FSTR + col8] = *(const uint4*)&Qh[row * HS + col8];
            *(uint4*)&sQl[row * FSTR + col8] = *(const uint4*)&Ql[row * HS + col8];
        }
    }

    // K/V copy slots: 8 x uint4 per tile
    const __nv_bfloat16* kvsrc[8];
    __nv_bfloat16* kvdst[8];
    {
        const __nv_bfloat16* bases[4] = {
            g_khi + hbase, g_klo + hbase, g_vhi + hbase, g_vlo + hbase };
        __nv_bfloat16* sb[4] = { sKh, sKl, sVh, sVl };
        #pragma unroll
        for (int j = 0; j < 8; j++) {
            int c = tid + j * 256;            // 0..2047
            int sel = c >> 9;
            int cc = c & 511;
            int row = cc >> 3;
            int col8 = (cc & 7) * 8;
            kvsrc[j] = bases[sel] + row * HS + col8;
            kvdst[j] = sb[sel] + row * FSTR + col8;
        }
    }

    // ldmatrix base addresses
    uint32_t aQh = smem_u32(&sQh[(wid * 16 + (lane & 15)) * FSTR + ((lane >> 4) & 1) * 8]);
    uint32_t aQl = aQh + 9216 * 2;
    uint32_t aKh = smem_u32(&sKh[(lane & 7) * FSTR + ((lane >> 3) & 1) * 8]);
    uint32_t aKl = aKh + 4608 * 2;
    uint32_t aVh = smem_u32(&sVh[(lane & 15) * FSTR]);
    uint32_t aVl = aVh + 4608 * 2;

    float m0 = -1e30f, m1 = -1e30f, l0 = 0.f, l1 = 0.f;
    float acc_o[8][4] = {};
    int rw0 = q0 + wid * 16;                  // warp's min row
    int rq0 = rw0 + g, rq1 = rq0 + 8;

    int ktmax = (q0 + FBM - 1) >> 6;

    uint4 pf[8];
    #pragma unroll
    for (int j = 0; j < 8; j++) pf[j] = *(const uint4*)(kvsrc[j]);

    for (int kt = 0; kt <= ktmax; kt++) {
        __syncthreads();
        #pragma unroll
        for (int j = 0; j < 8; j++) *(uint4*)(kvdst[j]) = pf[j];
        __syncthreads();
        if (kt < ktmax) {
            #pragma unroll
            for (int j = 0; j < 8; j++)
                pf[j] = *(const uint4*)(kvsrc[j] + (size_t)(kt + 1) * FBN * HS);
        }
        int k0 = kt * FBN;

        // ---- S = Q K^T (3-MMA split) ----
        float s[8][4] = {};
        #pragma unroll
        for (int kc = 0; kc < 4; kc++) {
            uint32_t qh[4], ql[4];
            ldsm_x4(qh, aQh + kc * 32);
            ldsm_x4(ql, aQl + kc * 32);
            #pragma unroll
            for (int nf = 0; nf < 8; nf++) {
                uint32_t kh2[2], kl2[2];
                ldsm_x2(kh2, aKh + nf * 1152 + kc * 32);
                ldsm_x2(kl2, aKl + nf * 1152 + kc * 32);
                mma_bf16(s[nf], qh, kh2);
                mma_bf16(s[nf], qh, kl2);
                mma_bf16(s[nf], ql, kh2);
            }
        }

        // ---- causal mask (diagonal tiles only) ----
        if (k0 + FBN - 1 > rw0) {
            #pragma unroll
            for (int nf = 0; nf < 8; nf++) {
                int c0 = k0 + nf * 8 + tig * 2;
                if (c0     > rq0) s[nf][0] = -1e30f;
                if (c0 + 1 > rq0) s[nf][1] = -1e30f;
                if (c0     > rq1) s[nf][2] = -1e30f;
                if (c0 + 1 > rq1) s[nf][3] = -1e30f;
            }
        }

        // ---- online softmax (fp32 on fragments) ----
        float mx0 = -1e30f, mx1 = -1e30f;
        #pragma unroll
        for (int nf = 0; nf < 8; nf++) {
            mx0 = fmaxf(mx0, fmaxf(s[nf][0], s[nf][1]));
            mx1 = fmaxf(mx1, fmaxf(s[nf][2], s[nf][3]));
        }
        #pragma unroll
        for (int off = 1; off <= 2; off <<= 1) {
            mx0 = fmaxf(mx0, __shfl_xor_sync(0xffffffffu, mx0, off));
            mx1 = fmaxf(mx1, __shfl_xor_sync(0xffffffffu, mx1, off));
        }
        float mn0 = fmaxf(m0, mx0), mn1 = fmaxf(m1, mx1);
        float sum0 = 0.f, sum1 = 0.f;
        #pragma unroll
        for (int nf = 0; nf < 8; nf++) {
            s[nf][0] = __expf(s[nf][0] - mn0);
            s[nf][1] = __expf(s[nf][1] - mn0);
            s[nf][2] = __expf(s[nf][2] - mn1);
            s[nf][3] = __expf(s[nf][3] - mn1);
            sum0 += s[nf][0] + s[nf][1];
            sum1 += s[nf][2] + s[nf][3];
        }
        #pragma unroll
        for (int off = 1; off <= 2; off <<= 1) {
            sum0 += __shfl_xor_sync(0xffffffffu, sum0, off);
            sum1 += __shfl_xor_sync(0xffffffffu, sum1, off);
        }
        float f0 = __expf(m0 - mn0), f1 = __expf(m1 - mn1);
        l0 = l0 * f0 + sum0; m0 = mn0;
        l1 = l1 * f1 + sum1; m1 = mn1;
        #pragma unroll
        for (int nf = 0; nf < 8; nf++) {
            acc_o[nf][0] *= f0; acc_o[nf][1] *= f0;
            acc_o[nf][2] *= f1; acc_o[nf][3] *= f1;
        }

        // ---- O += P V (split P = Ph + Pl; V pre-split) ----
        #pragma unroll
        for (int jc = 0; jc < 4; jc++) {
            uint32_t aPh[4], aPl[4];
            {
                float p00 = s[2*jc][0],   p01 = s[2*jc][1];
                float p10 = s[2*jc][2],   p11 = s[2*jc][3];
                float p20 = s[2*jc+1][0], p21 = s[2*jc+1][1];
                float p30 = s[2*jc+1][2], p31 = s[2*jc+1][3];
                aPh[0] = pack_bf16x2(p00, p01);
                aPh[1] = pack_bf16x2(p10, p11);
                aPh[2] = pack_bf16x2(p20, p21);
                aPh[3] = pack_bf16x2(p30, p31);
                __nv_bfloat162 b0 = *(__nv_bfloat162*)&aPh[0];
                __nv_bfloat162 b1 = *(__nv_bfloat162*)&aPh[1];
                __nv_bfloat162 b2 = *(__nv_bfloat162*)&aPh[2];
                __nv_bfloat162 b3 = *(__nv_bfloat162*)&aPh[3];
                aPl[0] = pack_bf16x2(p00 - __bfloat162float(b0.x), p01 - __bfloat162float(b0.y));
                aPl[1] = pack_bf16x2(p10 - __bfloat162float(b1.x), p11 - __bfloat162float(b1.y));
                aPl[2] = pack_bf16x2(p20 - __bfloat162float(b2.x), p21 - __bfloat162float(b2.y));
                aPl[3] = pack_bf16x2(p30 - __bfloat162float(b3.x), p31 - __bfloat162float(b3.y));
            }
            #pragma unroll
            for (int nf = 0; nf < 8; nf++) {
                uint32_t vh2[2], vl2[2];
                ldsm_x2t(vh2, aVh + jc * 2304 + nf * 16);
                ldsm_x2t(vl2, aVl + jc * 2304 + nf * 16);
                mma_bf16(acc_o[nf], aPh, vh2);
                mma_bf16(acc_o[nf], aPh, vl2);
                mma_bf16(acc_o[nf], aPl, vh2);
            }
        }
    }

    // ---- epilogue: O/l -> g_yhi/g_ylo bf16 split, [B,T,C] ----
    {
        float inv0 = 1.f / l0, inv1 = 1.f / l1;
        int b = bh >> 4, h = bh & 15;
        size_t rb0 = ((size_t)b * TT + rq0) * CC;
        size_t rb1 = ((size_t)b * TT + rq1) * CC;
        #pragma unroll
        for (int nf = 0; nf < 8; nf++) {
            int col = h * HS + nf * 8 + tig * 2;
            float v0 = acc_o[nf][0] * inv0, v1 = acc_o[nf][1] * inv0;
            float v2 = acc_o[nf][2] * inv1, v3 = acc_o[nf][3] * inv1;
            __nv_bfloat162 hh, ll;
            hh.x = __float2bfloat16(v0); hh.y = __float2bfloat16(v1);
            ll.x = __float2bfloat16(v0 - __bfloat162float(hh.x));
            ll.y = __float2bfloat16(v1 - __bfloat162float(hh.y));
            *(__nv_bfloat162*)&g_yhi[rb0 + col] = hh;
            *(__nv_bfloat162*)&g_ylo[rb0 + col] = ll;
            hh.x = __float2bfloat16(v2); hh.y = __float2bfloat16(v3);
            ll.x = __float2bfloat16(v2 - __bfloat162float(hh.x));
            ll.y = __float2bfloat16(v3 - __bfloat162float(hh.y));
            *(__nv_bfloat162*)&g_yhi[rb1 + col] = hh;
            *(__nv_bfloat162*)&g_ylo[rb1 + col] = ll;
        }
    }
}

// ---------------------------------------------------------------------------
extern "C" void kernel_launch(void* const* d_in, const int* in_sizes, int n_in,
                              void* d_out, int out_size) {
    const float* qx = (const float*)d_in[0];
    const float* wq = (const float*)d_in[1];
    const float* bq = (const float*)d_in[2];
    const float* wk = (const float*)d_in[3];
    const float* bk = (const float*)d_in[4];
    const float* wv = (const float*)d_in[5];
    const float* bv = (const float*)d_in[6];
    const float* wc = (const float*)d_in[7];
    const float* bc = (const float*)d_in[8];
    float* out = (float*)d_out;

    // device-global pointers
    float* p_v;            cudaGetSymbolAddress((void**)&p_v, g_v);
    __nv_bfloat16* p_xhi;  cudaGetSymbolAddress((void**)&p_xhi, g_xhi);
    __nv_bfloat16* p_xlo;  cudaGetSymbolAddress((void**)&p_xlo, g_xlo);
    __nv_bfloat16* p_yhi;  cudaGetSymbolAddress((void**)&p_yhi, g_yhi);
    __nv_bfloat16* p_ylo;  cudaGetSymbolAddress((void**)&p_ylo, g_ylo);
    __nv_bfloat16* p_wthi; cudaGetSymbolAddress((void**)&p_wthi, g_wthi);
    __nv_bfloat16* p_wtlo; cudaGetSymbolAddress((void**)&p_wtlo, g_wtlo);
    __nv_bfloat16* p_vhi;  cudaGetSymbolAddress((void**)&p_vhi, g_vhi);
    __nv_bfloat16* p_vlo;  cudaGetSymbolAddress((void**)&p_vlo, g_vlo);

    cudaFuncSetAttribute(gemm_mma_kernel,
                         cudaFuncAttributeMaxDynamicSharedMemorySize, GSMEM);
    cudaFuncSetAttribute(flash_tc_kernel,
                         cudaFuncAttributeMaxDynamicSharedMemorySize, FSMEM);

    rope_tables_kernel<<<(TT * 32 + 255) / 256, 256>>>();

    // Split inputs to bf16 hi/lo
    split_bf16_kernel<<<(MM * CC / 4 + 255) / 256, 256>>>(qx, p_xhi, p_xlo, MM * CC / 4);
    wt_split_kernel<<<dim3(32, 32, 4), dim3(32, 8)>>>(wq, wk, wv, wc);

    // QKV projections (fp32 out g_q/g_k/g_v in [B,H,T,HS] + bias)
    gemm_mma_kernel<<<dim3(MM / CTA_M, CC / CTA_N, 3), 512, GSMEM>>>(
        p_xhi, p_xlo, p_wthi, p_wtlo, bq, bk, bv, nullptr, 1);

    // RoPE + split Q/K; split V
    rope_split_kernel<<<(BB * HH * TT * 32 + 255) / 256, 256>>>();
    split_bf16_kernel<<<(BB * HH * TT * HS / 4 + 255) / 256, 256>>>(
        p_v, p_vhi, p_vlo, BB * HH * TT * HS / 4);

    // Tensor-core flash attention -> g_yhi/g_ylo
    flash_tc_kernel<<<dim3(TT / FBM, BB * HH), 256, FSMEM>>>();

    // Output projection -> d_out
    gemm_mma_kernel<<<dim3(MM / CTA_M, CC / CTA_N, 1), 512, GSMEM>>>(
        p_yhi, p_ylo, p_wthi + (size_t)3 * CC * CC, p_wtlo + (size_t)3 * CC * CC,
        bc, bc, bc, out, 0);
}

// round 7
// speedup vs baseline: 1.2515x; 1.2341x over previous
#include <cuda_runtime.h>
#include <cuda_bf16.h>
#include <cuda_fp16.h>
#include <math.h>
#include <stdint.h>

// Problem constants
#define BB 2
#define TT 2048
#define CC 1024
#define HH 16
#define HS 64
#define MM (BB*TT)       // 4096

// GEMM tiling (mma.sync fp16 2-MMA split), 256 threads, 2-stage cp.async
#define CTA_M 128
#define CTA_N 128
#define KSTG  32                 // K elems per smem stage
#define NS    (CC/KSTG)          // 32 stages
#define GSTGB 30720              // bytes per stage: Ah,Al,Bh x 128x40 fp16
#define GSMEM (2*GSTGB)          // 61440

// Flash tiling (R4 version)
#define FBM 128                  // q rows per CTA
#define FBN 64                   // kv rows per tile
#define FSTR 72                  // padded smem row stride (bf16)
#define FSMEM (36864*2)          // bytes

// Scratch (device globals: allocation-free)
__device__ float g_q[BB*HH*TT*HS];     // [B,H,T,HS] fp32 (pre-RoPE)
__device__ float g_k[BB*HH*TT*HS];
__device__ float g_v[BB*HH*TT*HS];
__device__ float g_cos[TT*32];
__device__ float g_sin[TT*32];

// fp16 operands for projections
__device__ __half g_xh[MM*CC];          // x hi
__device__ __half g_xl[MM*CC];          // x lo
__device__ __half g_yh[MM*CC];          // attn-out hi
__device__ __half g_yl[MM*CC];          // attn-out lo
__device__ __half g_wt16[4*CC*CC];      // transposed fp16 weights [n][k]: wq,wk,wv,wc

// attention operand splits (bf16, 3-MMA path) [B,H,T,HS]
__device__ __nv_bfloat16 g_qhi[BB*HH*TT*HS];
__device__ __nv_bfloat16 g_qlo[BB*HH*TT*HS];
__device__ __nv_bfloat16 g_khi[BB*HH*TT*HS];
__device__ __nv_bfloat16 g_klo[BB*HH*TT*HS];
__device__ __nv_bfloat16 g_vhi[BB*HH*TT*HS];
__device__ __nv_bfloat16 g_vlo[BB*HH*TT*HS];

// ---------------------------------------------------------------------------
// PTX helpers (family-wide sm_80+ only)
// ---------------------------------------------------------------------------
__device__ __forceinline__ uint32_t smem_u32(const void* p) {
    uint32_t a;
    asm("{ .reg .u64 t; cvta.to.shared.u64 t, %1; cvt.u32.u64 %0, t; }" : "=r"(a) : "l"(p));
    return a;
}
__device__ __forceinline__ void ldsm_x4(uint32_t* r, uint32_t addr) {
    asm volatile("ldmatrix.sync.aligned.m8n8.x4.shared.b16 {%0,%1,%2,%3}, [%4];"
        : "=r"(r[0]), "=r"(r[1]), "=r"(r[2]), "=r"(r[3]) : "r"(addr));
}
__device__ __forceinline__ void ldsm_x2(uint32_t* r, uint32_t addr) {
    asm volatile("ldmatrix.sync.aligned.m8n8.x2.shared.b16 {%0,%1}, [%2];"
        : "=r"(r[0]), "=r"(r[1]) : "r"(addr));
}
__device__ __forceinline__ void ldsm_x2t(uint32_t* r, uint32_t addr) {
    asm volatile("ldmatrix.sync.aligned.m8n8.x2.trans.shared.b16 {%0,%1}, [%2];"
        : "=r"(r[0]), "=r"(r[1]) : "r"(addr));
}
__device__ __forceinline__ void mma_bf16(float* c, const uint32_t* a, const uint32_t* b) {
    asm volatile(
        "mma.sync.aligned.m16n8k16.row.col.f32.bf16.bf16.f32 "
        "{%0,%1,%2,%3}, {%4,%5,%6,%7}, {%8,%9}, {%0,%1,%2,%3};"
        : "+f"(c[0]), "+f"(c[1]), "+f"(c[2]), "+f"(c[3])
        : "r"(a[0]), "r"(a[1]), "r"(a[2]), "r"(a[3]), "r"(b[0]), "r"(b[1]));
}
__device__ __forceinline__ void mma_f16(float* c, const uint32_t* a, const uint32_t* b) {
    asm volatile(
        "mma.sync.aligned.m16n8k16.row.col.f32.f16.f16.f32 "
        "{%0,%1,%2,%3}, {%4,%5,%6,%7}, {%8,%9}, {%0,%1,%2,%3};"
        : "+f"(c[0]), "+f"(c[1]), "+f"(c[2]), "+f"(c[3])
        : "r"(a[0]), "r"(a[1]), "r"(a[2]), "r"(a[3]), "r"(b[0]), "r"(b[1]));
}
__device__ __forceinline__ uint32_t pack_bf16x2(float lo, float hi) {
    __nv_bfloat162 v = __floats2bfloat162_rn(lo, hi);
    return *(uint32_t*)&v;
}
__device__ __forceinline__ void cp_async16(uint32_t dst, const void* src) {
    asm volatile("cp.async.cg.shared.global [%0], [%1], 16;" :: "r"(dst), "l"(src));
}
__device__ __forceinline__ void cp_commit() {
    asm volatile("cp.async.commit_group;" ::: "memory");
}
__device__ __forceinline__ void cp_wait(int more) {
    if (more) asm volatile("cp.async.wait_group 1;" ::: "memory");
    else      asm volatile("cp.async.wait_group 0;" ::: "memory");
}

// ---------------------------------------------------------------------------
// RoPE tables
// ---------------------------------------------------------------------------
__global__ void rope_tables_kernel() {
    int idx = blockIdx.x * blockDim.x + threadIdx.x;   // t*32 + i
    if (idx >= TT * 32) return;
    int i = idx & 31;
    int t = idx >> 5;
    double invf_d = exp(-(double)i * (log(10000.0) / 32.0));
    float invf = (float)invf_d;
    float arg_f = (float)t * invf;
    double s, c;
    sincos((double)arg_f, &s, &c);
    g_cos[idx] = (float)c;
    g_sin[idx] = (float)s;
}

// ---------------------------------------------------------------------------
// fp32 -> fp16 hi/lo split, vectorized x4 (for activations)
// ---------------------------------------------------------------------------
__global__ void split_f16_kernel(const float* __restrict__ src,
                                 __half* __restrict__ hi,
                                 __half* __restrict__ lo, int n4) {
    int i = blockIdx.x * blockDim.x + threadIdx.x;
    if (i >= n4) return;
    float4 v = ((const float4*)src)[i];
    float vv[4] = {v.x, v.y, v.z, v.w};
    __half h[4], l[4];
    #pragma unroll
    for (int j = 0; j < 4; j++) {
        h[j] = __float2half(vv[j]);
        l[j] = __float2half(vv[j] - __half2float(h[j]));
    }
    __half2 h01, h23, l01, l23;
    h01.x = h[0]; h01.y = h[1]; h23.x = h[2]; h23.y = h[3];
    l01.x = l[0]; l01.y = l[1]; l23.x = l[2]; l23.y = l[3];
    ((__half2*)hi)[2*i]   = h01;
    ((__half2*)hi)[2*i+1] = h23;
    ((__half2*)lo)[2*i]   = l01;
    ((__half2*)lo)[2*i+1] = l23;
}

// ---------------------------------------------------------------------------
// fp32 -> bf16 hi/lo split (for V, flash path)
// ---------------------------------------------------------------------------
__global__ void split_bf16_kernel(const float* __restrict__ src,
                                  __nv_bfloat16* __restrict__ hi,
                                  __nv_bfloat16* __restrict__ lo, int n4) {
    int i = blockIdx.x * blockDim.x + threadIdx.x;
    if (i >= n4) return;
    float4 v = ((const float4*)src)[i];
    float vv[4] = {v.x, v.y, v.z, v.w};
    __nv_bfloat16 h[4], l[4];
    #pragma unroll
    for (int j = 0; j < 4; j++) {
        h[j] = __float2bfloat16(vv[j]);
        l[j] = __float2bfloat16(vv[j] - __bfloat162float(h[j]));
    }
    __nv_bfloat162 h01, h23, l01, l23;
    h01.x = h[0]; h01.y = h[1]; h23.x = h[2]; h23.y = h[3];
    l01.x = l[0]; l01.y = l[1]; l23.x = l[2]; l23.y = l[3];
    ((__nv_bfloat162*)hi)[2*i]   = h01;
    ((__nv_bfloat162*)hi)[2*i+1] = h23;
    ((__nv_bfloat162*)lo)[2*i]   = l01;
    ((__nv_bfloat162*)lo)[2*i+1] = l23;
}

// ---------------------------------------------------------------------------
// Weight transpose + fp16 truncate: Wt16[n][k] = fp16(W[k][n])
// ---------------------------------------------------------------------------
__global__ void wt16_kernel(const float* __restrict__ wq, const float* __restrict__ wk,
                            const float* __restrict__ wv, const float* __restrict__ wc) {
    __shared__ float tile[32][33];
    int wsel = blockIdx.z;
    const float* W = (wsel == 0) ? wq : (wsel == 1) ? wk : (wsel == 2) ? wv : wc;
    __half* Wt = g_wt16 + (size_t)wsel * CC * CC;
    int k0 = blockIdx.x * 32, n0 = blockIdx.y * 32;
    int tx = threadIdx.x, ty = threadIdx.y;   // (32,8)
    #pragma unroll
    for (int j = 0; j < 4; j++)
        tile[ty + 8*j][tx] = W[(size_t)(k0 + ty + 8*j) * CC + n0 + tx];
    __syncthreads();
    #pragma unroll
    for (int j = 0; j < 4; j++)
        Wt[(size_t)(n0 + ty + 8*j) * CC + k0 + tx] = __float2half(tile[tx][ty + 8*j]);
}

// ---------------------------------------------------------------------------
// fp16 2-MMA split GEMM: D = (Ah+Al) @ Bh^T (+bias), B stored [n][k] fp16.
// CTA 128x128, 8 warps 2x4, warp tile 64x32, 2-stage cp.async ring.
// Stage layout (bytes): Ah @0, Al @10240, Bh @20480 (row stride 80B)
// ---------------------------------------------------------------------------
__global__ void __launch_bounds__(256, 1) gemm_mma_kernel(
    const __half* __restrict__ Ahi, const __half* __restrict__ Alo,
    const __half* __restrict__ B_all,
    const float* __restrict__ bias_q, const float* __restrict__ bias_k,
    const float* __restrict__ bias_v,
    float* __restrict__ o_direct, int qkv_mode)
{
    extern __shared__ __half gsm[];
    uint32_t smbase = smem_u32(gsm);

    int tid = threadIdx.x;
    int wid = tid >> 5, lane = tid & 31;
    int wm = wid >> 2, wn = wid & 3;
    int m0 = blockIdx.x * CTA_M;
    int n0 = blockIdx.y * CTA_N;
    int which = blockIdx.z;
    const __half* Bh = B_all + (size_t)which * CC * CC;
    const float* bias = qkv_mode ? ((which == 0) ? bias_q : (which == 1) ? bias_k : bias_v)
                                 : bias_q;

    // Per-thread copy slots: 6 x 16B per stage
    const __half* gsrc[6];
    uint32_t soff[6];
    #pragma unroll
    for (int j = 0; j < 6; j++) {
        int id = tid + j * 256;                // 0..1535
        int sel = id >> 9;                     // 0 Ah, 1 Al, 2 Bh
        int cc = id & 511;
        int row = cc >> 2;
        int c16 = (cc & 3) * 8;
        const __half* base =
            (sel == 0) ? Ahi + (size_t)m0 * CC :
            (sel == 1) ? Alo + (size_t)m0 * CC :
                         Bh  + (size_t)n0 * CC;
        gsrc[j] = base + (size_t)row * CC + c16;
        soff[j] = sel * 10240u + row * 80u + c16 * 2u;
    }

    // ldmatrix base addresses within stage 0
    uint32_t aAh[4], bB[2];
    {
        int ra = lane & 15;
        int ca8 = ((lane >> 4) & 1) * 8;
        #pragma unroll
        for (int mf = 0; mf < 4; mf++)
            aAh[mf] = smbase + (wm * 64 + mf * 16 + ra) * 80u + ca8 * 2u;
        int rb = ((lane >> 4) & 1) * 8 + (lane & 7);
        int cb8 = ((lane >> 3) & 1) * 8;
        #pragma unroll
        for (int np = 0; np < 2; np++)
            bB[np] = smbase + 20480u + (wn * 32 + np * 16 + rb) * 80u + cb8 * 2u;
    }

    float acc[4][4][4] = {};

    // Preload stages 0,1
    #pragma unroll
    for (int j = 0; j < 6; j++) cp_async16(smbase + soff[j], gsrc[j]);
    cp_commit();
    #pragma unroll
    for (int j = 0; j < 6; j++) cp_async16(smbase + GSTGB + soff[j], gsrc[j] + KSTG);
    cp_commit();

    for (int s = 0; s < NS; s++) {
        cp_wait(s < NS - 1);
        __syncthreads();

        uint32_t sb = (s & 1) * GSTGB;
        #pragma unroll
        for (int kk = 0; kk < 2; kk++) {
            uint32_t ah[4][4], al[4][4], bh[2][4];
            #pragma unroll
            for (int mf = 0; mf < 4; mf++) {
                ldsm_x4(ah[mf], aAh[mf] + sb + kk * 32);
                ldsm_x4(al[mf], aAh[mf] + sb + 10240u + kk * 32);
            }
            #pragma unroll
            for (int np = 0; np < 2; np++)
                ldsm_x4(bh[np], bB[np] + sb + kk * 32);
            #pragma unroll
            for (int mf = 0; mf < 4; mf++)
                #pragma unroll
                for (int nf = 0; nf < 4; nf++) {
                    const uint32_t* bf = &bh[nf >> 1][(nf & 1) * 2];
                    mma_f16(acc[mf][nf], ah[mf], bf);
                    mma_f16(acc[mf][nf], al[mf], bf);
                }
        }
        __syncthreads();
        if (s + 2 < NS) {
            uint32_t db = smbase + (s & 1) * GSTGB;
            #pragma unroll
            for (int j = 0; j < 6; j++)
                cp_async16(db + soff[j], gsrc[j] + (s + 2) * KSTG);
            cp_commit();
        }
    }

    int group = lane >> 2, tig = lane & 3;
    #pragma unroll
    for (int mf = 0; mf < 4; mf++) {
        #pragma unroll
        for (int nf = 0; nf < 4; nf++) {
            int ncol = n0 + wn * 32 + nf * 8 + tig * 2;
            float2 bv = *(const float2*)&bias[ncol];
            #pragma unroll
            for (int half = 0; half < 2; half++) {
                int m = m0 + wm * 64 + mf * 16 + group + half * 8;
                float2 o;
                o.x = acc[mf][nf][half * 2 + 0] + bv.x;
                o.y = acc[mf][nf][half * 2 + 1] + bv.y;
                if (qkv_mode) {
                    float* outp = (which == 0) ? g_q : (which == 1) ? g_k : g_v;
                    int b = m >> 11, t = m & (TT - 1);
                    int h = ncol >> 6, d = ncol & 63;
                    *(float2*)&outp[(((size_t)b * HH + h) * TT + t) * HS + d] = o;
                } else {
                    *(float2*)&o_direct[(size_t)m * CC + ncol] = o;
                }
            }
        }
    }
}

// ---------------------------------------------------------------------------
// RoPE apply + bf16 hi/lo split. Q scaled by 1/sqrt(HS)=0.125 before split.
// ---------------------------------------------------------------------------
__global__ void rope_split_kernel() {
    int idx = blockIdx.x * blockDim.x + threadIdx.x;
    if (idx >= BB * HH * TT * 32) return;
    int i  = idx & 31;
    int t  = (idx >> 5) & (TT - 1);
    int bh = idx >> 16;
    float c = g_cos[(t << 5) + i];
    float s = g_sin[(t << 5) + i];
    int base = (bh * TT + t) * HS + i;

    float q1 = g_q[base], q2 = g_q[base + 32];
    float qa = (q1 * c - q2 * s) * 0.125f;
    float qb = (q2 * c + q1 * s) * 0.125f;
    __nv_bfloat16 h;
    h = __float2bfloat16(qa); g_qhi[base]      = h; g_qlo[base]      = __float2bfloat16(qa - __bfloat162float(h));
    h = __float2bfloat16(qb); g_qhi[base + 32] = h; g_qlo[base + 32] = __float2bfloat16(qb - __bfloat162float(h));

    float k1 = g_k[base], k2 = g_k[base + 32];
    float ka = k1 * c - k2 * s;
    float kb = k2 * c + k1 * s;
    h = __float2bfloat16(ka); g_khi[base]      = h; g_klo[base]      = __float2bfloat16(ka - __bfloat162float(h));
    h = __float2bfloat16(kb); g_khi[base + 32] = h; g_klo[base + 32] = __float2bfloat16(kb - __bfloat162float(h));
}

// ---------------------------------------------------------------------------
// Tensor-core flash attention (R4 passing version; only the epilogue changed
// to emit fp16 hi/lo for the fp16 output projection).
// ---------------------------------------------------------------------------
__global__ void __launch_bounds__(256) flash_tc_kernel() {
    extern __shared__ __nv_bfloat16 fsm[];
    __nv_bfloat16* sQh = fsm;                 // 128 x 72
    __nv_bfloat16* sQl = fsm + 9216;
    __nv_bfloat16* sKh = fsm + 18432;         // 64 x 72
    __nv_bfloat16* sKl = fsm + 23040;
    __nv_bfloat16* sVh = fsm + 27648;
    __nv_bfloat16* sVl = fsm + 32256;

    int qb = blockIdx.x;
    int bh = blockIdx.y;
    int q0 = qb * FBM;
    size_t hbase = (size_t)bh * TT * HS;

    int tid = threadIdx.x;
    int wid = tid >> 5, lane = tid & 31;
    int g = lane >> 2, tig = lane & 3;

    // ---- stage Q tile (128x64 x hi/lo) ----
    {
        const __nv_bfloat16* Qh = g_qhi + hbase + (size_t)q0 * HS;
        const __nv_bfloat16* Ql = g_qlo + hbase + (size_t)q0 * HS;
        #pragma unroll
        for (int j = 0; j < 4; j++) {
            int c = tid + j * 256;            // 0..1023
            int row = c >> 3;
            int col8 = (c & 7) * 8;
            *(uint4*)&sQh[row * FSTR + col8] = *(const uint4*)&Qh[row * HS + col8];
            *(uint4*)&sQl[row * FSTR + col8] = *(const uint4*)&Ql[row * HS + col8];
        }
    }

    // K/V copy slots: 8 x uint4 per tile
    const __nv_bfloat16* kvsrc[8];
    __nv_bfloat16* kvdst[8];
    {
        const __nv_bfloat16* bases[4] = {
            g_khi + hbase, g_klo + hbase, g_vhi + hbase, g_vlo + hbase };
        __nv_bfloat16* sb[4] = { sKh, sKl, sVh, sVl };
        #pragma unroll
        for (int j = 0; j < 8; j++) {
            int c = tid + j * 256;            // 0..2047
            int sel = c >> 9;
            int cc = c & 511;
            int row = cc >> 3;
            int col8 = (cc & 7) * 8;
            kvsrc[j] = bases[sel] + row * HS + col8;
            kvdst[j] = sb[sel] + row * FSTR + col8;
        }
    }

    // ldmatrix base addresses
    uint32_t aQh = smem_u32(&sQh[(wid * 16 + (lane & 15)) * FSTR + ((lane >> 4) & 1) * 8]);
    uint32_t aQl = aQh + 9216 * 2;
    uint32_t aKh = smem_u32(&sKh[(lane & 7) * FSTR + ((lane >> 3) & 1) * 8]);
    uint32_t aKl = aKh + 4608 * 2;
    uint32_t aVh = smem_u32(&sVh[(lane & 15) * FSTR]);
    uint32_t aVl = aVh + 4608 * 2;

    float m0 = -1e30f, m1 = -1e30f, l0 = 0.f, l1 = 0.f;
    float acc_o[8][4] = {};
    int rw0 = q0 + wid * 16;                  // warp's min row
    int rq0 = rw0 + g, rq1 = rq0 + 8;

    int ktmax = (q0 + FBM - 1) >> 6;

    uint4 pf[8];
    #pragma unroll
    for (int j = 0; j < 8; j++) pf[j] = *(const uint4*)(kvsrc[j]);

    for (int kt = 0; kt <= ktmax; kt++) {
        __syncthreads();
        #pragma unroll
        for (int j = 0; j < 8; j++) *(uint4*)(kvdst[j]) = pf[j];
        __syncthreads();
        if (kt < ktmax) {
            #pragma unroll
            for (int j = 0; j < 8; j++)
                pf[j] = *(const uint4*)(kvsrc[j] + (size_t)(kt + 1) * FBN * HS);
        }
        int k0 = kt * FBN;

        // ---- S = Q K^T (3-MMA split) ----
        float s[8][4] = {};
        #pragma unroll
        for (int kc = 0; kc < 4; kc++) {
            uint32_t qh[4], ql[4];
            ldsm_x4(qh, aQh + kc * 32);
            ldsm_x4(ql, aQl + kc * 32);
            #pragma unroll
            for (int nf = 0; nf < 8; nf++) {
                uint32_t kh2[2], kl2[2];
                ldsm_x2(kh2, aKh + nf * 1152 + kc * 32);
                ldsm_x2(kl2, aKl + nf * 1152 + kc * 32);
                mma_bf16(s[nf], qh, kh2);
                mma_bf16(s[nf], qh, kl2);
                mma_bf16(s[nf], ql, kh2);
            }
        }

        // ---- causal mask (diagonal tiles only) ----
        if (k0 + FBN - 1 > rw0) {
            #pragma unroll
            for (int nf = 0; nf < 8; nf++) {
                int c0 = k0 + nf * 8 + tig * 2;
                if (c0     > rq0) s[nf][0] = -1e30f;
                if (c0 + 1 > rq0) s[nf][1] = -1e30f;
                if (c0     > rq1) s[nf][2] = -1e30f;
                if (c0 + 1 > rq1) s[nf][3] = -1e30f;
            }
        }

        // ---- online softmax (fp32 on fragments) ----
        float mx0 = -1e30f, mx1 = -1e30f;
        #pragma unroll
        for (int nf = 0; nf < 8; nf++) {
            mx0 = fmaxf(mx0, fmaxf(s[nf][0], s[nf][1]));
            mx1 = fmaxf(mx1, fmaxf(s[nf][2], s[nf][3]));
        }
        #pragma unroll
        for (int off = 1; off <= 2; off <<= 1) {
            mx0 = fmaxf(mx0, __shfl_xor_sync(0xffffffffu, mx0, off));
            mx1 = fmaxf(mx1, __shfl_xor_sync(0xffffffffu, mx1, off));
        }
        float mn0 = fmaxf(m0, mx0), mn1 = fmaxf(m1, mx1);
        float sum0 = 0.f, sum1 = 0.f;
        #pragma unroll
        for (int nf = 0; nf < 8; nf++) {
            s[nf][0] = __expf(s[nf][0] - mn0);
            s[nf][1] = __expf(s[nf][1] - mn0);
            s[nf][2] = __expf(s[nf][2] - mn1);
            s[nf][3] = __expf(s[nf][3] - mn1);
            sum0 += s[nf][0] + s[nf][1];
            sum1 += s[nf][2] + s[nf][3];
        }
        #pragma unroll
        for (int off = 1; off <= 2; off <<= 1) {
            sum0 += __shfl_xor_sync(0xffffffffu, sum0, off);
            sum1 += __shfl_xor_sync(0xffffffffu, sum1, off);
        }
        float f0 = __expf(m0 - mn0), f1 = __expf(m1 - mn1);
        l0 = l0 * f0 + sum0; m0 = mn0;
        l1 = l1 * f1 + sum1; m1 = mn1;
        #pragma unroll
        for (int nf = 0; nf < 8; nf++) {
            acc_o[nf][0] *= f0; acc_o[nf][1] *= f0;
            acc_o[nf][2] *= f1; acc_o[nf][3] *= f1;
        }

        // ---- O += P V (split P = Ph + Pl; V pre-split) ----
        #pragma unroll
        for (int jc = 0; jc < 4; jc++) {
            uint32_t aPh[4], aPl[4];
            {
                float p00 = s[2*jc][0],   p01 = s[2*jc][1];
                float p10 = s[2*jc][2],   p11 = s[2*jc][3];
                float p20 = s[2*jc+1][0], p21 = s[2*jc+1][1];
                float p30 = s[2*jc+1][2], p31 = s[2*jc+1][3];
                aPh[0] = pack_bf16x2(p00, p01);
                aPh[1] = pack_bf16x2(p10, p11);
                aPh[2] = pack_bf16x2(p20, p21);
                aPh[3] = pack_bf16x2(p30, p31);
                __nv_bfloat162 b0 = *(__nv_bfloat162*)&aPh[0];
                __nv_bfloat162 b1 = *(__nv_bfloat162*)&aPh[1];
                __nv_bfloat162 b2 = *(__nv_bfloat162*)&aPh[2];
                __nv_bfloat162 b3 = *(__nv_bfloat162*)&aPh[3];
                aPl[0] = pack_bf16x2(p00 - __bfloat162float(b0.x), p01 - __bfloat162float(b0.y));
                aPl[1] = pack_bf16x2(p10 - __bfloat162float(b1.x), p11 - __bfloat162float(b1.y));
                aPl[2] = pack_bf16x2(p20 - __bfloat162float(b2.x), p21 - __bfloat162float(b2.y));
                aPl[3] = pack_bf16x2(p30 - __bfloat162float(b3.x), p31 - __bfloat162float(b3.y));
            }
            #pragma unroll
            for (int nf = 0; nf < 8; nf++) {
                uint32_t vh2[2], vl2[2];
                ldsm_x2t(vh2, aVh + jc * 2304 + nf * 16);
                ldsm_x2t(vl2, aVl + jc * 2304 + nf * 16);
                mma_bf16(acc_o[nf], aPh, vh2);
                mma_bf16(acc_o[nf], aPh, vl2);
                mma_bf16(acc_o[nf], aPl, vh2);
            }
        }
    }

    // ---- epilogue: O/l -> g_yh/g_yl fp16 split, [B,T,C] ----
    {
        float inv0 = 1.f / l0, inv1 = 1.f / l1;
        int b = bh >> 4, h = bh & 15;
        size_t rb0 = ((size_t)b * TT + rq0) * CC;
        size_t rb1 = ((size_t)b * TT + rq1) * CC;
        #pragma unroll
        for (int nf = 0; nf < 8; nf++) {
            int col = h * HS + nf * 8 + tig * 2;
            float v0 = acc_o[nf][0] * inv0, v1 = acc_o[nf][1] * inv0;
            float v2 = acc_o[nf][2] * inv1, v3 = acc_o[nf][3] * inv1;
            __half2 hh, ll;
            hh.x = __float2half(v0); hh.y = __float2half(v1);
            ll.x = __float2half(v0 - __half2float(hh.x));
            ll.y = __float2half(v1 - __half2float(hh.y));
            *(__half2*)&g_yh[rb0 + col] = hh;
            *(__half2*)&g_yl[rb0 + col] = ll;
            hh.x = __float2half(v2); hh.y = __float2half(v3);
            ll.x = __float2half(v2 - __half2float(hh.x));
            ll.y = __float2half(v3 - __half2float(hh.y));
            *(__half2*)&g_yh[rb1 + col] = hh;
            *(__half2*)&g_yl[rb1 + col] = ll;
        }
    }
}

// ---------------------------------------------------------------------------
extern "C" void kernel_launch(void* const* d_in, const int* in_sizes, int n_in,
                              void* d_out, int out_size) {
    const float* qx = (const float*)d_in[0];
    const float* wq = (const float*)d_in[1];
    const float* bq = (const float*)d_in[2];
    const float* wk = (const float*)d_in[3];
    const float* bk = (const float*)d_in[4];
    const float* wv = (const float*)d_in[5];
    const float* bv = (const float*)d_in[6];
    const float* wc = (const float*)d_in[7];
    const float* bc = (const float*)d_in[8];
    float* out = (float*)d_out;

    // device-global pointers
    float* p_v;            cudaGetSymbolAddress((void**)&p_v, g_v);
    __half* p_xh;          cudaGetSymbolAddress((void**)&p_xh, g_xh);
    __half* p_xl;          cudaGetSymbolAddress((void**)&p_xl, g_xl);
    __half* p_yh;          cudaGetSymbolAddress((void**)&p_yh, g_yh);
    __half* p_yl;          cudaGetSymbolAddress((void**)&p_yl, g_yl);
    __half* p_wt16;        cudaGetSymbolAddress((void**)&p_wt16, g_wt16);
    __nv_bfloat16* p_vhi;  cudaGetSymbolAddress((void**)&p_vhi, g_vhi);
    __nv_bfloat16* p_vlo;  cudaGetSymbolAddress((void**)&p_vlo, g_vlo);

    cudaFuncSetAttribute(gemm_mma_kernel,
                         cudaFuncAttributeMaxDynamicSharedMemorySize, GSMEM);
    cudaFuncSetAttribute(flash_tc_kernel,
                         cudaFuncAttributeMaxDynamicSharedMemorySize, FSMEM);

    rope_tables_kernel<<<(TT * 32 + 255) / 256, 256>>>();

    // Split x to fp16 hi/lo; transpose+truncate weights to fp16
    split_f16_kernel<<<(MM * CC / 4 + 255) / 256, 256>>>(qx, p_xh, p_xl, MM * CC / 4);
    wt16_kernel<<<dim3(32, 32, 4), dim3(32, 8)>>>(wq, wk, wv, wc);

    // QKV projections (fp32 out g_q/g_k/g_v in [B,H,T,HS] + bias)
    gemm_mma_kernel<<<dim3(MM / CTA_M, CC / CTA_N, 3), 256, GSMEM>>>(
        p_xh, p_xl, p_wt16, bq, bk, bv, nullptr, 1);

    // RoPE + split Q/K (bf16); split V (bf16)
    rope_split_kernel<<<(BB * HH * TT * 32 + 255) / 256, 256>>>();
    split_bf16_kernel<<<(BB * HH * TT * HS / 4 + 255) / 256, 256>>>(
        p_v, p_vhi, p_vlo, BB * HH * TT * HS / 4);

    // Tensor-core flash attention -> g_yh/g_yl (fp16 split)
    flash_tc_kernel<<<dim3(TT / FBM, BB * HH), 256, FSMEM>>>();

    // Output projection -> d_out
    gemm_mma_kernel<<<dim3(MM / CTA_M, CC / CTA_N, 1), 256, GSMEM>>>(
        p_yh, p_yl, p_wt16 + (size_t)3 * CC * CC, bc, bc, bc, out, 0);
}

// round 8
// speedup vs baseline: 1.4040x; 1.1218x over previous
#include <cuda_runtime.h>
#include <cuda_bf16.h>
#include <cuda_fp16.h>
#include <math.h>
#include <stdint.h>

// Problem constants
#define BB 2
#define TT 2048
#define CC 1024
#define HH 16
#define HS 64
#define MM (BB*TT)       // 4096

// GEMM tiling (mma.sync fp16 2-MMA split), 256 threads, 2-stage cp.async
#define CTA_M 128
#define CTA_N 128
#define KSTG  32                 // K elems per smem stage
#define NS    (CC/KSTG)          // 32 stages
#define GSTGB 30720              // bytes per stage: Ah,Al,Bh x 128x40 fp16
#define GSMEM (2*GSTGB)          // 61440

// Flash tiling (fp16 2-MMA)
#define FBM 128                  // q rows per CTA
#define FBN 64                   // kv rows per tile
#define FSTR 72                  // padded smem row stride (fp16 elems; 144B)
// smem bytes: Qh@0, Ql@18432, Kh@36864, Vh@46080
#define FSMEM 55296

// Scratch (device globals: allocation-free)
__device__ float g_q[BB*HH*TT*HS];     // [B,H,T,HS] fp32 (pre-RoPE)
__device__ float g_k[BB*HH*TT*HS];
__device__ float g_v[BB*HH*TT*HS];
__device__ float g_cos[TT*32];
__device__ float g_sin[TT*32];

// fp16 operands for projections
__device__ __half g_xh[MM*CC];          // x hi
__device__ __half g_xl[MM*CC];          // x lo
__device__ __half g_yh[MM*CC];          // attn-out hi
__device__ __half g_yl[MM*CC];          // attn-out lo
__device__ __half g_wt16[4*CC*CC];      // transposed fp16 weights [n][k]

// fp16 attention operands [B,H,T,HS]
__device__ __half g_fqh[BB*HH*TT*HS];   // Q hi (unscaled)
__device__ __half g_fql[BB*HH*TT*HS];   // Q lo
__device__ __half g_fkh[BB*HH*TT*HS];   // K * 0.125, truncated
__device__ __half g_fvh[BB*HH*TT*HS];   // V truncated

// ---------------------------------------------------------------------------
// PTX helpers (family-wide sm_80+ only)
// ---------------------------------------------------------------------------
__device__ __forceinline__ uint32_t smem_u32(const void* p) {
    uint32_t a;
    asm("{ .reg .u64 t; cvta.to.shared.u64 t, %1; cvt.u32.u64 %0, t; }" : "=r"(a) : "l"(p));
    return a;
}
__device__ __forceinline__ void ldsm_x4(uint32_t* r, uint32_t addr) {
    asm volatile("ldmatrix.sync.aligned.m8n8.x4.shared.b16 {%0,%1,%2,%3}, [%4];"
        : "=r"(r[0]), "=r"(r[1]), "=r"(r[2]), "=r"(r[3]) : "r"(addr));
}
__device__ __forceinline__ void ldsm_x2t(uint32_t* r, uint32_t addr) {
    asm volatile("ldmatrix.sync.aligned.m8n8.x2.trans.shared.b16 {%0,%1}, [%2];"
        : "=r"(r[0]), "=r"(r[1]) : "r"(addr));
}
__device__ __forceinline__ void mma_f16(float* c, const uint32_t* a, const uint32_t* b) {
    asm volatile(
        "mma.sync.aligned.m16n8k16.row.col.f32.f16.f16.f32 "
        "{%0,%1,%2,%3}, {%4,%5,%6,%7}, {%8,%9}, {%0,%1,%2,%3};"
        : "+f"(c[0]), "+f"(c[1]), "+f"(c[2]), "+f"(c[3])
        : "r"(a[0]), "r"(a[1]), "r"(a[2]), "r"(a[3]), "r"(b[0]), "r"(b[1]));
}
__device__ __forceinline__ uint32_t pack_f16x2(float lo, float hi) {
    __half2 v = __floats2half2_rn(lo, hi);
    return *(uint32_t*)&v;
}
__device__ __forceinline__ void cp_async16(uint32_t dst, const void* src) {
    asm volatile("cp.async.cg.shared.global [%0], [%1], 16;" :: "r"(dst), "l"(src));
}
__device__ __forceinline__ void cp_commit() {
    asm volatile("cp.async.commit_group;" ::: "memory");
}
__device__ __forceinline__ void cp_wait(int more) {
    if (more) asm volatile("cp.async.wait_group 1;" ::: "memory");
    else      asm volatile("cp.async.wait_group 0;" ::: "memory");
}

// ---------------------------------------------------------------------------
// RoPE tables
// ---------------------------------------------------------------------------
__global__ void rope_tables_kernel() {
    int idx = blockIdx.x * blockDim.x + threadIdx.x;   // t*32 + i
    if (idx >= TT * 32) return;
    int i = idx & 31;
    int t = idx >> 5;
    double invf_d = exp(-(double)i * (log(10000.0) / 32.0));
    float invf = (float)invf_d;
    float arg_f = (float)t * invf;
    double s, c;
    sincos((double)arg_f, &s, &c);
    g_cos[idx] = (float)c;
    g_sin[idx] = (float)s;
}

// ---------------------------------------------------------------------------
// fp32 -> fp16 hi/lo split, vectorized x4
// ---------------------------------------------------------------------------
__global__ void split_f16_kernel(const float* __restrict__ src,
                                 __half* __restrict__ hi,
                                 __half* __restrict__ lo, int n4) {
    int i = blockIdx.x * blockDim.x + threadIdx.x;
    if (i >= n4) return;
    float4 v = ((const float4*)src)[i];
    float vv[4] = {v.x, v.y, v.z, v.w};
    __half h[4], l[4];
    #pragma unroll
    for (int j = 0; j < 4; j++) {
        h[j] = __float2half(vv[j]);
        l[j] = __float2half(vv[j] - __half2float(h[j]));
    }
    __half2 h01, h23, l01, l23;
    h01.x = h[0]; h01.y = h[1]; h23.x = h[2]; h23.y = h[3];
    l01.x = l[0]; l01.y = l[1]; l23.x = l[2]; l23.y = l[3];
    ((__half2*)hi)[2*i]   = h01;
    ((__half2*)hi)[2*i+1] = h23;
    ((__half2*)lo)[2*i]   = l01;
    ((__half2*)lo)[2*i+1] = l23;
}

// ---------------------------------------------------------------------------
// fp32 -> fp16 truncate (for V)
// ---------------------------------------------------------------------------
__global__ void trunc_f16_kernel(const float* __restrict__ src,
                                 __half* __restrict__ dst, int n4) {
    int i = blockIdx.x * blockDim.x + threadIdx.x;
    if (i >= n4) return;
    float4 v = ((const float4*)src)[i];
    __half2 a, b;
    a.x = __float2half(v.x); a.y = __float2half(v.y);
    b.x = __float2half(v.z); b.y = __float2half(v.w);
    ((__half2*)dst)[2*i]   = a;
    ((__half2*)dst)[2*i+1] = b;
}

// ---------------------------------------------------------------------------
// Weight transpose + fp16 truncate: Wt16[n][k] = fp16(W[k][n])
// ---------------------------------------------------------------------------
__global__ void wt16_kernel(const float* __restrict__ wq, const float* __restrict__ wk,
                            const float* __restrict__ wv, const float* __restrict__ wc) {
    __shared__ float tile[32][33];
    int wsel = blockIdx.z;
    const float* W = (wsel == 0) ? wq : (wsel == 1) ? wk : (wsel == 2) ? wv : wc;
    __half* Wt = g_wt16 + (size_t)wsel * CC * CC;
    int k0 = blockIdx.x * 32, n0 = blockIdx.y * 32;
    int tx = threadIdx.x, ty = threadIdx.y;   // (32,8)
    #pragma unroll
    for (int j = 0; j < 4; j++)
        tile[ty + 8*j][tx] = W[(size_t)(k0 + ty + 8*j) * CC + n0 + tx];
    __syncthreads();
    #pragma unroll
    for (int j = 0; j < 4; j++)
        Wt[(size_t)(n0 + ty + 8*j) * CC + k0 + tx] = __float2half(tile[tx][ty + 8*j]);
}

// ---------------------------------------------------------------------------
// fp16 2-MMA split GEMM (R7 passing version, unchanged).
// ---------------------------------------------------------------------------
__global__ void __launch_bounds__(256, 1) gemm_mma_kernel(
    const __half* __restrict__ Ahi, const __half* __restrict__ Alo,
    const __half* __restrict__ B_all,
    const float* __restrict__ bias_q, const float* __restrict__ bias_k,
    const float* __restrict__ bias_v,
    float* __restrict__ o_direct, int qkv_mode)
{
    extern __shared__ __half gsm[];
    uint32_t smbase = smem_u32(gsm);

    int tid = threadIdx.x;
    int wid = tid >> 5, lane = tid & 31;
    int wm = wid >> 2, wn = wid & 3;
    int m0 = blockIdx.x * CTA_M;
    int n0 = blockIdx.y * CTA_N;
    int which = blockIdx.z;
    const __half* Bh = B_all + (size_t)which * CC * CC;
    const float* bias = qkv_mode ? ((which == 0) ? bias_q : (which == 1) ? bias_k : bias_v)
                                 : bias_q;

    const __half* gsrc[6];
    uint32_t soff[6];
    #pragma unroll
    for (int j = 0; j < 6; j++) {
        int id = tid + j * 256;
        int sel = id >> 9;                     // 0 Ah, 1 Al, 2 Bh
        int cc = id & 511;
        int row = cc >> 2;
        int c16 = (cc & 3) * 8;
        const __half* base =
            (sel == 0) ? Ahi + (size_t)m0 * CC :
            (sel == 1) ? Alo + (size_t)m0 * CC :
                         Bh  + (size_t)n0 * CC;
        gsrc[j] = base + (size_t)row * CC + c16;
        soff[j] = sel * 10240u + row * 80u + c16 * 2u;
    }

    uint32_t aAh[4], bB[2];
    {
        int ra = lane & 15;
        int ca8 = ((lane >> 4) & 1) * 8;
        #pragma unroll
        for (int mf = 0; mf < 4; mf++)
            aAh[mf] = smbase + (wm * 64 + mf * 16 + ra) * 80u + ca8 * 2u;
        int rb = ((lane >> 4) & 1) * 8 + (lane & 7);
        int cb8 = ((lane >> 3) & 1) * 8;
        #pragma unroll
        for (int np = 0; np < 2; np++)
            bB[np] = smbase + 20480u + (wn * 32 + np * 16 + rb) * 80u + cb8 * 2u;
    }

    float acc[4][4][4] = {};

    #pragma unroll
    for (int j = 0; j < 6; j++) cp_async16(smbase + soff[j], gsrc[j]);
    cp_commit();
    #pragma unroll
    for (int j = 0; j < 6; j++) cp_async16(smbase + GSTGB + soff[j], gsrc[j] + KSTG);
    cp_commit();

    for (int s = 0; s < NS; s++) {
        cp_wait(s < NS - 1);
        __syncthreads();

        uint32_t sb = (s & 1) * GSTGB;
        #pragma unroll
        for (int kk = 0; kk < 2; kk++) {
            uint32_t ah[4][4], al[4][4], bh[2][4];
            #pragma unroll
            for (int mf = 0; mf < 4; mf++) {
                ldsm_x4(ah[mf], aAh[mf] + sb + kk * 32);
                ldsm_x4(al[mf], aAh[mf] + sb + 10240u + kk * 32);
            }
            #pragma unroll
            for (int np = 0; np < 2; np++)
                ldsm_x4(bh[np], bB[np] + sb + kk * 32);
            #pragma unroll
            for (int mf = 0; mf < 4; mf++)
                #pragma unroll
                for (int nf = 0; nf < 4; nf++) {
                    const uint32_t* bf = &bh[nf >> 1][(nf & 1) * 2];
                    mma_f16(acc[mf][nf], ah[mf], bf);
                    mma_f16(acc[mf][nf], al[mf], bf);
                }
        }
        __syncthreads();
        if (s + 2 < NS) {
            uint32_t db = smbase + (s & 1) * GSTGB;
            #pragma unroll
            for (int j = 0; j < 6; j++)
                cp_async16(db + soff[j], gsrc[j] + (s + 2) * KSTG);
            cp_commit();
        }
    }

    int group = lane >> 2, tig = lane & 3;
    #pragma unroll
    for (int mf = 0; mf < 4; mf++) {
        #pragma unroll
        for (int nf = 0; nf < 4; nf++) {
            int ncol = n0 + wn * 32 + nf * 8 + tig * 2;
            float2 bv = *(const float2*)&bias[ncol];
            #pragma unroll
            for (int half = 0; half < 2; half++) {
                int m = m0 + wm * 64 + mf * 16 + group + half * 8;
                float2 o;
                o.x = acc[mf][nf][half * 2 + 0] + bv.x;
                o.y = acc[mf][nf][half * 2 + 1] + bv.y;
                if (qkv_mode) {
                    float* outp = (which == 0) ? g_q : (which == 1) ? g_k : g_v;
                    int b = m >> 11, t = m & (TT - 1);
                    int h = ncol >> 6, d = ncol & 63;
                    *(float2*)&outp[(((size_t)b * HH + h) * TT + t) * HS + d] = o;
                } else {
                    *(float2*)&o_direct[(size_t)m * CC + ncol] = o;
                }
            }
        }
    }
}

// ---------------------------------------------------------------------------
// RoPE apply + fp16 operand prep.
// Q: unscaled, split fp16 hi/lo. K: scaled by 0.125, truncated fp16.
// ---------------------------------------------------------------------------
__global__ void rope_split_kernel() {
    int idx = blockIdx.x * blockDim.x + threadIdx.x;
    if (idx >= BB * HH * TT * 32) return;
    int i  = idx & 31;
    int t  = (idx >> 5) & (TT - 1);
    int bh = idx >> 16;
    float c = g_cos[(t << 5) + i];
    float s = g_sin[(t << 5) + i];
    int base = (bh * TT + t) * HS + i;

    float q1 = g_q[base], q2 = g_q[base + 32];
    float qa = q1 * c - q2 * s;
    float qb = q2 * c + q1 * s;
    __half h;
    h = __float2half(qa); g_fqh[base]      = h; g_fql[base]      = __float2half(qa - __half2float(h));
    h = __float2half(qb); g_fqh[base + 32] = h; g_fql[base + 32] = __float2half(qb - __half2float(h));

    float k1 = g_k[base], k2 = g_k[base + 32];
    g_fkh[base]      = __float2half((k1 * c - k2 * s) * 0.125f);
    g_fkh[base + 32] = __float2half((k2 * c + k1 * s) * 0.125f);
}

// ---------------------------------------------------------------------------
// Tensor-core flash attention (causal), fp16 2-MMA split, fp32 softmax.
// Smem (bytes): Qh@0, Ql@18432, Kh@36864, Vh@46080; row stride 144B.
// ---------------------------------------------------------------------------
__global__ void __launch_bounds__(256) flash_tc_kernel() {
    extern __shared__ __half fsm[];
    uint32_t smbase = smem_u32(fsm);

    int qb = blockIdx.x;
    int bh = blockIdx.y;
    int q0 = qb * FBM;
    size_t hbase = (size_t)bh * TT * HS;

    int tid = threadIdx.x;
    int wid = tid >> 5, lane = tid & 31;
    int g = lane >> 2, tig = lane & 3;

    // ---- stage Q tile (128x64 hi/lo fp16) ----
    {
        const __half* Qh = g_fqh + hbase + (size_t)q0 * HS;
        const __half* Ql = g_fql + hbase + (size_t)q0 * HS;
        #pragma unroll
        for (int j = 0; j < 4; j++) {
            int c = tid + j * 256;            // 0..1023
            int row = c >> 3;
            int col8 = (c & 7) * 8;
            *(uint4*)&fsm[row * FSTR + col8] = *(const uint4*)&Qh[row * HS + col8];
            *(uint4*)&fsm[9216 + row * FSTR + col8] = *(const uint4*)&Ql[row * HS + col8];
        }
    }

    // K/V copy slots: 4 x uint4 per tile (Kh, Vh only)
    const __half* kvsrc[4];
    __half* kvdst[4];
    #pragma unroll
    for (int j = 0; j < 4; j++) {
        int c = tid + j * 256;                // 0..1023
        int sel = c >> 9;                     // 0 Kh, 1 Vh
        int cc = c & 511;
        int row = cc >> 3;
        int col8 = (cc & 7) * 8;
        kvsrc[j] = (sel ? g_fvh : g_fkh) + hbase + row * HS + col8;
        kvdst[j] = fsm + (sel ? 23040 : 18432) + row * FSTR + col8;
    }

    // ldmatrix base addresses (byte offsets)
    uint32_t aQh = smbase + (wid * 16 + (lane & 15)) * 144u + ((lane >> 4) & 1) * 16u;
    uint32_t aQl = aQh + 18432u;
    int rb = ((lane >> 4) & 1) * 8 + (lane & 7);
    int cb8 = ((lane >> 3) & 1) * 8;
    uint32_t aK[4];
    #pragma unroll
    for (int np = 0; np < 4; np++)
        aK[np] = smbase + 36864u + (np * 16 + rb) * 144u + cb8 * 2u;
    uint32_t aVh = smbase + 46080u + (lane & 15) * 144u;

    float m0 = -1e30f, m1 = -1e30f, l0 = 0.f, l1 = 0.f;
    float acc_o[8][4] = {};
    int rw0 = q0 + wid * 16;
    int rq0 = rw0 + g, rq1 = rq0 + 8;

    int ktmax = (q0 + FBM - 1) >> 6;

    uint4 pf[4];
    #pragma unroll
    for (int j = 0; j < 4; j++) pf[j] = *(const uint4*)(kvsrc[j]);

    for (int kt = 0; kt <= ktmax; kt++) {
        __syncthreads();
        #pragma unroll
        for (int j = 0; j < 4; j++) *(uint4*)(kvdst[j]) = pf[j];
        __syncthreads();
        if (kt < ktmax) {
            #pragma unroll
            for (int j = 0; j < 4; j++)
                pf[j] = *(const uint4*)(kvsrc[j] + (size_t)(kt + 1) * FBN * HS);
        }
        int k0 = kt * FBN;

        // ---- S = Q K^T (2-MMA fp16 split) ----
        float s[8][4] = {};
        #pragma unroll
        for (int kc = 0; kc < 4; kc++) {
            uint32_t qh[4], ql[4];
            ldsm_x4(qh, aQh + kc * 32);
            ldsm_x4(ql, aQl + kc * 32);
            #pragma unroll
            for (int np = 0; np < 4; np++) {
                uint32_t kh4[4];
                ldsm_x4(kh4, aK[np] + kc * 32);
                #pragma unroll
                for (int hf = 0; hf < 2; hf++) {
                    int nf = np * 2 + hf;
                    mma_f16(s[nf], qh, &kh4[hf * 2]);
                    mma_f16(s[nf], ql, &kh4[hf * 2]);
                }
            }
        }

        // ---- causal mask (diagonal tiles only) ----
        if (k0 + FBN - 1 > rw0) {
            #pragma unroll
            for (int nf = 0; nf < 8; nf++) {
                int c0 = k0 + nf * 8 + tig * 2;
                if (c0     > rq0) s[nf][0] = -1e30f;
                if (c0 + 1 > rq0) s[nf][1] = -1e30f;
                if (c0     > rq1) s[nf][2] = -1e30f;
                if (c0 + 1 > rq1) s[nf][3] = -1e30f;
            }
        }

        // ---- online softmax (fp32 on fragments) ----
        float mx0 = -1e30f, mx1 = -1e30f;
        #pragma unroll
        for (int nf = 0; nf < 8; nf++) {
            mx0 = fmaxf(mx0, fmaxf(s[nf][0], s[nf][1]));
            mx1 = fmaxf(mx1, fmaxf(s[nf][2], s[nf][3]));
        }
        #pragma unroll
        for (int off = 1; off <= 2; off <<= 1) {
            mx0 = fmaxf(mx0, __shfl_xor_sync(0xffffffffu, mx0, off));
            mx1 = fmaxf(mx1, __shfl_xor_sync(0xffffffffu, mx1, off));
        }
        float mn0 = fmaxf(m0, mx0), mn1 = fmaxf(m1, mx1);
        float sum0 = 0.f, sum1 = 0.f;
        #pragma unroll
        for (int nf = 0; nf < 8; nf++) {
            s[nf][0] = __expf(s[nf][0] - mn0);
            s[nf][1] = __expf(s[nf][1] - mn0);
            s[nf][2] = __expf(s[nf][2] - mn1);
            s[nf][3] = __expf(s[nf][3] - mn1);
            sum0 += s[nf][0] + s[nf][1];
            sum1 += s[nf][2] + s[nf][3];
        }
        #pragma unroll
        for (int off = 1; off <= 2; off <<= 1) {
            sum0 += __shfl_xor_sync(0xffffffffu, sum0, off);
            sum1 += __shfl_xor_sync(0xffffffffu, sum1, off);
        }
        float f0 = __expf(m0 - mn0), f1 = __expf(m1 - mn1);
        l0 = l0 * f0 + sum0; m0 = mn0;
        l1 = l1 * f1 + sum1; m1 = mn1;
        #pragma unroll
        for (int nf = 0; nf < 8; nf++) {
            acc_o[nf][0] *= f0; acc_o[nf][1] *= f0;
            acc_o[nf][2] *= f1; acc_o[nf][3] *= f1;
        }

        // ---- O += P V (P split fp16 hi/lo exactly; V truncated) ----
        #pragma unroll
        for (int jc = 0; jc < 4; jc++) {
            uint32_t aPh[4], aPl[4];
            {
                float p00 = s[2*jc][0],   p01 = s[2*jc][1];
                float p10 = s[2*jc][2],   p11 = s[2*jc][3];
                float p20 = s[2*jc+1][0], p21 = s[2*jc+1][1];
                float p30 = s[2*jc+1][2], p31 = s[2*jc+1][3];
                aPh[0] = pack_f16x2(p00, p01);
                aPh[1] = pack_f16x2(p10, p11);
                aPh[2] = pack_f16x2(p20, p21);
                aPh[3] = pack_f16x2(p30, p31);
                __half2 b0 = *(__half2*)&aPh[0];
                __half2 b1 = *(__half2*)&aPh[1];
                __half2 b2 = *(__half2*)&aPh[2];
                __half2 b3 = *(__half2*)&aPh[3];
                aPl[0] = pack_f16x2(p00 - __half2float(b0.x), p01 - __half2float(b0.y));
                aPl[1] = pack_f16x2(p10 - __half2float(b1.x), p11 - __half2float(b1.y));
                aPl[2] = pack_f16x2(p20 - __half2float(b2.x), p21 - __half2float(b2.y));
                aPl[3] = pack_f16x2(p30 - __half2float(b3.x), p31 - __half2float(b3.y));
            }
            #pragma unroll
            for (int nf = 0; nf < 8; nf++) {
                uint32_t vh2[2];
                ldsm_x2t(vh2, aVh + jc * 2304 + nf * 16);
                mma_f16(acc_o[nf], aPh, vh2);
                mma_f16(acc_o[nf], aPl, vh2);
            }
        }
    }

    // ---- epilogue: O/l -> g_yh/g_yl fp16 split, [B,T,C] ----
    {
        float inv0 = 1.f / l0, inv1 = 1.f / l1;
        int b = bh >> 4, h = bh & 15;
        size_t rb0 = ((size_t)b * TT + rq0) * CC;
        size_t rb1 = ((size_t)b * TT + rq1) * CC;
        #pragma unroll
        for (int nf = 0; nf < 8; nf++) {
            int col = h * HS + nf * 8 + tig * 2;
            float v0 = acc_o[nf][0] * inv0, v1 = acc_o[nf][1] * inv0;
            float v2 = acc_o[nf][2] * inv1, v3 = acc_o[nf][3] * inv1;
            __half2 hh, ll;
            hh.x = __float2half(v0); hh.y = __float2half(v1);
            ll.x = __float2half(v0 - __half2float(hh.x));
            ll.y = __float2half(v1 - __half2float(hh.y));
            *(__half2*)&g_yh[rb0 + col] = hh;
            *(__half2*)&g_yl[rb0 + col] = ll;
            hh.x = __float2half(v2); hh.y = __float2half(v3);
            ll.x = __float2half(v2 - __half2float(hh.x));
            ll.y = __float2half(v3 - __half2float(hh.y));
            *(__half2*)&g_yh[rb1 + col] = hh;
            *(__half2*)&g_yl[rb1 + col] = ll;
        }
    }
}

// ---------------------------------------------------------------------------
extern "C" void kernel_launch(void* const* d_in, const int* in_sizes, int n_in,
                              void* d_out, int out_size) {
    const float* qx = (const float*)d_in[0];
    const float* wq = (const float*)d_in[1];
    const float* bq = (const float*)d_in[2];
    const float* wk = (const float*)d_in[3];
    const float* bk = (const float*)d_in[4];
    const float* wv = (const float*)d_in[5];
    const float* bv = (const float*)d_in[6];
    const float* wc = (const float*)d_in[7];
    const float* bc = (const float*)d_in[8];
    float* out = (float*)d_out;

    // device-global pointers
    float* p_v;            cudaGetSymbolAddress((void**)&p_v, g_v);
    __half* p_xh;          cudaGetSymbolAddress((void**)&p_xh, g_xh);
    __half* p_xl;          cudaGetSymbolAddress((void**)&p_xl, g_xl);
    __half* p_yh;          cudaGetSymbolAddress((void**)&p_yh, g_yh);
    __half* p_yl;          cudaGetSymbolAddress((void**)&p_yl, g_yl);
    __half* p_wt16;        cudaGetSymbolAddress((void**)&p_wt16, g_wt16);
    __half* p_fvh;         cudaGetSymbolAddress((void**)&p_fvh, g_fvh);

    cudaFuncSetAttribute(gemm_mma_kernel,
                         cudaFuncAttributeMaxDynamicSharedMemorySize, GSMEM);
    cudaFuncSetAttribute(flash_tc_kernel,
                         cudaFuncAttributeMaxDynamicSharedMemorySize, FSMEM);

    rope_tables_kernel<<<(TT * 32 + 255) / 256, 256>>>();

    // Split x to fp16 hi/lo; transpose+truncate weights to fp16
    split_f16_kernel<<<(MM * CC / 4 + 255) / 256, 256>>>(qx, p_xh, p_xl, MM * CC / 4);
    wt16_kernel<<<dim3(32, 32, 4), dim3(32, 8)>>>(wq, wk, wv, wc);

    // QKV projections (fp32 out g_q/g_k/g_v in [B,H,T,HS] + bias)
    gemm_mma_kernel<<<dim3(MM / CTA_M, CC / CTA_N, 3), 256, GSMEM>>>(
        p_xh, p_xl, p_wt16, bq, bk, bv, nullptr, 1);

    // RoPE + fp16 operand prep; truncate V
    rope_split_kernel<<<(BB * HH * TT * 32 + 255) / 256, 256>>>();
    trunc_f16_kernel<<<(BB * HH * TT * HS / 4 + 255) / 256, 256>>>(
        p_v, p_fvh, BB * HH * TT * HS / 4);

    // Tensor-core flash attention -> g_yh/g_yl (fp16 split)
    flash_tc_kernel<<<dim3(TT / FBM, BB * HH), 256, FSMEM>>>();

    // Output projection -> d_out
    gemm_mma_kernel<<<dim3(MM / CTA_M, CC / CTA_N, 1), 256, GSMEM>>>(
        p_yh, p_yl, p_wt16 + (size_t)3 * CC * CC, bc, bc, bc, out, 0);
}

// round 9
// speedup vs baseline: 1.7777x; 1.2662x over previous
#include <cuda_runtime.h>
#include <cuda_bf16.h>
#include <cuda_fp16.h>
#include <math.h>
#include <stdint.h>

// Problem constants
#define BB 2
#define TT 2048
#define CC 1024
#define HH 16
#define HS 64
#define MM (BB*TT)       // 4096

// GEMM tiling (mma.sync fp16, 1 MMA, truncated operands), 256 threads
#define CTA_M 128
#define CTA_N 128
#define KSTG  32                 // K elems per smem stage
#define NS    (CC/KSTG)          // 32 stages
#define GSTGB 20480              // bytes per stage: Ah,Bh x 128x40 fp16
#define GSMEM (2*GSTGB)          // 40960

// Flash tiling (fp16 2-MMA, R8 version)
#define FBM 128                  // q rows per CTA
#define FBN 64                   // kv rows per tile
#define FSTR 72                  // padded smem row stride (fp16 elems; 144B)
// smem bytes: Qh@0, Ql@18432, Kh@36864, Vh@46080
#define FSMEM 55296

// Scratch (device globals: allocation-free)
__device__ float g_q[BB*HH*TT*HS];     // [B,H,T,HS] fp32 (pre-RoPE)
__device__ float g_k[BB*HH*TT*HS];
__device__ float g_v[BB*HH*TT*HS];
__device__ float g_cos[TT*32];
__device__ float g_sin[TT*32];

// fp16 operands for projections
__device__ __half g_xh[MM*CC];          // x truncated
__device__ __half g_yh[MM*CC];          // attn-out truncated
__device__ __half g_wt16[4*CC*CC];      // transposed fp16 weights [n][k]

// fp16 attention operands [B,H,T,HS]
__device__ __half g_fqh[BB*HH*TT*HS];   // Q hi (unscaled)
__device__ __half g_fql[BB*HH*TT*HS];   // Q lo
__device__ __half g_fkh[BB*HH*TT*HS];   // K * 0.125, truncated
__device__ __half g_fvh[BB*HH*TT*HS];   // V truncated

// ---------------------------------------------------------------------------
// PTX helpers (family-wide sm_80+ only)
// ---------------------------------------------------------------------------
__device__ __forceinline__ uint32_t smem_u32(const void* p) {
    uint32_t a;
    asm("{ .reg .u64 t; cvta.to.shared.u64 t, %1; cvt.u32.u64 %0, t; }" : "=r"(a) : "l"(p));
    return a;
}
__device__ __forceinline__ void ldsm_x4(uint32_t* r, uint32_t addr) {
    asm volatile("ldmatrix.sync.aligned.m8n8.x4.shared.b16 {%0,%1,%2,%3}, [%4];"
        : "=r"(r[0]), "=r"(r[1]), "=r"(r[2]), "=r"(r[3]) : "r"(addr));
}
__device__ __forceinline__ void ldsm_x2t(uint32_t* r, uint32_t addr) {
    asm volatile("ldmatrix.sync.aligned.m8n8.x2.trans.shared.b16 {%0,%1}, [%2];"
        : "=r"(r[0]), "=r"(r[1]) : "r"(addr));
}
__device__ __forceinline__ void mma_f16(float* c, const uint32_t* a, const uint32_t* b) {
    asm volatile(
        "mma.sync.aligned.m16n8k16.row.col.f32.f16.f16.f32 "
        "{%0,%1,%2,%3}, {%4,%5,%6,%7}, {%8,%9}, {%0,%1,%2,%3};"
        : "+f"(c[0]), "+f"(c[1]), "+f"(c[2]), "+f"(c[3])
        : "r"(a[0]), "r"(a[1]), "r"(a[2]), "r"(a[3]), "r"(b[0]), "r"(b[1]));
}
__device__ __forceinline__ uint32_t pack_f16x2(float lo, float hi) {
    __half2 v = __floats2half2_rn(lo, hi);
    return *(uint32_t*)&v;
}
__device__ __forceinline__ void cp_async16(uint32_t dst, const void* src) {
    asm volatile("cp.async.cg.shared.global [%0], [%1], 16;" :: "r"(dst), "l"(src));
}
__device__ __forceinline__ void cp_commit() {
    asm volatile("cp.async.commit_group;" ::: "memory");
}
__device__ __forceinline__ void cp_wait(int more) {
    if (more) asm volatile("cp.async.wait_group 1;" ::: "memory");
    else      asm volatile("cp.async.wait_group 0;" ::: "memory");
}

// ---------------------------------------------------------------------------
// RoPE tables
// ---------------------------------------------------------------------------
__global__ void rope_tables_kernel() {
    int idx = blockIdx.x * blockDim.x + threadIdx.x;   // t*32 + i
    if (idx >= TT * 32) return;
    int i = idx & 31;
    int t = idx >> 5;
    double invf_d = exp(-(double)i * (log(10000.0) / 32.0));
    float invf = (float)invf_d;
    float arg_f = (float)t * invf;
    double s, c;
    sincos((double)arg_f, &s, &c);
    g_cos[idx] = (float)c;
    g_sin[idx] = (float)s;
}

// ---------------------------------------------------------------------------
// fp32 -> fp16 truncate, vectorized x4
// ---------------------------------------------------------------------------
__global__ void trunc_f16_kernel(const float* __restrict__ src,
                                 __half* __restrict__ dst, int n4) {
    int i = blockIdx.x * blockDim.x + threadIdx.x;
    if (i >= n4) return;
    float4 v = ((const float4*)src)[i];
    __half2 a, b;
    a.x = __float2half(v.x); a.y = __float2half(v.y);
    b.x = __float2half(v.z); b.y = __float2half(v.w);
    ((__half2*)dst)[2*i]   = a;
    ((__half2*)dst)[2*i+1] = b;
}

// ---------------------------------------------------------------------------
// Weight transpose + fp16 truncate: Wt16[n][k] = fp16(W[k][n])
// ---------------------------------------------------------------------------
__global__ void wt16_kernel(const float* __restrict__ wq, const float* __restrict__ wk,
                            const float* __restrict__ wv, const float* __restrict__ wc) {
    __shared__ float tile[32][33];
    int wsel = blockIdx.z;
    const float* W = (wsel == 0) ? wq : (wsel == 1) ? wk : (wsel == 2) ? wv : wc;
    __half* Wt = g_wt16 + (size_t)wsel * CC * CC;
    int k0 = blockIdx.x * 32, n0 = blockIdx.y * 32;
    int tx = threadIdx.x, ty = threadIdx.y;   // (32,8)
    #pragma unroll
    for (int j = 0; j < 4; j++)
        tile[ty + 8*j][tx] = W[(size_t)(k0 + ty + 8*j) * CC + n0 + tx];
    __syncthreads();
    #pragma unroll
    for (int j = 0; j < 4; j++)
        Wt[(size_t)(n0 + ty + 8*j) * CC + k0 + tx] = __float2half(tile[tx][ty + 8*j]);
}

// ---------------------------------------------------------------------------
// fp16 single-MMA GEMM: D = Ah @ Bh^T (+bias), both operands truncated fp16.
// CTA 128x128, 8 warps 2x4, warp tile 64x32, 2-stage cp.async ring.
// Stage layout (bytes): Ah @0, Bh @10240 (row stride 80B)
// ---------------------------------------------------------------------------
__global__ void __launch_bounds__(256, 1) gemm_mma_kernel(
    const __half* __restrict__ Ahi,
    const __half* __restrict__ B_all,
    const float* __restrict__ bias_q, const float* __restrict__ bias_k,
    const float* __restrict__ bias_v,
    float* __restrict__ o_direct, int qkv_mode)
{
    extern __shared__ __half gsm[];
    uint32_t smbase = smem_u32(gsm);

    int tid = threadIdx.x;
    int wid = tid >> 5, lane = tid & 31;
    int wm = wid >> 2, wn = wid & 3;
    int m0 = blockIdx.x * CTA_M;
    int n0 = blockIdx.y * CTA_N;
    int which = blockIdx.z;
    const __half* Bh = B_all + (size_t)which * CC * CC;
    const float* bias = qkv_mode ? ((which == 0) ? bias_q : (which == 1) ? bias_k : bias_v)
                                 : bias_q;

    // Per-thread copy slots: 4 x 16B per stage
    const __half* gsrc[4];
    uint32_t soff[4];
    #pragma unroll
    for (int j = 0; j < 4; j++) {
        int id = tid + j * 256;                // 0..1023
        int sel = id >> 9;                     // 0 Ah, 1 Bh
        int cc = id & 511;
        int row = cc >> 2;
        int c16 = (cc & 3) * 8;
        const __half* base = (sel == 0) ? Ahi + (size_t)m0 * CC
                                        : Bh  + (size_t)n0 * CC;
        gsrc[j] = base + (size_t)row * CC + c16;
        soff[j] = sel * 10240u + row * 80u + c16 * 2u;
    }

    // ldmatrix base addresses within stage 0
    uint32_t aAh[4], bB[2];
    {
        int ra = lane & 15;
        int ca8 = ((lane >> 4) & 1) * 8;
        #pragma unroll
        for (int mf = 0; mf < 4; mf++)
            aAh[mf] = smbase + (wm * 64 + mf * 16 + ra) * 80u + ca8 * 2u;
        int rb = ((lane >> 4) & 1) * 8 + (lane & 7);
        int cb8 = ((lane >> 3) & 1) * 8;
        #pragma unroll
        for (int np = 0; np < 2; np++)
            bB[np] = smbase + 10240u + (wn * 32 + np * 16 + rb) * 80u + cb8 * 2u;
    }

    float acc[4][4][4] = {};

    // Preload stages 0,1
    #pragma unroll
    for (int j = 0; j < 4; j++) cp_async16(smbase + soff[j], gsrc[j]);
    cp_commit();
    #pragma unroll
    for (int j = 0; j < 4; j++) cp_async16(smbase + GSTGB + soff[j], gsrc[j] + KSTG);
    cp_commit();

    for (int s = 0; s < NS; s++) {
        cp_wait(s < NS - 1);
        __syncthreads();

        uint32_t sb = (s & 1) * GSTGB;
        #pragma unroll
        for (int kk = 0; kk < 2; kk++) {
            uint32_t ah[4][4], bh[2][4];
            #pragma unroll
            for (int mf = 0; mf < 4; mf++)
                ldsm_x4(ah[mf], aAh[mf] + sb + kk * 32);
            #pragma unroll
            for (int np = 0; np < 2; np++)
                ldsm_x4(bh[np], bB[np] + sb + kk * 32);
            #pragma unroll
            for (int mf = 0; mf < 4; mf++)
                #pragma unroll
                for (int nf = 0; nf < 4; nf++)
                    mma_f16(acc[mf][nf], ah[mf], &bh[nf >> 1][(nf & 1) * 2]);
        }
        __syncthreads();
        if (s + 2 < NS) {
            uint32_t db = smbase + (s & 1) * GSTGB;
            #pragma unroll
            for (int j = 0; j < 4; j++)
                cp_async16(db + soff[j], gsrc[j] + (s + 2) * KSTG);
            cp_commit();
        }
    }

    int group = lane >> 2, tig = lane & 3;
    #pragma unroll
    for (int mf = 0; mf < 4; mf++) {
        #pragma unroll
        for (int nf = 0; nf < 4; nf++) {
            int ncol = n0 + wn * 32 + nf * 8 + tig * 2;
            float2 bv = *(const float2*)&bias[ncol];
            #pragma unroll
            for (int half = 0; half < 2; half++) {
                int m = m0 + wm * 64 + mf * 16 + group + half * 8;
                float2 o;
                o.x = acc[mf][nf][half * 2 + 0] + bv.x;
                o.y = acc[mf][nf][half * 2 + 1] + bv.y;
                if (qkv_mode) {
                    float* outp = (which == 0) ? g_q : (which == 1) ? g_k : g_v;
                    int b = m >> 11, t = m & (TT - 1);
                    int h = ncol >> 6, d = ncol & 63;
                    *(float2*)&outp[(((size_t)b * HH + h) * TT + t) * HS + d] = o;
                } else {
                    *(float2*)&o_direct[(size_t)m * CC + ncol] = o;
                }
            }
        }
    }
}

// ---------------------------------------------------------------------------
// RoPE apply + fp16 operand prep.
// Q: unscaled, split fp16 hi/lo. K: scaled by 0.125, truncated fp16.
// ---------------------------------------------------------------------------
__global__ void rope_split_kernel() {
    int idx = blockIdx.x * blockDim.x + threadIdx.x;
    if (idx >= BB * HH * TT * 32) return;
    int i  = idx & 31;
    int t  = (idx >> 5) & (TT - 1);
    int bh = idx >> 16;
    float c = g_cos[(t << 5) + i];
    float s = g_sin[(t << 5) + i];
    int base = (bh * TT + t) * HS + i;

    float q1 = g_q[base], q2 = g_q[base + 32];
    float qa = q1 * c - q2 * s;
    float qb = q2 * c + q1 * s;
    __half h;
    h = __float2half(qa); g_fqh[base]      = h; g_fql[base]      = __float2half(qa - __half2float(h));
    h = __float2half(qb); g_fqh[base + 32] = h; g_fql[base + 32] = __float2half(qb - __half2float(h));

    float k1 = g_k[base], k2 = g_k[base + 32];
    g_fkh[base]      = __float2half((k1 * c - k2 * s) * 0.125f);
    g_fkh[base + 32] = __float2half((k2 * c + k1 * s) * 0.125f);
}

// ---------------------------------------------------------------------------
// Tensor-core flash attention (R8 passing version; epilogue writes g_yh only).
// Smem (bytes): Qh@0, Ql@18432, Kh@36864, Vh@46080; row stride 144B.
// ---------------------------------------------------------------------------
__global__ void __launch_bounds__(256) flash_tc_kernel() {
    extern __shared__ __half fsm[];
    uint32_t smbase = smem_u32(fsm);

    int qb = blockIdx.x;
    int bh = blockIdx.y;
    int q0 = qb * FBM;
    size_t hbase = (size_t)bh * TT * HS;

    int tid = threadIdx.x;
    int wid = tid >> 5, lane = tid & 31;
    int g = lane >> 2, tig = lane & 3;

    // ---- stage Q tile (128x64 hi/lo fp16) ----
    {
        const __half* Qh = g_fqh + hbase + (size_t)q0 * HS;
        const __half* Ql = g_fql + hbase + (size_t)q0 * HS;
        #pragma unroll
        for (int j = 0; j < 4; j++) {
            int c = tid + j * 256;            // 0..1023
            int row = c >> 3;
            int col8 = (c & 7) * 8;
            *(uint4*)&fsm[row * FSTR + col8] = *(const uint4*)&Qh[row * HS + col8];
            *(uint4*)&fsm[9216 + row * FSTR + col8] = *(const uint4*)&Ql[row * HS + col8];
        }
    }

    // K/V copy slots: 4 x uint4 per tile (Kh, Vh only)
    const __half* kvsrc[4];
    __half* kvdst[4];
    #pragma unroll
    for (int j = 0; j < 4; j++) {
        int c = tid + j * 256;                // 0..1023
        int sel = c >> 9;                     // 0 Kh, 1 Vh
        int cc = c & 511;
        int row = cc >> 3;
        int col8 = (cc & 7) * 8;
        kvsrc[j] = (sel ? g_fvh : g_fkh) + hbase + row * HS + col8;
        kvdst[j] = fsm + (sel ? 23040 : 18432) + row * FSTR + col8;
    }

    // ldmatrix base addresses (byte offsets)
    uint32_t aQh = smbase + (wid * 16 + (lane & 15)) * 144u + ((lane >> 4) & 1) * 16u;
    uint32_t aQl = aQh + 18432u;
    int rb = ((lane >> 4) & 1) * 8 + (lane & 7);
    int cb8 = ((lane >> 3) & 1) * 8;
    uint32_t aK[4];
    #pragma unroll
    for (int np = 0; np < 4; np++)
        aK[np] = smbase + 36864u + (np * 16 + rb) * 144u + cb8 * 2u;
    uint32_t aVh = smbase + 46080u + (lane & 15) * 144u;

    float m0 = -1e30f, m1 = -1e30f, l0 = 0.f, l1 = 0.f;
    float acc_o[8][4] = {};
    int rw0 = q0 + wid * 16;
    int rq0 = rw0 + g, rq1 = rq0 + 8;

    int ktmax = (q0 + FBM - 1) >> 6;

    uint4 pf[4];
    #pragma unroll
    for (int j = 0; j < 4; j++) pf[j] = *(const uint4*)(kvsrc[j]);

    for (int kt = 0; kt <= ktmax; kt++) {
        __syncthreads();
        #pragma unroll
        for (int j = 0; j < 4; j++) *(uint4*)(kvdst[j]) = pf[j];
        __syncthreads();
        if (kt < ktmax) {
            #pragma unroll
            for (int j = 0; j < 4; j++)
                pf[j] = *(const uint4*)(kvsrc[j] + (size_t)(kt + 1) * FBN * HS);
        }
        int k0 = kt * FBN;

        // ---- S = Q K^T (2-MMA fp16 split) ----
        float s[8][4] = {};
        #pragma unroll
        for (int kc = 0; kc < 4; kc++) {
            uint32_t qh[4], ql[4];
            ldsm_x4(qh, aQh + kc * 32);
            ldsm_x4(ql, aQl + kc * 32);
            #pragma unroll
            for (int np = 0; np < 4; np++) {
                uint32_t kh4[4];
                ldsm_x4(kh4, aK[np] + kc * 32);
                #pragma unroll
                for (int hf = 0; hf < 2; hf++) {
                    int nf = np * 2 + hf;
                    mma_f16(s[nf], qh, &kh4[hf * 2]);
                    mma_f16(s[nf], ql, &kh4[hf * 2]);
                }
            }
        }

        // ---- causal mask (diagonal tiles only) ----
        if (k0 + FBN - 1 > rw0) {
            #pragma unroll
            for (int nf = 0; nf < 8; nf++) {
                int c0 = k0 + nf * 8 + tig * 2;
                if (c0     > rq0) s[nf][0] = -1e30f;
                if (c0 + 1 > rq0) s[nf][1] = -1e30f;
                if (c0     > rq1) s[nf][2] = -1e30f;
                if (c0 + 1 > rq1) s[nf][3] = -1e30f;
            }
        }

        // ---- online softmax (fp32 on fragments) ----
        float mx0 = -1e30f, mx1 = -1e30f;
        #pragma unroll
        for (int nf = 0; nf < 8; nf++) {
            mx0 = fmaxf(mx0, fmaxf(s[nf][0], s[nf][1]));
            mx1 = fmaxf(mx1, fmaxf(s[nf][2], s[nf][3]));
        }
        #pragma unroll
        for (int off = 1; off <= 2; off <<= 1) {
            mx0 = fmaxf(mx0, __shfl_xor_sync(0xffffffffu, mx0, off));
            mx1 = fmaxf(mx1, __shfl_xor_sync(0xffffffffu, mx1, off));
        }
        float mn0 = fmaxf(m0, mx0), mn1 = fmaxf(m1, mx1);
        float sum0 = 0.f, sum1 = 0.f;
        #pragma unroll
        for (int nf = 0; nf < 8; nf++) {
            s[nf][0] = __expf(s[nf][0] - mn0);
            s[nf][1] = __expf(s[nf][1] - mn0);
            s[nf][2] = __expf(s[nf][2] - mn1);
            s[nf][3] = __expf(s[nf][3] - mn1);
            sum0 += s[nf][0] + s[nf][1];
            sum1 += s[nf][2] + s[nf][3];
        }
        #pragma unroll
        for (int off = 1; off <= 2; off <<= 1) {
            sum0 += __shfl_xor_sync(0xffffffffu, sum0, off);
            sum1 += __shfl_xor_sync(0xffffffffu, sum1, off);
        }
        float f0 = __expf(m0 - mn0), f1 = __expf(m1 - mn1);
        l0 = l0 * f0 + sum0; m0 = mn0;
        l1 = l1 * f1 + sum1; m1 = mn1;
        #pragma unroll
        for (int nf = 0; nf < 8; nf++) {
            acc_o[nf][0] *= f0; acc_o[nf][1] *= f0;
            acc_o[nf][2] *= f1; acc_o[nf][3] *= f1;
        }

        // ---- O += P V (P split fp16 hi/lo exactly; V truncated) ----
        #pragma unroll
        for (int jc = 0; jc < 4; jc++) {
            uint32_t aPh[4], aPl[4];
            {
                float p00 = s[2*jc][0],   p01 = s[2*jc][1];
                float p10 = s[2*jc][2],   p11 = s[2*jc][3];
                float p20 = s[2*jc+1][0], p21 = s[2*jc+1][1];
                float p30 = s[2*jc+1][2], p31 = s[2*jc+1][3];
                aPh[0] = pack_f16x2(p00, p01);
                aPh[1] = pack_f16x2(p10, p11);
                aPh[2] = pack_f16x2(p20, p21);
                aPh[3] = pack_f16x2(p30, p31);
                __half2 b0 = *(__half2*)&aPh[0];
                __half2 b1 = *(__half2*)&aPh[1];
                __half2 b2 = *(__half2*)&aPh[2];
                __half2 b3 = *(__half2*)&aPh[3];
                aPl[0] = pack_f16x2(p00 - __half2float(b0.x), p01 - __half2float(b0.y));
                aPl[1] = pack_f16x2(p10 - __half2float(b1.x), p11 - __half2float(b1.y));
                aPl[2] = pack_f16x2(p20 - __half2float(b2.x), p21 - __half2float(b2.y));
                aPl[3] = pack_f16x2(p30 - __half2float(b3.x), p31 - __half2float(b3.y));
            }
            #pragma unroll
            for (int nf = 0; nf < 8; nf++) {
                uint32_t vh2[2];
                ldsm_x2t(vh2, aVh + jc * 2304 + nf * 16);
                mma_f16(acc_o[nf], aPh, vh2);
                mma_f16(acc_o[nf], aPl, vh2);
            }
        }
    }

    // ---- epilogue: O/l -> g_yh fp16 (truncated), [B,T,C] ----
    {
        float inv0 = 1.f / l0, inv1 = 1.f / l1;
        int b = bh >> 4, h = bh & 15;
        size_t rb0 = ((size_t)b * TT + rq0) * CC;
        size_t rb1 = ((size_t)b * TT + rq1) * CC;
        #pragma unroll
        for (int nf = 0; nf < 8; nf++) {
            int col = h * HS + nf * 8 + tig * 2;
            __half2 hh;
            hh.x = __float2half(acc_o[nf][0] * inv0);
            hh.y = __float2half(acc_o[nf][1] * inv0);
            *(__half2*)&g_yh[rb0 + col] = hh;
            hh.x = __float2half(acc_o[nf][2] * inv1);
            hh.y = __float2half(acc_o[nf][3] * inv1);
            *(__half2*)&g_yh[rb1 + col] = hh;
        }
    }
}

// ---------------------------------------------------------------------------
extern "C" void kernel_launch(void* const* d_in, const int* in_sizes, int n_in,
                              void* d_out, int out_size) {
    const float* qx = (const float*)d_in[0];
    const float* wq = (const float*)d_in[1];
    const float* bq = (const float*)d_in[2];
    const float* wk = (const float*)d_in[3];
    const float* bk = (const float*)d_in[4];
    const float* wv = (const float*)d_in[5];
    const float* bv = (const float*)d_in[6];
    const float* wc = (const float*)d_in[7];
    const float* bc = (const float*)d_in[8];
    float* out = (float*)d_out;

    // device-global pointers
    float* p_v;            cudaGetSymbolAddress((void**)&p_v, g_v);
    __half* p_xh;          cudaGetSymbolAddress((void**)&p_xh, g_xh);
    __half* p_yh;          cudaGetSymbolAddress((void**)&p_yh, g_yh);
    __half* p_wt16;        cudaGetSymbolAddress((void**)&p_wt16, g_wt16);
    __half* p_fvh;         cudaGetSymbolAddress((void**)&p_fvh, g_fvh);

    cudaFuncSetAttribute(gemm_mma_kernel,
                         cudaFuncAttributeMaxDynamicSharedMemorySize, GSMEM);
    cudaFuncSetAttribute(flash_tc_kernel,
                         cudaFuncAttributeMaxDynamicSharedMemorySize, FSMEM);

    rope_tables_kernel<<<(TT * 32 + 255) / 256, 256>>>();

    // Truncate x to fp16; transpose+truncate weights to fp16
    trunc_f16_kernel<<<(MM * CC / 4 + 255) / 256, 256>>>(qx, p_xh, MM * CC / 4);
    wt16_kernel<<<dim3(32, 32, 4), dim3(32, 8)>>>(wq, wk, wv, wc);

    // QKV projections (fp32 out g_q/g_k/g_v in [B,H,T,HS] + bias)
    gemm_mma_kernel<<<dim3(MM / CTA_M, CC / CTA_N, 3), 256, GSMEM>>>(
        p_xh, p_wt16, bq, bk, bv, nullptr, 1);

    // RoPE + fp16 operand prep; truncate V
    rope_split_kernel<<<(BB * HH * TT * 32 + 255) / 256, 256>>>();
    trunc_f16_kernel<<<(BB * HH * TT * HS / 4 + 255) / 256, 256>>>(
        p_v, p_fvh, BB * HH * TT * HS / 4);

    // Tensor-core flash attention -> g_yh (fp16 truncated)
    flash_tc_kernel<<<dim3(TT / FBM, BB * HH), 256, FSMEM>>>();

    // Output projection -> d_out
    gemm_mma_kernel<<<dim3(MM / CTA_M, CC / CTA_N, 1), 256, GSMEM>>>(
        p_yh, p_wt16 + (size_t)3 * CC * CC, bc, bc, bc, out, 0);
}

// round 10
// speedup vs baseline: 1.9420x; 1.0924x over previous
#include <cuda_runtime.h>
#include <cuda_bf16.h>
#include <cuda_fp16.h>
#include <math.h>
#include <stdint.h>

// Problem constants
#define BB 2
#define TT 2048
#define CC 1024
#define HH 16
#define HS 64
#define MM (BB*TT)       // 4096

// GEMM tiling (mma.sync fp16, 1 MMA, truncated operands), 256 threads
#define CTA_M 128
#define CTA_N 128
#define KSTG  32                 // K elems per smem stage
#define NS    (CC/KSTG)          // 32 stages
#define GSTGB 20480              // bytes per stage: Ah,Bh x 128x40 fp16
#define GSMEM (2*GSTGB)          // 40960

// Flash tiling (fp16 2-MMA)
#define FBM 128                  // q rows per CTA
#define FBN 64                   // kv rows per tile
#define FSTR 72                  // padded smem row stride (fp16 elems; 144B)
// smem bytes: Qh@0, Ql@18432, Kh@36864, Vh@46080
#define FSMEM 55296

// Scratch (device globals: allocation-free)
__device__ float g_q[BB*HH*TT*HS];     // [B,H,T,HS] fp32 (pre-RoPE)
__device__ float g_k[BB*HH*TT*HS];
__device__ float g_v[BB*HH*TT*HS];
__device__ float g_cos[TT*32];
__device__ float g_sin[TT*32];

// fp16 operands for projections
__device__ __half g_xh[MM*CC];          // x truncated
__device__ __half g_yh[MM*CC];          // attn-out truncated
__device__ __half g_wt16[4*CC*CC];      // transposed fp16 weights [n][k]

// fp16 attention operands [B,H,T,HS]
__device__ __half g_fqh[BB*HH*TT*HS];   // Q hi (unscaled)
__device__ __half g_fql[BB*HH*TT*HS];   // Q lo
__device__ __half g_fkh[BB*HH*TT*HS];   // K * 0.125, truncated
__device__ __half g_fvh[BB*HH*TT*HS];   // V truncated

// ---------------------------------------------------------------------------
// PTX helpers (family-wide sm_80+ only)
// ---------------------------------------------------------------------------
__device__ __forceinline__ uint32_t smem_u32(const void* p) {
    uint32_t a;
    asm("{ .reg .u64 t; cvta.to.shared.u64 t, %1; cvt.u32.u64 %0, t; }" : "=r"(a) : "l"(p));
    return a;
}
__device__ __forceinline__ void ldsm_x4(uint32_t* r, uint32_t addr) {
    asm volatile("ldmatrix.sync.aligned.m8n8.x4.shared.b16 {%0,%1,%2,%3}, [%4];"
        : "=r"(r[0]), "=r"(r[1]), "=r"(r[2]), "=r"(r[3]) : "r"(addr));
}
__device__ __forceinline__ void ldsm_x2t(uint32_t* r, uint32_t addr) {
    asm volatile("ldmatrix.sync.aligned.m8n8.x2.trans.shared.b16 {%0,%1}, [%2];"
        : "=r"(r[0]), "=r"(r[1]) : "r"(addr));
}
__device__ __forceinline__ void mma_f16(float* c, const uint32_t* a, const uint32_t* b) {
    asm volatile(
        "mma.sync.aligned.m16n8k16.row.col.f32.f16.f16.f32 "
        "{%0,%1,%2,%3}, {%4,%5,%6,%7}, {%8,%9}, {%0,%1,%2,%3};"
        : "+f"(c[0]), "+f"(c[1]), "+f"(c[2]), "+f"(c[3])
        : "r"(a[0]), "r"(a[1]), "r"(a[2]), "r"(a[3]), "r"(b[0]), "r"(b[1]));
}
__device__ __forceinline__ uint32_t pack_f16x2(float lo, float hi) {
    __half2 v = __floats2half2_rn(lo, hi);
    return *(uint32_t*)&v;
}
__device__ __forceinline__ void cp_async16(uint32_t dst, const void* src) {
    asm volatile("cp.async.cg.shared.global [%0], [%1], 16;" :: "r"(dst), "l"(src));
}
__device__ __forceinline__ void cp_commit() {
    asm volatile("cp.async.commit_group;" ::: "memory");
}
__device__ __forceinline__ void cp_wait(int more) {
    if (more) asm volatile("cp.async.wait_group 1;" ::: "memory");
    else      asm volatile("cp.async.wait_group 0;" ::: "memory");
}

// ---------------------------------------------------------------------------
// RoPE tables
// ---------------------------------------------------------------------------
__global__ void rope_tables_kernel() {
    int idx = blockIdx.x * blockDim.x + threadIdx.x;   // t*32 + i
    if (idx >= TT * 32) return;
    int i = idx & 31;
    int t = idx >> 5;
    double invf_d = exp(-(double)i * (log(10000.0) / 32.0));
    float invf = (float)invf_d;
    float arg_f = (float)t * invf;
    double s, c;
    sincos((double)arg_f, &s, &c);
    g_cos[idx] = (float)c;
    g_sin[idx] = (float)s;
}

// ---------------------------------------------------------------------------
// fp32 -> fp16 truncate, vectorized x4
// ---------------------------------------------------------------------------
__global__ void trunc_f16_kernel(const float* __restrict__ src,
                                 __half* __restrict__ dst, int n4) {
    int i = blockIdx.x * blockDim.x + threadIdx.x;
    if (i >= n4) return;
    float4 v = ((const float4*)src)[i];
    __half2 a, b;
    a.x = __float2half(v.x); a.y = __float2half(v.y);
    b.x = __float2half(v.z); b.y = __float2half(v.w);
    ((__half2*)dst)[2*i]   = a;
    ((__half2*)dst)[2*i+1] = b;
}

// ---------------------------------------------------------------------------
// Weight transpose + fp16 truncate: Wt16[n][k] = fp16(W[k][n])
// ---------------------------------------------------------------------------
__global__ void wt16_kernel(const float* __restrict__ wq, const float* __restrict__ wk,
                            const float* __restrict__ wv, const float* __restrict__ wc) {
    __shared__ float tile[32][33];
    int wsel = blockIdx.z;
    const float* W = (wsel == 0) ? wq : (wsel == 1) ? wk : (wsel == 2) ? wv : wc;
    __half* Wt = g_wt16 + (size_t)wsel * CC * CC;
    int k0 = blockIdx.x * 32, n0 = blockIdx.y * 32;
    int tx = threadIdx.x, ty = threadIdx.y;   // (32,8)
    #pragma unroll
    for (int j = 0; j < 4; j++)
        tile[ty + 8*j][tx] = W[(size_t)(k0 + ty + 8*j) * CC + n0 + tx];
    __syncthreads();
    #pragma unroll
    for (int j = 0; j < 4; j++)
        Wt[(size_t)(n0 + ty + 8*j) * CC + k0 + tx] = __float2half(tile[tx][ty + 8*j]);
}

// ---------------------------------------------------------------------------
// fp16 single-MMA GEMM: D = Ah @ Bh^T (+bias), both operands truncated fp16.
// CTA 128x128, 8 warps 2x4, warp tile 64x32, 2-stage cp.async ring.
// __launch_bounds__(256, 2): 2 CTAs/SM for latency hiding.
// Stage layout (bytes): Ah @0, Bh @10240 (row stride 80B)
// ---------------------------------------------------------------------------
__global__ void __launch_bounds__(256, 2) gemm_mma_kernel(
    const __half* __restrict__ Ahi,
    const __half* __restrict__ B_all,
    const float* __restrict__ bias_q, const float* __restrict__ bias_k,
    const float* __restrict__ bias_v,
    float* __restrict__ o_direct, int qkv_mode)
{
    extern __shared__ __half gsm[];
    uint32_t smbase = smem_u32(gsm);

    int tid = threadIdx.x;
    int wid = tid >> 5, lane = tid & 31;
    int wm = wid >> 2, wn = wid & 3;
    int m0 = blockIdx.x * CTA_M;
    int n0 = blockIdx.y * CTA_N;
    int which = blockIdx.z;
    const __half* Bh = B_all + (size_t)which * CC * CC;
    const float* bias = qkv_mode ? ((which == 0) ? bias_q : (which == 1) ? bias_k : bias_v)
                                 : bias_q;

    // Per-thread copy slots: 4 x 16B per stage
    const __half* gsrc[4];
    uint32_t soff[4];
    #pragma unroll
    for (int j = 0; j < 4; j++) {
        int id = tid + j * 256;                // 0..1023
        int sel = id >> 9;                     // 0 Ah, 1 Bh
        int cc = id & 511;
        int row = cc >> 2;
        int c16 = (cc & 3) * 8;
        const __half* base = (sel == 0) ? Ahi + (size_t)m0 * CC
                                        : Bh  + (size_t)n0 * CC;
        gsrc[j] = base + (size_t)row * CC + c16;
        soff[j] = sel * 10240u + row * 80u + c16 * 2u;
    }

    // ldmatrix base addresses within stage 0
    uint32_t aAh[4], bB[2];
    {
        int ra = lane & 15;
        int ca8 = ((lane >> 4) & 1) * 8;
        #pragma unroll
        for (int mf = 0; mf < 4; mf++)
            aAh[mf] = smbase + (wm * 64 + mf * 16 + ra) * 80u + ca8 * 2u;
        int rb = ((lane >> 4) & 1) * 8 + (lane & 7);
        int cb8 = ((lane >> 3) & 1) * 8;
        #pragma unroll
        for (int np = 0; np < 2; np++)
            bB[np] = smbase + 10240u + (wn * 32 + np * 16 + rb) * 80u + cb8 * 2u;
    }

    float acc[4][4][4] = {};

    // Preload stages 0,1
    #pragma unroll
    for (int j = 0; j < 4; j++) cp_async16(smbase + soff[j], gsrc[j]);
    cp_commit();
    #pragma unroll
    for (int j = 0; j < 4; j++) cp_async16(smbase + GSTGB + soff[j], gsrc[j] + KSTG);
    cp_commit();

    for (int s = 0; s < NS; s++) {
        cp_wait(s < NS - 1);
        __syncthreads();

        uint32_t sb = (s & 1) * GSTGB;
        #pragma unroll
        for (int kk = 0; kk < 2; kk++) {
            uint32_t ah[4][4], bh[2][4];
            #pragma unroll
            for (int mf = 0; mf < 4; mf++)
                ldsm_x4(ah[mf], aAh[mf] + sb + kk * 32);
            #pragma unroll
            for (int np = 0; np < 2; np++)
                ldsm_x4(bh[np], bB[np] + sb + kk * 32);
            #pragma unroll
            for (int mf = 0; mf < 4; mf++)
                #pragma unroll
                for (int nf = 0; nf < 4; nf++)
                    mma_f16(acc[mf][nf], ah[mf], &bh[nf >> 1][(nf & 1) * 2]);
        }
        __syncthreads();
        if (s + 2 < NS) {
            uint32_t db = smbase + (s & 1) * GSTGB;
            #pragma unroll
            for (int j = 0; j < 4; j++)
                cp_async16(db + soff[j], gsrc[j] + (s + 2) * KSTG);
            cp_commit();
        }
    }

    int group = lane >> 2, tig = lane & 3;
    #pragma unroll
    for (int mf = 0; mf < 4; mf++) {
        #pragma unroll
        for (int nf = 0; nf < 4; nf++) {
            int ncol = n0 + wn * 32 + nf * 8 + tig * 2;
            float2 bv = *(const float2*)&bias[ncol];
            #pragma unroll
            for (int half = 0; half < 2; half++) {
                int m = m0 + wm * 64 + mf * 16 + group + half * 8;
                float2 o;
                o.x = acc[mf][nf][half * 2 + 0] + bv.x;
                o.y = acc[mf][nf][half * 2 + 1] + bv.y;
                if (qkv_mode) {
                    float* outp = (which == 0) ? g_q : (which == 1) ? g_k : g_v;
                    int b = m >> 11, t = m & (TT - 1);
                    int h = ncol >> 6, d = ncol & 63;
                    *(float2*)&outp[(((size_t)b * HH + h) * TT + t) * HS + d] = o;
                } else {
                    *(float2*)&o_direct[(size_t)m * CC + ncol] = o;
                }
            }
        }
    }
}

// ---------------------------------------------------------------------------
// RoPE apply + fp16 operand prep.
// Q: unscaled, split fp16 hi/lo. K: scaled by 0.125, truncated fp16.
// ---------------------------------------------------------------------------
__global__ void rope_split_kernel() {
    int idx = blockIdx.x * blockDim.x + threadIdx.x;
    if (idx >= BB * HH * TT * 32) return;
    int i  = idx & 31;
    int t  = (idx >> 5) & (TT - 1);
    int bh = idx >> 16;
    float c = g_cos[(t << 5) + i];
    float s = g_sin[(t << 5) + i];
    int base = (bh * TT + t) * HS + i;

    float q1 = g_q[base], q2 = g_q[base + 32];
    float qa = q1 * c - q2 * s;
    float qb = q2 * c + q1 * s;
    __half h;
    h = __float2half(qa); g_fqh[base]      = h; g_fql[base]      = __float2half(qa - __half2float(h));
    h = __float2half(qb); g_fqh[base + 32] = h; g_fql[base + 32] = __float2half(qb - __half2float(h));

    float k1 = g_k[base], k2 = g_k[base + 32];
    g_fkh[base]      = __float2half((k1 * c - k2 * s) * 0.125f);
    g_fkh[base + 32] = __float2half((k2 * c + k1 * s) * 0.125f);
}

// ---------------------------------------------------------------------------
// Tensor-core flash attention (fp16 2-MMA split, fp32 softmax).
// __launch_bounds__(256, 2): 2 CTAs/SM.
// Smem (bytes): Qh@0, Ql@18432, Kh@36864, Vh@46080; row stride 144B.
// ---------------------------------------------------------------------------
__global__ void __launch_bounds__(256, 2) flash_tc_kernel() {
    extern __shared__ __half fsm[];
    uint32_t smbase = smem_u32(fsm);

    int qb = blockIdx.x;
    int bh = blockIdx.y;
    int q0 = qb * FBM;
    size_t hbase = (size_t)bh * TT * HS;

    int tid = threadIdx.x;
    int wid = tid >> 5, lane = tid & 31;
    int g = lane >> 2, tig = lane & 3;

    // ---- stage Q tile (128x64 hi/lo fp16) ----
    {
        const __half* Qh = g_fqh + hbase + (size_t)q0 * HS;
        const __half* Ql = g_fql + hbase + (size_t)q0 * HS;
        #pragma unroll
        for (int j = 0; j < 4; j++) {
            int c = tid + j * 256;            // 0..1023
            int row = c >> 3;
            int col8 = (c & 7) * 8;
            *(uint4*)&fsm[row * FSTR + col8] = *(const uint4*)&Qh[row * HS + col8];
            *(uint4*)&fsm[9216 + row * FSTR + col8] = *(const uint4*)&Ql[row * HS + col8];
        }
    }

    // K/V copy slots: 4 x uint4 per tile (Kh, Vh only)
    const __half* kvsrc[4];
    __half* kvdst[4];
    #pragma unroll
    for (int j = 0; j < 4; j++) {
        int c = tid + j * 256;                // 0..1023
        int sel = c >> 9;                     // 0 Kh, 1 Vh
        int cc = c & 511;
        int row = cc >> 3;
        int col8 = (cc & 7) * 8;
        kvsrc[j] = (sel ? g_fvh : g_fkh) + hbase + row * HS + col8;
        kvdst[j] = fsm + (sel ? 23040 : 18432) + row * FSTR + col8;
    }

    // ldmatrix base addresses (byte offsets)
    uint32_t aQh = smbase + (wid * 16 + (lane & 15)) * 144u + ((lane >> 4) & 1) * 16u;
    uint32_t aQl = aQh + 18432u;
    int rb = ((lane >> 4) & 1) * 8 + (lane & 7);
    int cb8 = ((lane >> 3) & 1) * 8;
    uint32_t aK[4];
    #pragma unroll
    for (int np = 0; np < 4; np++)
        aK[np] = smbase + 36864u + (np * 16 + rb) * 144u + cb8 * 2u;
    uint32_t aVh = smbase + 46080u + (lane & 15) * 144u;

    float m0 = -1e30f, m1 = -1e30f, l0 = 0.f, l1 = 0.f;
    float acc_o[8][4] = {};
    int rw0 = q0 + wid * 16;
    int rq0 = rw0 + g, rq1 = rq0 + 8;

    int ktmax = (q0 + FBM - 1) >> 6;

    uint4 pf[4];
    #pragma unroll
    for (int j = 0; j < 4; j++) pf[j] = *(const uint4*)(kvsrc[j]);

    for (int kt = 0; kt <= ktmax; kt++) {
        __syncthreads();
        #pragma unroll
        for (int j = 0; j < 4; j++) *(uint4*)(kvdst[j]) = pf[j];
        __syncthreads();
        if (kt < ktmax) {
            #pragma unroll
            for (int j = 0; j < 4; j++)
                pf[j] = *(const uint4*)(kvsrc[j] + (size_t)(kt + 1) * FBN * HS);
        }
        int k0 = kt * FBN;

        // ---- S = Q K^T (2-MMA fp16 split) ----
        float s[8][4] = {};
        #pragma unroll
        for (int kc = 0; kc < 4; kc++) {
            uint32_t qh[4], ql[4];
            ldsm_x4(qh, aQh + kc * 32);
            ldsm_x4(ql, aQl + kc * 32);
            #pragma unroll
            for (int np = 0; np < 4; np++) {
                uint32_t kh4[4];
                ldsm_x4(kh4, aK[np] + kc * 32);
                #pragma unroll
                for (int hf = 0; hf < 2; hf++) {
                    int nf = np * 2 + hf;
                    mma_f16(s[nf], qh, &kh4[hf * 2]);
                    mma_f16(s[nf], ql, &kh4[hf * 2]);
                }
            }
        }

        // ---- causal mask (diagonal tiles only) ----
        if (k0 + FBN - 1 > rw0) {
            #pragma unroll
            for (int nf = 0; nf < 8; nf++) {
                int c0 = k0 + nf * 8 + tig * 2;
                if (c0     > rq0) s[nf][0] = -1e30f;
                if (c0 + 1 > rq0) s[nf][1] = -1e30f;
                if (c0     > rq1) s[nf][2] = -1e30f;
                if (c0 + 1 > rq1) s[nf][3] = -1e30f;
            }
        }

        // ---- online softmax (fp32 on fragments) ----
        float mx0 = -1e30f, mx1 = -1e30f;
        #pragma unroll
        for (int nf = 0; nf < 8; nf++) {
            mx0 = fmaxf(mx0, fmaxf(s[nf][0], s[nf][1]));
            mx1 = fmaxf(mx1, fmaxf(s[nf][2], s[nf][3]));
        }
        #pragma unroll
        for (int off = 1; off <= 2; off <<= 1) {
            mx0 = fmaxf(mx0, __shfl_xor_sync(0xffffffffu, mx0, off));
            mx1 = fmaxf(mx1, __shfl_xor_sync(0xffffffffu, mx1, off));
        }
        float mn0 = fmaxf(m0, mx0), mn1 = fmaxf(m1, mx1);
        float sum0 = 0.f, sum1 = 0.f;
        #pragma unroll
        for (int nf = 0; nf < 8; nf++) {
            s[nf][0] = __expf(s[nf][0] - mn0);
            s[nf][1] = __expf(s[nf][1] - mn0);
            s[nf][2] = __expf(s[nf][2] - mn1);
            s[nf][3] = __expf(s[nf][3] - mn1);
            sum0 += s[nf][0] + s[nf][1];
            sum1 += s[nf][2] + s[nf][3];
        }
        #pragma unroll
        for (int off = 1; off <= 2; off <<= 1) {
            sum0 += __shfl_xor_sync(0xffffffffu, sum0, off);
            sum1 += __shfl_xor_sync(0xffffffffu, sum1, off);
        }
        float f0 = __expf(m0 - mn0), f1 = __expf(m1 - mn1);
        l0 = l0 * f0 + sum0; m0 = mn0;
        l1 = l1 * f1 + sum1; m1 = mn1;
        #pragma unroll
        for (int nf = 0; nf < 8; nf++) {
            acc_o[nf][0] *= f0; acc_o[nf][1] *= f0;
            acc_o[nf][2] *= f1; acc_o[nf][3] *= f1;
        }

        // ---- O += P V (P split fp16 hi/lo exactly; V truncated) ----
        #pragma unroll
        for (int jc = 0; jc < 4; jc++) {
            uint32_t aPh[4], aPl[4];
            {
                float p00 = s[2*jc][0],   p01 = s[2*jc][1];
                float p10 = s[2*jc][2],   p11 = s[2*jc][3];
                float p20 = s[2*jc+1][0], p21 = s[2*jc+1][1];
                float p30 = s[2*jc+1][2], p31 = s[2*jc+1][3];
                aPh[0] = pack_f16x2(p00, p01);
                aPh[1] = pack_f16x2(p10, p11);
                aPh[2] = pack_f16x2(p20, p21);
                aPh[3] = pack_f16x2(p30, p31);
                __half2 b0 = *(__half2*)&aPh[0];
                __half2 b1 = *(__half2*)&aPh[1];
                __half2 b2 = *(__half2*)&aPh[2];
                __half2 b3 = *(__half2*)&aPh[3];
                aPl[0] = pack_f16x2(p00 - __half2float(b0.x), p01 - __half2float(b0.y));
                aPl[1] = pack_f16x2(p10 - __half2float(b1.x), p11 - __half2float(b1.y));
                aPl[2] = pack_f16x2(p20 - __half2float(b2.x), p21 - __half2float(b2.y));
                aPl[3] = pack_f16x2(p30 - __half2float(b3.x), p31 - __half2float(b3.y));
            }
            #pragma unroll
            for (int nf = 0; nf < 8; nf++) {
                uint32_t vh2[2];
                ldsm_x2t(vh2, aVh + jc * 2304 + nf * 16);
                mma_f16(acc_o[nf], aPh, vh2);
                mma_f16(acc_o[nf], aPl, vh2);
            }
        }
    }

    // ---- epilogue: O/l -> g_yh fp16 (truncated), [B,T,C] ----
    {
        float inv0 = 1.f / l0, inv1 = 1.f / l1;
        int b = bh >> 4, h = bh & 15;
        size_t rb0 = ((size_t)b * TT + rq0) * CC;
        size_t rb1 = ((size_t)b * TT + rq1) * CC;
        #pragma unroll
        for (int nf = 0; nf < 8; nf++) {
            int col = h * HS + nf * 8 + tig * 2;
            __half2 hh;
            hh.x = __float2half(acc_o[nf][0] * inv0);
            hh.y = __float2half(acc_o[nf][1] * inv0);
            *(__half2*)&g_yh[rb0 + col] = hh;
            hh.x = __float2half(acc_o[nf][2] * inv1);
            hh.y = __float2half(acc_o[nf][3] * inv1);
            *(__half2*)&g_yh[rb1 + col] = hh;
        }
    }
}

// ---------------------------------------------------------------------------
extern "C" void kernel_launch(void* const* d_in, const int* in_sizes, int n_in,
                              void* d_out, int out_size) {
    const float* qx = (const float*)d_in[0];
    const float* wq = (const float*)d_in[1];
    const float* bq = (const float*)d_in[2];
    const float* wk = (const float*)d_in[3];
    const float* bk = (const float*)d_in[4];
    const float* wv = (const float*)d_in[5];
    const float* bv = (const float*)d_in[6];
    const float* wc = (const float*)d_in[7];
    const float* bc = (const float*)d_in[8];
    float* out = (float*)d_out;

    // device-global pointers
    float* p_v;            cudaGetSymbolAddress((void**)&p_v, g_v);
    __half* p_xh;          cudaGetSymbolAddress((void**)&p_xh, g_xh);
    __half* p_yh;          cudaGetSymbolAddress((void**)&p_yh, g_yh);
    __half* p_wt16;        cudaGetSymbolAddress((void**)&p_wt16, g_wt16);
    __half* p_fvh;         cudaGetSymbolAddress((void**)&p_fvh, g_fvh);

    cudaFuncSetAttribute(gemm_mma_kernel,
                         cudaFuncAttributeMaxDynamicSharedMemorySize, GSMEM);
    cudaFuncSetAttribute(flash_tc_kernel,
                         cudaFuncAttributeMaxDynamicSharedMemorySize, FSMEM);

    rope_tables_kernel<<<(TT * 32 + 255) / 256, 256>>>();

    // Truncate x to fp16; transpose+truncate weights to fp16
    trunc_f16_kernel<<<(MM * CC / 4 + 255) / 256, 256>>>(qx, p_xh, MM * CC / 4);
    wt16_kernel<<<dim3(32, 32, 4), dim3(32, 8)>>>(wq, wk, wv, wc);

    // QKV projections (fp32 out g_q/g_k/g_v in [B,H,T,HS] + bias)
    gemm_mma_kernel<<<dim3(MM / CTA_M, CC / CTA_N, 3), 256, GSMEM>>>(
        p_xh, p_wt16, bq, bk, bv, nullptr, 1);

    // RoPE + fp16 operand prep; truncate V
    rope_split_kernel<<<(BB * HH * TT * 32 + 255) / 256, 256>>>();
    trunc_f16_kernel<<<(BB * HH * TT * HS / 4 + 255) / 256, 256>>>(
        p_v, p_fvh, BB * HH * TT * HS / 4);

    // Tensor-core flash attention -> g_yh (fp16 truncated)
    flash_tc_kernel<<<dim3(TT / FBM, BB * HH), 256, FSMEM>>>();

    // Output projection -> d_out
    gemm_mma_kernel<<<dim3(MM / CTA_M, CC / CTA_N, 1), 256, GSMEM>>>(
        p_yh, p_wt16 + (size_t)3 * CC * CC, bc, bc, bc, out, 0);
}

// round 11
// speedup vs baseline: 2.3254x; 1.1974x over previous
#include <cuda_runtime.h>
#include <cuda_bf16.h>
#include <cuda_fp16.h>
#include <math.h>
#include <stdint.h>

// Problem constants
#define BB 2
#define TT 2048
#define CC 1024
#define HH 16
#define HS 64
#define MM (BB*TT)       // 4096

// GEMM tiling (mma.sync fp16, 1 MMA, truncated operands), 256 threads
#define CTA_M 128
#define CTA_N 128
#define KSTG  32                 // K elems per smem stage
#define NS    (CC/KSTG)          // 32 stages
#define GSTGB 20480              // bytes per stage: Ah,Bh x 128x40 fp16
#define GSMEM (2*GSTGB)          // 40960

// Flash tiling (fp16 1-MMA)
#define FBM 128                  // q rows per CTA
#define FBN 64                   // kv rows per tile
#define FSTR 72                  // padded smem row stride (fp16 elems; 144B)
// smem half-offsets: Qh@0, Kh@9216, Vh@13824 ; bytes: 18432 / 27648
#define FSMEM 36864

// Scratch (device globals: allocation-free)
__device__ float g_q[BB*HH*TT*HS];     // [B,H,T,HS] fp32 (pre-RoPE)
__device__ float g_k[BB*HH*TT*HS];
__device__ float g_v[BB*HH*TT*HS];
__device__ float g_cos[TT*32];
__device__ float g_sin[TT*32];

// fp16 operands for projections
__device__ __half g_xh[MM*CC];          // x truncated
__device__ __half g_yh[MM*CC];          // attn-out truncated
__device__ __half g_wt16[4*CC*CC];      // transposed fp16 weights [n][k]

// fp16 attention operands [B,H,T,HS]
__device__ __half g_fqh[BB*HH*TT*HS];   // Q truncated (unscaled)
__device__ __half g_fkh[BB*HH*TT*HS];   // K * 0.125, truncated
__device__ __half g_fvh[BB*HH*TT*HS];   // V truncated

// ---------------------------------------------------------------------------
// PTX helpers (family-wide sm_80+ only)
// ---------------------------------------------------------------------------
__device__ __forceinline__ uint32_t smem_u32(const void* p) {
    uint32_t a;
    asm("{ .reg .u64 t; cvta.to.shared.u64 t, %1; cvt.u32.u64 %0, t; }" : "=r"(a) : "l"(p));
    return a;
}
__device__ __forceinline__ void ldsm_x4(uint32_t* r, uint32_t addr) {
    asm volatile("ldmatrix.sync.aligned.m8n8.x4.shared.b16 {%0,%1,%2,%3}, [%4];"
        : "=r"(r[0]), "=r"(r[1]), "=r"(r[2]), "=r"(r[3]) : "r"(addr));
}
__device__ __forceinline__ void ldsm_x2t(uint32_t* r, uint32_t addr) {
    asm volatile("ldmatrix.sync.aligned.m8n8.x2.trans.shared.b16 {%0,%1}, [%2];"
        : "=r"(r[0]), "=r"(r[1]) : "r"(addr));
}
__device__ __forceinline__ void mma_f16(float* c, const uint32_t* a, const uint32_t* b) {
    asm volatile(
        "mma.sync.aligned.m16n8k16.row.col.f32.f16.f16.f32 "
        "{%0,%1,%2,%3}, {%4,%5,%6,%7}, {%8,%9}, {%0,%1,%2,%3};"
        : "+f"(c[0]), "+f"(c[1]), "+f"(c[2]), "+f"(c[3])
        : "r"(a[0]), "r"(a[1]), "r"(a[2]), "r"(a[3]), "r"(b[0]), "r"(b[1]));
}
__device__ __forceinline__ uint32_t pack_f16x2(float lo, float hi) {
    __half2 v = __floats2half2_rn(lo, hi);
    return *(uint32_t*)&v;
}
__device__ __forceinline__ void cp_async16(uint32_t dst, const void* src) {
    asm volatile("cp.async.cg.shared.global [%0], [%1], 16;" :: "r"(dst), "l"(src));
}
__device__ __forceinline__ void cp_commit() {
    asm volatile("cp.async.commit_group;" ::: "memory");
}
__device__ __forceinline__ void cp_wait(int more) {
    if (more) asm volatile("cp.async.wait_group 1;" ::: "memory");
    else      asm volatile("cp.async.wait_group 0;" ::: "memory");
}

// ---------------------------------------------------------------------------
// RoPE tables
// ---------------------------------------------------------------------------
__global__ void rope_tables_kernel() {
    int idx = blockIdx.x * blockDim.x + threadIdx.x;   // t*32 + i
    if (idx >= TT * 32) return;
    int i = idx & 31;
    int t = idx >> 5;
    double invf_d = exp(-(double)i * (log(10000.0) / 32.0));
    float invf = (float)invf_d;
    float arg_f = (float)t * invf;
    double s, c;
    sincos((double)arg_f, &s, &c);
    g_cos[idx] = (float)c;
    g_sin[idx] = (float)s;
}

// ---------------------------------------------------------------------------
// fp32 -> fp16 truncate, vectorized x4
// ---------------------------------------------------------------------------
__global__ void trunc_f16_kernel(const float* __restrict__ src,
                                 __half* __restrict__ dst, int n4) {
    int i = blockIdx.x * blockDim.x + threadIdx.x;
    if (i >= n4) return;
    float4 v = ((const float4*)src)[i];
    __half2 a, b;
    a.x = __float2half(v.x); a.y = __float2half(v.y);
    b.x = __float2half(v.z); b.y = __float2half(v.w);
    ((__half2*)dst)[2*i]   = a;
    ((__half2*)dst)[2*i+1] = b;
}

// ---------------------------------------------------------------------------
// Weight transpose + fp16 truncate: Wt16[n][k] = fp16(W[k][n])
// ---------------------------------------------------------------------------
__global__ void wt16_kernel(const float* __restrict__ wq, const float* __restrict__ wk,
                            const float* __restrict__ wv, const float* __restrict__ wc) {
    __shared__ float tile[32][33];
    int wsel = blockIdx.z;
    const float* W = (wsel == 0) ? wq : (wsel == 1) ? wk : (wsel == 2) ? wv : wc;
    __half* Wt = g_wt16 + (size_t)wsel * CC * CC;
    int k0 = blockIdx.x * 32, n0 = blockIdx.y * 32;
    int tx = threadIdx.x, ty = threadIdx.y;   // (32,8)
    #pragma unroll
    for (int j = 0; j < 4; j++)
        tile[ty + 8*j][tx] = W[(size_t)(k0 + ty + 8*j) * CC + n0 + tx];
    __syncthreads();
    #pragma unroll
    for (int j = 0; j < 4; j++)
        Wt[(size_t)(n0 + ty + 8*j) * CC + k0 + tx] = __float2half(tile[tx][ty + 8*j]);
}

// ---------------------------------------------------------------------------
// fp16 single-MMA GEMM (R10 passing version, unchanged).
// ---------------------------------------------------------------------------
__global__ void __launch_bounds__(256, 2) gemm_mma_kernel(
    const __half* __restrict__ Ahi,
    const __half* __restrict__ B_all,
    const float* __restrict__ bias_q, const float* __restrict__ bias_k,
    const float* __restrict__ bias_v,
    float* __restrict__ o_direct, int qkv_mode)
{
    extern __shared__ __half gsm[];
    uint32_t smbase = smem_u32(gsm);

    int tid = threadIdx.x;
    int wid = tid >> 5, lane = tid & 31;
    int wm = wid >> 2, wn = wid & 3;
    int m0 = blockIdx.x * CTA_M;
    int n0 = blockIdx.y * CTA_N;
    int which = blockIdx.z;
    const __half* Bh = B_all + (size_t)which * CC * CC;
    const float* bias = qkv_mode ? ((which == 0) ? bias_q : (which == 1) ? bias_k : bias_v)
                                 : bias_q;

    const __half* gsrc[4];
    uint32_t soff[4];
    #pragma unroll
    for (int j = 0; j < 4; j++) {
        int id = tid + j * 256;                // 0..1023
        int sel = id >> 9;                     // 0 Ah, 1 Bh
        int cc = id & 511;
        int row = cc >> 2;
        int c16 = (cc & 3) * 8;
        const __half* base = (sel == 0) ? Ahi + (size_t)m0 * CC
                                        : Bh  + (size_t)n0 * CC;
        gsrc[j] = base + (size_t)row * CC + c16;
        soff[j] = sel * 10240u + row * 80u + c16 * 2u;
    }

    uint32_t aAh[4], bB[2];
    {
        int ra = lane & 15;
        int ca8 = ((lane >> 4) & 1) * 8;
        #pragma unroll
        for (int mf = 0; mf < 4; mf++)
            aAh[mf] = smbase + (wm * 64 + mf * 16 + ra) * 80u + ca8 * 2u;
        int rb = ((lane >> 4) & 1) * 8 + (lane & 7);
        int cb8 = ((lane >> 3) & 1) * 8;
        #pragma unroll
        for (int np = 0; np < 2; np++)
            bB[np] = smbase + 10240u + (wn * 32 + np * 16 + rb) * 80u + cb8 * 2u;
    }

    float acc[4][4][4] = {};

    #pragma unroll
    for (int j = 0; j < 4; j++) cp_async16(smbase + soff[j], gsrc[j]);
    cp_commit();
    #pragma unroll
    for (int j = 0; j < 4; j++) cp_async16(smbase + GSTGB + soff[j], gsrc[j] + KSTG);
    cp_commit();

    for (int s = 0; s < NS; s++) {
        cp_wait(s < NS - 1);
        __syncthreads();

        uint32_t sb = (s & 1) * GSTGB;
        #pragma unroll
        for (int kk = 0; kk < 2; kk++) {
            uint32_t ah[4][4], bh[2][4];
            #pragma unroll
            for (int mf = 0; mf < 4; mf++)
                ldsm_x4(ah[mf], aAh[mf] + sb + kk * 32);
            #pragma unroll
            for (int np = 0; np < 2; np++)
                ldsm_x4(bh[np], bB[np] + sb + kk * 32);
            #pragma unroll
            for (int mf = 0; mf < 4; mf++)
                #pragma unroll
                for (int nf = 0; nf < 4; nf++)
                    mma_f16(acc[mf][nf], ah[mf], &bh[nf >> 1][(nf & 1) * 2]);
        }
        __syncthreads();
        if (s + 2 < NS) {
            uint32_t db = smbase + (s & 1) * GSTGB;
            #pragma unroll
            for (int j = 0; j < 4; j++)
                cp_async16(db + soff[j], gsrc[j] + (s + 2) * KSTG);
            cp_commit();
        }
    }

    int group = lane >> 2, tig = lane & 3;
    #pragma unroll
    for (int mf = 0; mf < 4; mf++) {
        #pragma unroll
        for (int nf = 0; nf < 4; nf++) {
            int ncol = n0 + wn * 32 + nf * 8 + tig * 2;
            float2 bv = *(const float2*)&bias[ncol];
            #pragma unroll
            for (int half = 0; half < 2; half++) {
                int m = m0 + wm * 64 + mf * 16 + group + half * 8;
                float2 o;
                o.x = acc[mf][nf][half * 2 + 0] + bv.x;
                o.y = acc[mf][nf][half * 2 + 1] + bv.y;
                if (qkv_mode) {
                    float* outp = (which == 0) ? g_q : (which == 1) ? g_k : g_v;
                    int b = m >> 11, t = m & (TT - 1);
                    int h = ncol >> 6, d = ncol & 63;
                    *(float2*)&outp[(((size_t)b * HH + h) * TT + t) * HS + d] = o;
                } else {
                    *(float2*)&o_direct[(size_t)m * CC + ncol] = o;
                }
            }
        }
    }
}

// ---------------------------------------------------------------------------
// RoPE apply + fp16 operand prep.
// Q: truncated fp16 (unscaled). K: scaled by 0.125, truncated fp16.
// ---------------------------------------------------------------------------
__global__ void rope_split_kernel() {
    int idx = blockIdx.x * blockDim.x + threadIdx.x;
    if (idx >= BB * HH * TT * 32) return;
    int i  = idx & 31;
    int t  = (idx >> 5) & (TT - 1);
    int bh = idx >> 16;
    float c = g_cos[(t << 5) + i];
    float s = g_sin[(t << 5) + i];
    int base = (bh * TT + t) * HS + i;

    float q1 = g_q[base], q2 = g_q[base + 32];
    g_fqh[base]      = __float2half(q1 * c - q2 * s);
    g_fqh[base + 32] = __float2half(q2 * c + q1 * s);

    float k1 = g_k[base], k2 = g_k[base + 32];
    g_fkh[base]      = __float2half((k1 * c - k2 * s) * 0.125f);
    g_fkh[base + 32] = __float2half((k2 * c + k1 * s) * 0.125f);
}

// ---------------------------------------------------------------------------
// Tensor-core flash attention (pure fp16 operands, 1 MMA per tile unit,
// fp32 accumulate + softmax). 2 CTAs/SM.
// Smem half-offsets: Qh@0, Kh@9216, Vh@13824 (row stride 72 halfs = 144B).
// ---------------------------------------------------------------------------
__global__ void __launch_bounds__(256, 2) flash_tc_kernel() {
    extern __shared__ __half fsm[];
    uint32_t smbase = smem_u32(fsm);

    int qb = blockIdx.x;
    int bh = blockIdx.y;
    int q0 = qb * FBM;
    size_t hbase = (size_t)bh * TT * HS;

    int tid = threadIdx.x;
    int wid = tid >> 5, lane = tid & 31;
    int g = lane >> 2, tig = lane & 3;

    // ---- stage Q tile (128x64 fp16) ----
    {
        const __half* Qh = g_fqh + hbase + (size_t)q0 * HS;
        #pragma unroll
        for (int j = 0; j < 4; j++) {
            int c = tid + j * 256;            // 0..1023
            int row = c >> 3;
            int col8 = (c & 7) * 8;
            *(uint4*)&fsm[row * FSTR + col8] = *(const uint4*)&Qh[row * HS + col8];
        }
    }

    // K/V copy slots: 4 x uint4 per tile (Kh, Vh)
    const __half* kvsrc[4];
    __half* kvdst[4];
    #pragma unroll
    for (int j = 0; j < 4; j++) {
        int c = tid + j * 256;                // 0..1023
        int sel = c >> 9;                     // 0 Kh, 1 Vh
        int cc = c & 511;
        int row = cc >> 3;
        int col8 = (cc & 7) * 8;
        kvsrc[j] = (sel ? g_fvh : g_fkh) + hbase + row * HS + col8;
        kvdst[j] = fsm + (sel ? 13824 : 9216) + row * FSTR + col8;
    }

    // ldmatrix base addresses (byte offsets)
    uint32_t aQh = smbase + (wid * 16 + (lane & 15)) * 144u + ((lane >> 4) & 1) * 16u;
    int rb = ((lane >> 4) & 1) * 8 + (lane & 7);
    int cb8 = ((lane >> 3) & 1) * 8;
    uint32_t aK[4];
    #pragma unroll
    for (int np = 0; np < 4; np++)
        aK[np] = smbase + 18432u + (np * 16 + rb) * 144u + cb8 * 2u;
    uint32_t aVh = smbase + 27648u + (lane & 15) * 144u;

    float m0 = -1e30f, m1 = -1e30f, l0 = 0.f, l1 = 0.f;
    float acc_o[8][4] = {};
    int rw0 = q0 + wid * 16;
    int rq0 = rw0 + g, rq1 = rq0 + 8;

    int ktmax = (q0 + FBM - 1) >> 6;

    uint4 pf[4];
    #pragma unroll
    for (int j = 0; j < 4; j++) pf[j] = *(const uint4*)(kvsrc[j]);

    for (int kt = 0; kt <= ktmax; kt++) {
        __syncthreads();
        #pragma unroll
        for (int j = 0; j < 4; j++) *(uint4*)(kvdst[j]) = pf[j];
        __syncthreads();
        if (kt < ktmax) {
            #pragma unroll
            for (int j = 0; j < 4; j++)
                pf[j] = *(const uint4*)(kvsrc[j] + (size_t)(kt + 1) * FBN * HS);
        }
        int k0 = kt * FBN;

        // ---- S = Q K^T (1 MMA) ----
        float s[8][4] = {};
        #pragma unroll
        for (int kc = 0; kc < 4; kc++) {
            uint32_t qh[4];
            ldsm_x4(qh, aQh + kc * 32);
            #pragma unroll
            for (int np = 0; np < 4; np++) {
                uint32_t kh4[4];
                ldsm_x4(kh4, aK[np] + kc * 32);
                mma_f16(s[np * 2 + 0], qh, &kh4[0]);
                mma_f16(s[np * 2 + 1], qh, &kh4[2]);
            }
        }

        // ---- causal mask (diagonal tiles only) ----
        if (k0 + FBN - 1 > rw0) {
            #pragma unroll
            for (int nf = 0; nf < 8; nf++) {
                int c0 = k0 + nf * 8 + tig * 2;
                if (c0     > rq0) s[nf][0] = -1e30f;
                if (c0 + 1 > rq0) s[nf][1] = -1e30f;
                if (c0     > rq1) s[nf][2] = -1e30f;
                if (c0 + 1 > rq1) s[nf][3] = -1e30f;
            }
        }

        // ---- online softmax (fp32 on fragments) ----
        float mx0 = -1e30f, mx1 = -1e30f;
        #pragma unroll
        for (int nf = 0; nf < 8; nf++) {
            mx0 = fmaxf(mx0, fmaxf(s[nf][0], s[nf][1]));
            mx1 = fmaxf(mx1, fmaxf(s[nf][2], s[nf][3]));
        }
        #pragma unroll
        for (int off = 1; off <= 2; off <<= 1) {
            mx0 = fmaxf(mx0, __shfl_xor_sync(0xffffffffu, mx0, off));
            mx1 = fmaxf(mx1, __shfl_xor_sync(0xffffffffu, mx1, off));
        }
        float mn0 = fmaxf(m0, mx0), mn1 = fmaxf(m1, mx1);
        float sum0 = 0.f, sum1 = 0.f;
        #pragma unroll
        for (int nf = 0; nf < 8; nf++) {
            s[nf][0] = __expf(s[nf][0] - mn0);
            s[nf][1] = __expf(s[nf][1] - mn0);
            s[nf][2] = __expf(s[nf][2] - mn1);
            s[nf][3] = __expf(s[nf][3] - mn1);
            sum0 += s[nf][0] + s[nf][1];
            sum1 += s[nf][2] + s[nf][3];
        }
        #pragma unroll
        for (int off = 1; off <= 2; off <<= 1) {
            sum0 += __shfl_xor_sync(0xffffffffu, sum0, off);
            sum1 += __shfl_xor_sync(0xffffffffu, sum1, off);
        }
        float f0 = __expf(m0 - mn0), f1 = __expf(m1 - mn1);
        l0 = l0 * f0 + sum0; m0 = mn0;
        l1 = l1 * f1 + sum1; m1 = mn1;
        #pragma unroll
        for (int nf = 0; nf < 8; nf++) {
            acc_o[nf][0] *= f0; acc_o[nf][1] *= f0;
            acc_o[nf][2] *= f1; acc_o[nf][3] *= f1;
        }

        // ---- O += P V (P truncated fp16; 1 MMA) ----
        #pragma unroll
        for (int jc = 0; jc < 4; jc++) {
            uint32_t aPh[4];
            aPh[0] = pack_f16x2(s[2*jc][0],   s[2*jc][1]);
            aPh[1] = pack_f16x2(s[2*jc][2],   s[2*jc][3]);
            aPh[2] = pack_f16x2(s[2*jc+1][0], s[2*jc+1][1]);
            aPh[3] = pack_f16x2(s[2*jc+1][2], s[2*jc+1][3]);
            #pragma unroll
            for (int nf = 0; nf < 8; nf++) {
                uint32_t vh2[2];
                ldsm_x2t(vh2, aVh + jc * 2304 + nf * 16);
                mma_f16(acc_o[nf], aPh, vh2);
            }
        }
    }

    // ---- epilogue: O/l -> g_yh fp16 (truncated), [B,T,C] ----
    {
        float inv0 = 1.f / l0, inv1 = 1.f / l1;
        int b = bh >> 4, h = bh & 15;
        size_t rb0 = ((size_t)b * TT + rq0) * CC;
        size_t rb1 = ((size_t)b * TT + rq1) * CC;
        #pragma unroll
        for (int nf = 0; nf < 8; nf++) {
            int col = h * HS + nf * 8 + tig * 2;
            __half2 hh;
            hh.x = __float2half(acc_o[nf][0] * inv0);
            hh.y = __float2half(acc_o[nf][1] * inv0);
            *(__half2*)&g_yh[rb0 + col] = hh;
            hh.x = __float2half(acc_o[nf][2] * inv1);
            hh.y = __float2half(acc_o[nf][3] * inv1);
            *(__half2*)&g_yh[rb1 + col] = hh;
        }
    }
}

// ---------------------------------------------------------------------------
extern "C" void kernel_launch(void* const* d_in, const int* in_sizes, int n_in,
                              void* d_out, int out_size) {
    const float* qx = (const float*)d_in[0];
    const float* wq = (const float*)d_in[1];
    const float* bq = (const float*)d_in[2];
    const float* wk = (const float*)d_in[3];
    const float* bk = (const float*)d_in[4];
    const float* wv = (const float*)d_in[5];
    const float* bv = (const float*)d_in[6];
    const float* wc = (const float*)d_in[7];
    const float* bc = (const float*)d_in[8];
    float* out = (float*)d_out;

    // device-global pointers
    float* p_v;            cudaGetSymbolAddress((void**)&p_v, g_v);
    __half* p_xh;          cudaGetSymbolAddress((void**)&p_xh, g_xh);
    __half* p_yh;          cudaGetSymbolAddress((void**)&p_yh, g_yh);
    __half* p_wt16;        cudaGetSymbolAddress((void**)&p_wt16, g_wt16);
    __half* p_fvh;         cudaGetSymbolAddress((void**)&p_fvh, g_fvh);

    cudaFuncSetAttribute(gemm_mma_kernel,
                         cudaFuncAttributeMaxDynamicSharedMemorySize, GSMEM);
    cudaFuncSetAttribute(flash_tc_kernel,
                         cudaFuncAttributeMaxDynamicSharedMemorySize, FSMEM);

    rope_tables_kernel<<<(TT * 32 + 255) / 256, 256>>>();

    // Truncate x to fp16; transpose+truncate weights to fp16
    trunc_f16_kernel<<<(MM * CC / 4 + 255) / 256, 256>>>(qx, p_xh, MM * CC / 4);
    wt16_kernel<<<dim3(32, 32, 4), dim3(32, 8)>>>(wq, wk, wv, wc);

    // QKV projections (fp32 out g_q/g_k/g_v in [B,H,T,HS] + bias)
    gemm_mma_kernel<<<dim3(MM / CTA_M, CC / CTA_N, 3), 256, GSMEM>>>(
        p_xh, p_wt16, bq, bk, bv, nullptr, 1);

    // RoPE + fp16 operand prep; truncate V
    rope_split_kernel<<<(BB * HH * TT * 32 + 255) / 256, 256>>>();
    trunc_f16_kernel<<<(BB * HH * TT * HS / 4 + 255) / 256, 256>>>(
        p_v, p_fvh, BB * HH * TT * HS / 4);

    // Tensor-core flash attention -> g_yh (fp16 truncated)
    flash_tc_kernel<<<dim3(TT / FBM, BB * HH), 256, FSMEM>>>();

    // Output projection -> d_out
    gemm_mma_kernel<<<dim3(MM / CTA_M, CC / CTA_N, 1), 256, GSMEM>>>(
        p_yh, p_wt16 + (size_t)3 * CC * CC, bc, bc, bc, out, 0);
}

// round 12
// speedup vs baseline: 2.5296x; 1.0878x over previous
#include <cuda_runtime.h>
#include <cuda_bf16.h>
#include <cuda_fp16.h>
#include <math.h>
#include <stdint.h>

// Problem constants
#define BB 2
#define TT 2048
#define CC 1024
#define HH 16
#define HS 64
#define MM (BB*TT)       // 4096

// GEMM tiling (mma.sync fp16, 1 MMA), 256 threads, KSTG=64, 2-stage cp.async
#define CTA_M 128
#define CTA_N 128
#define KSTG  64                 // K elems per smem stage
#define NS    (CC/KSTG)          // 16 stages
#define GROWB 144u               // row stride bytes (64+8 halfs)
#define GOPB  18432u             // per-operand bytes per stage (128*144)
#define GSTGB 36864u             // bytes per stage: Ah,Bh
#define GSMEM (2*36864)          // 73728

// Flash tiling (fp16 1-MMA, R11 version)
#define FBM 128                  // q rows per CTA
#define FBN 64                   // kv rows per tile
#define FSTR 72                  // padded smem row stride (fp16 elems; 144B)
#define FSMEM 36864

// Scratch (device globals: allocation-free)
__device__ float g_q[BB*HH*TT*HS];     // [B,H,T,HS] fp32 (pre-RoPE)
__device__ float g_k[BB*HH*TT*HS];
__device__ float g_cos[TT*32];
__device__ float g_sin[TT*32];

// fp16 operands for projections
__device__ __half g_xh[MM*CC];          // x truncated
__device__ __half g_yh[MM*CC];          // attn-out truncated
__device__ __half g_wt16[4*CC*CC];      // transposed fp16 weights [n][k]

// fp16 attention operands [B,H,T,HS]
__device__ __half g_fqh[BB*HH*TT*HS];   // Q truncated (unscaled)
__device__ __half g_fkh[BB*HH*TT*HS];   // K * 0.125, truncated
__device__ __half g_fvh[BB*HH*TT*HS];   // V truncated (written by QKV epilogue)

// ---------------------------------------------------------------------------
// PTX helpers (family-wide sm_80+ only)
// ---------------------------------------------------------------------------
__device__ __forceinline__ uint32_t smem_u32(const void* p) {
    uint32_t a;
    asm("{ .reg .u64 t; cvta.to.shared.u64 t, %1; cvt.u32.u64 %0, t; }" : "=r"(a) : "l"(p));
    return a;
}
__device__ __forceinline__ void ldsm_x4(uint32_t* r, uint32_t addr) {
    asm volatile("ldmatrix.sync.aligned.m8n8.x4.shared.b16 {%0,%1,%2,%3}, [%4];"
        : "=r"(r[0]), "=r"(r[1]), "=r"(r[2]), "=r"(r[3]) : "r"(addr));
}
__device__ __forceinline__ void ldsm_x2t(uint32_t* r, uint32_t addr) {
    asm volatile("ldmatrix.sync.aligned.m8n8.x2.trans.shared.b16 {%0,%1}, [%2];"
        : "=r"(r[0]), "=r"(r[1]) : "r"(addr));
}
__device__ __forceinline__ void mma_f16(float* c, const uint32_t* a, const uint32_t* b) {
    asm volatile(
        "mma.sync.aligned.m16n8k16.row.col.f32.f16.f16.f32 "
        "{%0,%1,%2,%3}, {%4,%5,%6,%7}, {%8,%9}, {%0,%1,%2,%3};"
        : "+f"(c[0]), "+f"(c[1]), "+f"(c[2]), "+f"(c[3])
        : "r"(a[0]), "r"(a[1]), "r"(a[2]), "r"(a[3]), "r"(b[0]), "r"(b[1]));
}
__device__ __forceinline__ uint32_t pack_f16x2(float lo, float hi) {
    __half2 v = __floats2half2_rn(lo, hi);
    return *(uint32_t*)&v;
}
__device__ __forceinline__ void cp_async16(uint32_t dst, const void* src) {
    asm volatile("cp.async.cg.shared.global [%0], [%1], 16;" :: "r"(dst), "l"(src));
}
__device__ __forceinline__ void cp_commit() {
    asm volatile("cp.async.commit_group;" ::: "memory");
}
__device__ __forceinline__ void cp_wait(int more) {
    if (more) asm volatile("cp.async.wait_group 1;" ::: "memory");
    else      asm volatile("cp.async.wait_group 0;" ::: "memory");
}

// ---------------------------------------------------------------------------
// RoPE tables
// ---------------------------------------------------------------------------
__global__ void rope_tables_kernel() {
    int idx = blockIdx.x * blockDim.x + threadIdx.x;   // t*32 + i
    if (idx >= TT * 32) return;
    int i = idx & 31;
    int t = idx >> 5;
    double invf_d = exp(-(double)i * (log(10000.0) / 32.0));
    float invf = (float)invf_d;
    float arg_f = (float)t * invf;
    double s, c;
    sincos((double)arg_f, &s, &c);
    g_cos[idx] = (float)c;
    g_sin[idx] = (float)s;
}

// ---------------------------------------------------------------------------
// fp32 -> fp16 truncate, vectorized x4 (for x)
// ---------------------------------------------------------------------------
__global__ void trunc_f16_kernel(const float* __restrict__ src,
                                 __half* __restrict__ dst, int n4) {
    int i = blockIdx.x * blockDim.x + threadIdx.x;
    if (i >= n4) return;
    float4 v = ((const float4*)src)[i];
    __half2 a, b;
    a.x = __float2half(v.x); a.y = __float2half(v.y);
    b.x = __float2half(v.z); b.y = __float2half(v.w);
    ((__half2*)dst)[2*i]   = a;
    ((__half2*)dst)[2*i+1] = b;
}

// ---------------------------------------------------------------------------
// Weight transpose + fp16 truncate: Wt16[n][k] = fp16(W[k][n])
// ---------------------------------------------------------------------------
__global__ void wt16_kernel(const float* __restrict__ wq, const float* __restrict__ wk,
                            const float* __restrict__ wv, const float* __restrict__ wc) {
    __shared__ float tile[32][33];
    int wsel = blockIdx.z;
    const float* W = (wsel == 0) ? wq : (wsel == 1) ? wk : (wsel == 2) ? wv : wc;
    __half* Wt = g_wt16 + (size_t)wsel * CC * CC;
    int k0 = blockIdx.x * 32, n0 = blockIdx.y * 32;
    int tx = threadIdx.x, ty = threadIdx.y;   // (32,8)
    #pragma unroll
    for (int j = 0; j < 4; j++)
        tile[ty + 8*j][tx] = W[(size_t)(k0 + ty + 8*j) * CC + n0 + tx];
    __syncthreads();
    #pragma unroll
    for (int j = 0; j < 4; j++)
        Wt[(size_t)(n0 + ty + 8*j) * CC + k0 + tx] = __float2half(tile[tx][ty + 8*j]);
}

// ---------------------------------------------------------------------------
// fp16 single-MMA GEMM, KSTG=64 (half the barrier events of R10/R11).
// D = Ah @ Bh^T (+bias). CTA 128x128, 8 warps 2x4, 2-stage cp.async ring.
// Stage layout (bytes): Ah @0, Bh @18432 (row stride 144B).
// qkv_mode: which==2 (V) writes fp16 g_fvh directly; Q/K write fp32.
// ---------------------------------------------------------------------------
__global__ void __launch_bounds__(256, 2) gemm_mma_kernel(
    const __half* __restrict__ Ahi,
    const __half* __restrict__ B_all,
    const float* __restrict__ bias_q, const float* __restrict__ bias_k,
    const float* __restrict__ bias_v,
    float* __restrict__ o_direct, int qkv_mode)
{
    extern __shared__ __half gsm[];
    uint32_t smbase = smem_u32(gsm);

    int tid = threadIdx.x;
    int wid = tid >> 5, lane = tid & 31;
    int wm = wid >> 2, wn = wid & 3;
    int m0 = blockIdx.x * CTA_M;
    int n0 = blockIdx.y * CTA_N;
    int which = blockIdx.z;
    const __half* Bh = B_all + (size_t)which * CC * CC;
    const float* bias = qkv_mode ? ((which == 0) ? bias_q : (which == 1) ? bias_k : bias_v)
                                 : bias_q;

    // Per-thread copy slots: 8 x 16B per stage (2 operands x 128 rows x 8 chunks)
    const __half* gsrc[8];
    uint32_t soff[8];
    #pragma unroll
    for (int j = 0; j < 8; j++) {
        int id = tid + j * 256;                // 0..2047
        int sel = id >> 10;                    // 0 Ah, 1 Bh
        int cc = id & 1023;
        int row = cc >> 3;                     // 0..127
        int c16 = (cc & 7) * 8;                // bf16 offset of 16B chunk
        const __half* base = (sel == 0) ? Ahi + (size_t)m0 * CC
                                        : Bh  + (size_t)n0 * CC;
        gsrc[j] = base + (size_t)row * CC + c16;
        soff[j] = sel * GOPB + row * GROWB + c16 * 2u;
    }

    // ldmatrix base addresses within stage 0
    uint32_t aAh[4], bB[2];
    {
        int ra = lane & 15;
        int ca8 = ((lane >> 4) & 1) * 8;
        #pragma unroll
        for (int mf = 0; mf < 4; mf++)
            aAh[mf] = smbase + (wm * 64 + mf * 16 + ra) * GROWB + ca8 * 2u;
        int rb = ((lane >> 4) & 1) * 8 + (lane & 7);
        int cb8 = ((lane >> 3) & 1) * 8;
        #pragma unroll
        for (int np = 0; np < 2; np++)
            bB[np] = smbase + GOPB + (wn * 32 + np * 16 + rb) * GROWB + cb8 * 2u;
    }

    float acc[4][4][4] = {};

    // Preload stages 0,1
    #pragma unroll
    for (int j = 0; j < 8; j++) cp_async16(smbase + soff[j], gsrc[j]);
    cp_commit();
    #pragma unroll
    for (int j = 0; j < 8; j++) cp_async16(smbase + GSTGB + soff[j], gsrc[j] + KSTG);
    cp_commit();

    for (int s = 0; s < NS; s++) {
        cp_wait(s < NS - 1);
        __syncthreads();

        uint32_t sb = (s & 1) * GSTGB;
        #pragma unroll
        for (int kk = 0; kk < 4; kk++) {
            uint32_t ah[4][4], bh[2][4];
            #pragma unroll
            for (int mf = 0; mf < 4; mf++)
                ldsm_x4(ah[mf], aAh[mf] + sb + kk * 32);
            #pragma unroll
            for (int np = 0; np < 2; np++)
                ldsm_x4(bh[np], bB[np] + sb + kk * 32);
            #pragma unroll
            for (int mf = 0; mf < 4; mf++)
                #pragma unroll
                for (int nf = 0; nf < 4; nf++)
                    mma_f16(acc[mf][nf], ah[mf], &bh[nf >> 1][(nf & 1) * 2]);
        }
        __syncthreads();
        if (s + 2 < NS) {
            uint32_t db = smbase + (s & 1) * GSTGB;
            #pragma unroll
            for (int j = 0; j < 8; j++)
                cp_async16(db + soff[j], gsrc[j] + (s + 2) * KSTG);
            cp_commit();
        }
    }

    int group = lane >> 2, tig = lane & 3;
    #pragma unroll
    for (int mf = 0; mf < 4; mf++) {
        #pragma unroll
        for (int nf = 0; nf < 4; nf++) {
            int ncol = n0 + wn * 32 + nf * 8 + tig * 2;
            float2 bv = *(const float2*)&bias[ncol];
            #pragma unroll
            for (int half = 0; half < 2; half++) {
                int m = m0 + wm * 64 + mf * 16 + group + half * 8;
                float2 o;
                o.x = acc[mf][nf][half * 2 + 0] + bv.x;
                o.y = acc[mf][nf][half * 2 + 1] + bv.y;
                if (qkv_mode) {
                    int b = m >> 11, t = m & (TT - 1);
                    int h = ncol >> 6, d = ncol & 63;
                    size_t off = (((size_t)b * HH + h) * TT + t) * HS + d;
                    if (which == 2) {
                        __half2 hv;
                        hv.x = __float2half(o.x);
                        hv.y = __float2half(o.y);
                        *(__half2*)&g_fvh[off] = hv;
                    } else {
                        float* outp = (which == 0) ? g_q : g_k;
                        *(float2*)&outp[off] = o;
                    }
                } else {
                    *(float2*)&o_direct[(size_t)m * CC + ncol] = o;
                }
            }
        }
    }
}

// ---------------------------------------------------------------------------
// RoPE apply + fp16 operand prep.
// Q: truncated fp16 (unscaled). K: scaled by 0.125, truncated fp16.
// ---------------------------------------------------------------------------
__global__ void rope_split_kernel() {
    int idx = blockIdx.x * blockDim.x + threadIdx.x;
    if (idx >= BB * HH * TT * 32) return;
    int i  = idx & 31;
    int t  = (idx >> 5) & (TT - 1);
    int bh = idx >> 16;
    float c = g_cos[(t << 5) + i];
    float s = g_sin[(t << 5) + i];
    int base = (bh * TT + t) * HS + i;

    float q1 = g_q[base], q2 = g_q[base + 32];
    g_fqh[base]      = __float2half(q1 * c - q2 * s);
    g_fqh[base + 32] = __float2half(q2 * c + q1 * s);

    float k1 = g_k[base], k2 = g_k[base + 32];
    g_fkh[base]      = __float2half((k1 * c - k2 * s) * 0.125f);
    g_fkh[base + 32] = __float2half((k2 * c + k1 * s) * 0.125f);
}

// ---------------------------------------------------------------------------
// Tensor-core flash attention (R11 passing version, unchanged).
// Smem half-offsets: Qh@0, Kh@9216, Vh@13824 (row stride 72 halfs = 144B).
// ---------------------------------------------------------------------------
__global__ void __launch_bounds__(256, 2) flash_tc_kernel() {
    extern __shared__ __half fsm[];
    uint32_t smbase = smem_u32(fsm);

    int qb = blockIdx.x;
    int bh = blockIdx.y;
    int q0 = qb * FBM;
    size_t hbase = (size_t)bh * TT * HS;

    int tid = threadIdx.x;
    int wid = tid >> 5, lane = tid & 31;
    int g = lane >> 2, tig = lane & 3;

    // ---- stage Q tile (128x64 fp16) ----
    {
        const __half* Qh = g_fqh + hbase + (size_t)q0 * HS;
        #pragma unroll
        for (int j = 0; j < 4; j++) {
            int c = tid + j * 256;            // 0..1023
            int row = c >> 3;
            int col8 = (c & 7) * 8;
            *(uint4*)&fsm[row * FSTR + col8] = *(const uint4*)&Qh[row * HS + col8];
        }
    }

    // K/V copy slots: 4 x uint4 per tile (Kh, Vh)
    const __half* kvsrc[4];
    __half* kvdst[4];
    #pragma unroll
    for (int j = 0; j < 4; j++) {
        int c = tid + j * 256;                // 0..1023
        int sel = c >> 9;                     // 0 Kh, 1 Vh
        int cc = c & 511;
        int row = cc >> 3;
        int col8 = (cc & 7) * 8;
        kvsrc[j] = (sel ? g_fvh : g_fkh) + hbase + row * HS + col8;
        kvdst[j] = fsm + (sel ? 13824 : 9216) + row * FSTR + col8;
    }

    // ldmatrix base addresses (byte offsets)
    uint32_t aQh = smbase + (wid * 16 + (lane & 15)) * 144u + ((lane >> 4) & 1) * 16u;
    int rb = ((lane >> 4) & 1) * 8 + (lane & 7);
    int cb8 = ((lane >> 3) & 1) * 8;
    uint32_t aK[4];
    #pragma unroll
    for (int np = 0; np < 4; np++)
        aK[np] = smbase + 18432u + (np * 16 + rb) * 144u + cb8 * 2u;
    uint32_t aVh = smbase + 27648u + (lane & 15) * 144u;

    float m0 = -1e30f, m1 = -1e30f, l0 = 0.f, l1 = 0.f;
    float acc_o[8][4] = {};
    int rw0 = q0 + wid * 16;
    int rq0 = rw0 + g, rq1 = rq0 + 8;

    int ktmax = (q0 + FBM - 1) >> 6;

    uint4 pf[4];
    #pragma unroll
    for (int j = 0; j < 4; j++) pf[j] = *(const uint4*)(kvsrc[j]);

    for (int kt = 0; kt <= ktmax; kt++) {
        __syncthreads();
        #pragma unroll
        for (int j = 0; j < 4; j++) *(uint4*)(kvdst[j]) = pf[j];
        __syncthreads();
        if (kt < ktmax) {
            #pragma unroll
            for (int j = 0; j < 4; j++)
                pf[j] = *(const uint4*)(kvsrc[j] + (size_t)(kt + 1) * FBN * HS);
        }
        int k0 = kt * FBN;

        // ---- S = Q K^T (1 MMA) ----
        float s[8][4] = {};
        #pragma unroll
        for (int kc = 0; kc < 4; kc++) {
            uint32_t qh[4];
            ldsm_x4(qh, aQh + kc * 32);
            #pragma unroll
            for (int np = 0; np < 4; np++) {
                uint32_t kh4[4];
                ldsm_x4(kh4, aK[np] + kc * 32);
                mma_f16(s[np * 2 + 0], qh, &kh4[0]);
                mma_f16(s[np * 2 + 1], qh, &kh4[2]);
            }
        }

        // ---- causal mask (diagonal tiles only) ----
        if (k0 + FBN - 1 > rw0) {
            #pragma unroll
            for (int nf = 0; nf < 8; nf++) {
                int c0 = k0 + nf * 8 + tig * 2;
                if (c0     > rq0) s[nf][0] = -1e30f;
                if (c0 + 1 > rq0) s[nf][1] = -1e30f;
                if (c0     > rq1) s[nf][2] = -1e30f;
                if (c0 + 1 > rq1) s[nf][3] = -1e30f;
            }
        }

        // ---- online softmax (fp32 on fragments) ----
        float mx0 = -1e30f, mx1 = -1e30f;
        #pragma unroll
        for (int nf = 0; nf < 8; nf++) {
            mx0 = fmaxf(mx0, fmaxf(s[nf][0], s[nf][1]));
            mx1 = fmaxf(mx1, fmaxf(s[nf][2], s[nf][3]));
        }
        #pragma unroll
        for (int off = 1; off <= 2; off <<= 1) {
            mx0 = fmaxf(mx0, __shfl_xor_sync(0xffffffffu, mx0, off));
            mx1 = fmaxf(mx1, __shfl_xor_sync(0xffffffffu, mx1, off));
        }
        float mn0 = fmaxf(m0, mx0), mn1 = fmaxf(m1, mx1);
        float sum0 = 0.f, sum1 = 0.f;
        #pragma unroll
        for (int nf = 0; nf < 8; nf++) {
            s[nf][0] = __expf(s[nf][0] - mn0);
            s[nf][1] = __expf(s[nf][1] - mn0);
            s[nf][2] = __expf(s[nf][2] - mn1);
            s[nf][3] = __expf(s[nf][3] - mn1);
            sum0 += s[nf][0] + s[nf][1];
            sum1 += s[nf][2] + s[nf][3];
        }
        #pragma unroll
        for (int off = 1; off <= 2; off <<= 1) {
            sum0 += __shfl_xor_sync(0xffffffffu, sum0, off);
            sum1 += __shfl_xor_sync(0xffffffffu, sum1, off);
        }
        float f0 = __expf(m0 - mn0), f1 = __expf(m1 - mn1);
        l0 = l0 * f0 + sum0; m0 = mn0;
        l1 = l1 * f1 + sum1; m1 = mn1;
        #pragma unroll
        for (int nf = 0; nf < 8; nf++) {
            acc_o[nf][0] *= f0; acc_o[nf][1] *= f0;
            acc_o[nf][2] *= f1; acc_o[nf][3] *= f1;
        }

        // ---- O += P V (P truncated fp16; 1 MMA) ----
        #pragma unroll
        for (int jc = 0; jc < 4; jc++) {
            uint32_t aPh[4];
            aPh[0] = pack_f16x2(s[2*jc][0],   s[2*jc][1]);
            aPh[1] = pack_f16x2(s[2*jc][2],   s[2*jc][3]);
            aPh[2] = pack_f16x2(s[2*jc+1][0], s[2*jc+1][1]);
            aPh[3] = pack_f16x2(s[2*jc+1][2], s[2*jc+1][3]);
            #pragma unroll
            for (int nf = 0; nf < 8; nf++) {
                uint32_t vh2[2];
                ldsm_x2t(vh2, aVh + jc * 2304 + nf * 16);
                mma_f16(acc_o[nf], aPh, vh2);
            }
        }
    }

    // ---- epilogue: O/l -> g_yh fp16 (truncated), [B,T,C] ----
    {
        float inv0 = 1.f / l0, inv1 = 1.f / l1;
        int b = bh >> 4, h = bh & 15;
        size_t rb0 = ((size_t)b * TT + rq0) * CC;
        size_t rb1 = ((size_t)b * TT + rq1) * CC;
        #pragma unroll
        for (int nf = 0; nf < 8; nf++) {
            int col = h * HS + nf * 8 + tig * 2;
            __half2 hh;
            hh.x = __float2half(acc_o[nf][0] * inv0);
            hh.y = __float2half(acc_o[nf][1] * inv0);
            *(__half2*)&g_yh[rb0 + col] = hh;
            hh.x = __float2half(acc_o[nf][2] * inv1);
            hh.y = __float2half(acc_o[nf][3] * inv1);
            *(__half2*)&g_yh[rb1 + col] = hh;
        }
    }
}

// ---------------------------------------------------------------------------
extern "C" void kernel_launch(void* const* d_in, const int* in_sizes, int n_in,
                              void* d_out, int out_size) {
    const float* qx = (const float*)d_in[0];
    const float* wq = (const float*)d_in[1];
    const float* bq = (const float*)d_in[2];
    const float* wk = (const float*)d_in[3];
    const float* bk = (const float*)d_in[4];
    const float* wv = (const float*)d_in[5];
    const float* bv = (const float*)d_in[6];
    const float* wc = (const float*)d_in[7];
    const float* bc = (const float*)d_in[8];
    float* out = (float*)d_out;

    // device-global pointers
    __half* p_xh;          cudaGetSymbolAddress((void**)&p_xh, g_xh);
    __half* p_yh;          cudaGetSymbolAddress((void**)&p_yh, g_yh);
    __half* p_wt16;        cudaGetSymbolAddress((void**)&p_wt16, g_wt16);

    cudaFuncSetAttribute(gemm_mma_kernel,
                         cudaFuncAttributeMaxDynamicSharedMemorySize, GSMEM);
    cudaFuncSetAttribute(flash_tc_kernel,
                         cudaFuncAttributeMaxDynamicSharedMemorySize, FSMEM);

    rope_tables_kernel<<<(TT * 32 + 255) / 256, 256>>>();

    // Truncate x to fp16; transpose+truncate weights to fp16
    trunc_f16_kernel<<<(MM * CC / 4 + 255) / 256, 256>>>(qx, p_xh, MM * CC / 4);
    wt16_kernel<<<dim3(32, 32, 4), dim3(32, 8)>>>(wq, wk, wv, wc);

    // QKV projections (Q,K fp32 -> g_q/g_k; V fp16 -> g_fvh directly)
    gemm_mma_kernel<<<dim3(MM / CTA_M, CC / CTA_N, 3), 256, GSMEM>>>(
        p_xh, p_wt16, bq, bk, bv, nullptr, 1);

    // RoPE + fp16 operand prep (Q, K)
    rope_split_kernel<<<(BB * HH * TT * 32 + 255) / 256, 256>>>();

    // Tensor-core flash attention -> g_yh (fp16 truncated)
    flash_tc_kernel<<<dim3(TT / FBM, BB * HH), 256, FSMEM>>>();

    // Output projection -> d_out
    gemm_mma_kernel<<<dim3(MM / CTA_M, CC / CTA_N, 1), 256, GSMEM>>>(
        p_yh, p_wt16 + (size_t)3 * CC * CC, bc, bc, bc, out, 0);
}

// round 13
// speedup vs baseline: 2.5663x; 1.0145x over previous
#include <cuda_runtime.h>
#include <cuda_bf16.h>
#include <cuda_fp16.h>
#include <math.h>
#include <stdint.h>

// Problem constants
#define BB 2
#define TT 2048
#define CC 1024
#define HH 16
#define HS 64
#define MM (BB*TT)       // 4096

// GEMM tiling (mma.sync fp16, 1 MMA), 256 threads, KSTG=64, 3-stage cp.async
#define CTA_M 128
#define CTA_N 128
#define KSTG  64                 // K elems per smem stage
#define NS    (CC/KSTG)          // 16 stages
#define GROWB 144u               // row stride bytes (64+8 halfs)
#define GOPB  18432u             // per-operand bytes per stage (128*144)
#define GSTGB 36864u             // bytes per stage: Ah,Bh
#define GSMEM (3*36864)          // 110592 (3-stage ring)

// Flash tiling (fp16 1-MMA, double-buffered KV)
#define FBM 128                  // q rows per CTA
#define FBN 64                   // kv rows per tile
#define FSTR 72                  // padded smem row stride (fp16 elems; 144B)
// half-offsets: Q@0 (9216 halfs), KV stage p @ 9216 + p*9216 (K@+0, V@+4608)
#define FSMEM 55296              // bytes: Q 18432 + 2 KV stages x 18432

// Scratch (device globals: allocation-free)
__device__ float g_q[BB*HH*TT*HS];     // [B,H,T,HS] fp32 (pre-RoPE)
__device__ float g_k[BB*HH*TT*HS];
__device__ float g_cos[TT*32];
__device__ float g_sin[TT*32];

// fp16 operands for projections
__device__ __half g_xh[MM*CC];          // x truncated
__device__ __half g_yh[MM*CC];          // attn-out truncated
__device__ __half g_wt16[4*CC*CC];      // transposed fp16 weights [n][k]

// fp16 attention operands [B,H,T,HS]
__device__ __half g_fqh[BB*HH*TT*HS];   // Q truncated (unscaled)
__device__ __half g_fkh[BB*HH*TT*HS];   // K * 0.125, truncated
__device__ __half g_fvh[BB*HH*TT*HS];   // V truncated (written by QKV epilogue)

// ---------------------------------------------------------------------------
// PTX helpers (family-wide sm_80+ only)
// ---------------------------------------------------------------------------
__device__ __forceinline__ uint32_t smem_u32(const void* p) {
    uint32_t a;
    asm("{ .reg .u64 t; cvta.to.shared.u64 t, %1; cvt.u32.u64 %0, t; }" : "=r"(a) : "l"(p));
    return a;
}
__device__ __forceinline__ void ldsm_x4(uint32_t* r, uint32_t addr) {
    asm volatile("ldmatrix.sync.aligned.m8n8.x4.shared.b16 {%0,%1,%2,%3}, [%4];"
        : "=r"(r[0]), "=r"(r[1]), "=r"(r[2]), "=r"(r[3]) : "r"(addr));
}
__device__ __forceinline__ void ldsm_x2t(uint32_t* r, uint32_t addr) {
    asm volatile("ldmatrix.sync.aligned.m8n8.x2.trans.shared.b16 {%0,%1}, [%2];"
        : "=r"(r[0]), "=r"(r[1]) : "r"(addr));
}
__device__ __forceinline__ void mma_f16(float* c, const uint32_t* a, const uint32_t* b) {
    asm volatile(
        "mma.sync.aligned.m16n8k16.row.col.f32.f16.f16.f32 "
        "{%0,%1,%2,%3}, {%4,%5,%6,%7}, {%8,%9}, {%0,%1,%2,%3};"
        : "+f"(c[0]), "+f"(c[1]), "+f"(c[2]), "+f"(c[3])
        : "r"(a[0]), "r"(a[1]), "r"(a[2]), "r"(a[3]), "r"(b[0]), "r"(b[1]));
}
__device__ __forceinline__ uint32_t pack_f16x2(float lo, float hi) {
    __half2 v = __floats2half2_rn(lo, hi);
    return *(uint32_t*)&v;
}
__device__ __forceinline__ void cp_async16(uint32_t dst, const void* src) {
    asm volatile("cp.async.cg.shared.global [%0], [%1], 16;" :: "r"(dst), "l"(src));
}
__device__ __forceinline__ void cp_commit() {
    asm volatile("cp.async.commit_group;" ::: "memory");
}
__device__ __forceinline__ void cp_wait(int more) {
    if (more) asm volatile("cp.async.wait_group 1;" ::: "memory");
    else      asm volatile("cp.async.wait_group 0;" ::: "memory");
}

// ---------------------------------------------------------------------------
// RoPE tables
// ---------------------------------------------------------------------------
__global__ void rope_tables_kernel() {
    int idx = blockIdx.x * blockDim.x + threadIdx.x;   // t*32 + i
    if (idx >= TT * 32) return;
    int i = idx & 31;
    int t = idx >> 5;
    double invf_d = exp(-(double)i * (log(10000.0) / 32.0));
    float invf = (float)invf_d;
    float arg_f = (float)t * invf;
    double s, c;
    sincos((double)arg_f, &s, &c);
    g_cos[idx] = (float)c;
    g_sin[idx] = (float)s;
}

// ---------------------------------------------------------------------------
// fp32 -> fp16 truncate, vectorized x4 (for x)
// ---------------------------------------------------------------------------
__global__ void trunc_f16_kernel(const float* __restrict__ src,
                                 __half* __restrict__ dst, int n4) {
    int i = blockIdx.x * blockDim.x + threadIdx.x;
    if (i >= n4) return;
    float4 v = ((const float4*)src)[i];
    __half2 a, b;
    a.x = __float2half(v.x); a.y = __float2half(v.y);
    b.x = __float2half(v.z); b.y = __float2half(v.w);
    ((__half2*)dst)[2*i]   = a;
    ((__half2*)dst)[2*i+1] = b;
}

// ---------------------------------------------------------------------------
// Weight transpose + fp16 truncate: Wt16[n][k] = fp16(W[k][n])
// ---------------------------------------------------------------------------
__global__ void wt16_kernel(const float* __restrict__ wq, const float* __restrict__ wk,
                            const float* __restrict__ wv, const float* __restrict__ wc) {
    __shared__ float tile[32][33];
    int wsel = blockIdx.z;
    const float* W = (wsel == 0) ? wq : (wsel == 1) ? wk : (wsel == 2) ? wv : wc;
    __half* Wt = g_wt16 + (size_t)wsel * CC * CC;
    int k0 = blockIdx.x * 32, n0 = blockIdx.y * 32;
    int tx = threadIdx.x, ty = threadIdx.y;   // (32,8)
    #pragma unroll
    for (int j = 0; j < 4; j++)
        tile[ty + 8*j][tx] = W[(size_t)(k0 + ty + 8*j) * CC + n0 + tx];
    __syncthreads();
    #pragma unroll
    for (int j = 0; j < 4; j++)
        Wt[(size_t)(n0 + ty + 8*j) * CC + k0 + tx] = __float2half(tile[tx][ty + 8*j]);
}

// ---------------------------------------------------------------------------
// fp16 single-MMA GEMM, KSTG=64, 3-stage cp.async ring: ONE barrier per stage.
// D = Ah @ Bh^T (+bias). CTA 128x128, 8 warps 2x4.
// Stage layout (bytes): Ah @0, Bh @18432 (row stride 144B).
// qkv_mode: which==2 (V) writes fp16 g_fvh directly; Q/K write fp32.
// ---------------------------------------------------------------------------
__global__ void __launch_bounds__(256, 2) gemm_mma_kernel(
    const __half* __restrict__ Ahi,
    const __half* __restrict__ B_all,
    const float* __restrict__ bias_q, const float* __restrict__ bias_k,
    const float* __restrict__ bias_v,
    float* __restrict__ o_direct, int qkv_mode)
{
    extern __shared__ __half gsm[];
    uint32_t smbase = smem_u32(gsm);

    int tid = threadIdx.x;
    int wid = tid >> 5, lane = tid & 31;
    int wm = wid >> 2, wn = wid & 3;
    int m0 = blockIdx.x * CTA_M;
    int n0 = blockIdx.y * CTA_N;
    int which = blockIdx.z;
    const __half* Bh = B_all + (size_t)which * CC * CC;
    const float* bias = qkv_mode ? ((which == 0) ? bias_q : (which == 1) ? bias_k : bias_v)
                                 : bias_q;

    // Per-thread copy slots: 8 x 16B per stage
    const __half* gsrc[8];
    uint32_t soff[8];
    #pragma unroll
    for (int j = 0; j < 8; j++) {
        int id = tid + j * 256;                // 0..2047
        int sel = id >> 10;                    // 0 Ah, 1 Bh
        int cc = id & 1023;
        int row = cc >> 3;                     // 0..127
        int c16 = (cc & 7) * 8;
        const __half* base = (sel == 0) ? Ahi + (size_t)m0 * CC
                                        : Bh  + (size_t)n0 * CC;
        gsrc[j] = base + (size_t)row * CC + c16;
        soff[j] = sel * GOPB + row * GROWB + c16 * 2u;
    }

    // ldmatrix base addresses within stage 0
    uint32_t aAh[4], bB[2];
    {
        int ra = lane & 15;
        int ca8 = ((lane >> 4) & 1) * 8;
        #pragma unroll
        for (int mf = 0; mf < 4; mf++)
            aAh[mf] = smbase + (wm * 64 + mf * 16 + ra) * GROWB + ca8 * 2u;
        int rb = ((lane >> 4) & 1) * 8 + (lane & 7);
        int cb8 = ((lane >> 3) & 1) * 8;
        #pragma unroll
        for (int np = 0; np < 2; np++)
            bB[np] = smbase + GOPB + (wn * 32 + np * 16 + rb) * GROWB + cb8 * 2u;
    }

    float acc[4][4][4] = {};

    // Preload stages 0,1
    #pragma unroll
    for (int j = 0; j < 8; j++) cp_async16(smbase + soff[j], gsrc[j]);
    cp_commit();
    #pragma unroll
    for (int j = 0; j < 8; j++) cp_async16(smbase + GSTGB + soff[j], gsrc[j] + KSTG);
    cp_commit();

    int buf = 0;                               // stage s lives in buffer s%3
    for (int s = 0; s < NS; s++) {
        cp_wait(s < NS - 1);
        __syncthreads();

        // Prefetch s+2 into the buffer freed at stage s-1 (safe: everyone
        // passed this barrier, hence finished computing stage s-1).
        if (s + 2 < NS) {
            int nb = buf + 2; if (nb >= 3) nb -= 3;
            uint32_t db = smbase + nb * GSTGB;
            #pragma unroll
            for (int j = 0; j < 8; j++)
                cp_async16(db + soff[j], gsrc[j] + (s + 2) * KSTG);
            cp_commit();
        }

        uint32_t sb = buf * GSTGB;
        #pragma unroll
        for (int kk = 0; kk < 4; kk++) {
            uint32_t ah[4][4], bh[2][4];
            #pragma unroll
            for (int mf = 0; mf < 4; mf++)
                ldsm_x4(ah[mf], aAh[mf] + sb + kk * 32);
            #pragma unroll
            for (int np = 0; np < 2; np++)
                ldsm_x4(bh[np], bB[np] + sb + kk * 32);
            #pragma unroll
            for (int mf = 0; mf < 4; mf++)
                #pragma unroll
                for (int nf = 0; nf < 4; nf++)
                    mma_f16(acc[mf][nf], ah[mf], &bh[nf >> 1][(nf & 1) * 2]);
        }
        buf++; if (buf == 3) buf = 0;
    }

    int group = lane >> 2, tig = lane & 3;
    #pragma unroll
    for (int mf = 0; mf < 4; mf++) {
        #pragma unroll
        for (int nf = 0; nf < 4; nf++) {
            int ncol = n0 + wn * 32 + nf * 8 + tig * 2;
            float2 bv = *(const float2*)&bias[ncol];
            #pragma unroll
            for (int half = 0; half < 2; half++) {
                int m = m0 + wm * 64 + mf * 16 + group + half * 8;
                float2 o;
                o.x = acc[mf][nf][half * 2 + 0] + bv.x;
                o.y = acc[mf][nf][half * 2 + 1] + bv.y;
                if (qkv_mode) {
                    int b = m >> 11, t = m & (TT - 1);
                    int h = ncol >> 6, d = ncol & 63;
                    size_t off = (((size_t)b * HH + h) * TT + t) * HS + d;
                    if (which == 2) {
                        __half2 hv;
                        hv.x = __float2half(o.x);
                        hv.y = __float2half(o.y);
                        *(__half2*)&g_fvh[off] = hv;
                    } else {
                        float* outp = (which == 0) ? g_q : g_k;
                        *(float2*)&outp[off] = o;
                    }
                } else {
                    *(float2*)&o_direct[(size_t)m * CC + ncol] = o;
                }
            }
        }
    }
}

// ---------------------------------------------------------------------------
// RoPE apply + fp16 operand prep.
// Q: truncated fp16 (unscaled). K: scaled by 0.125, truncated fp16.
// ---------------------------------------------------------------------------
__global__ void rope_split_kernel() {
    int idx = blockIdx.x * blockDim.x + threadIdx.x;
    if (idx >= BB * HH * TT * 32) return;
    int i  = idx & 31;
    int t  = (idx >> 5) & (TT - 1);
    int bh = idx >> 16;
    float c = g_cos[(t << 5) + i];
    float s = g_sin[(t << 5) + i];
    int base = (bh * TT + t) * HS + i;

    float q1 = g_q[base], q2 = g_q[base + 32];
    g_fqh[base]      = __float2half(q1 * c - q2 * s);
    g_fqh[base + 32] = __float2half(q2 * c + q1 * s);

    float k1 = g_k[base], k2 = g_k[base + 32];
    g_fkh[base]      = __float2half((k1 * c - k2 * s) * 0.125f);
    g_fkh[base + 32] = __float2half((k2 * c + k1 * s) * 0.125f);
}

// ---------------------------------------------------------------------------
// Tensor-core flash attention (pure fp16, 1 MMA, fp32 softmax).
// Double-buffered KV tiles: ONE barrier per tile.
// Half-offsets: Q@0 (9216), KV stage p @ 9216+p*9216 (K@+0, V@+4608).
// ---------------------------------------------------------------------------
__global__ void __launch_bounds__(256, 2) flash_tc_kernel() {
    extern __shared__ __half fsm[];
    uint32_t smbase = smem_u32(fsm);

    int qb = blockIdx.x;
    int bh = blockIdx.y;
    int q0 = qb * FBM;
    size_t hbase = (size_t)bh * TT * HS;

    int tid = threadIdx.x;
    int wid = tid >> 5, lane = tid & 31;
    int g = lane >> 2, tig = lane & 3;

    // ---- stage Q tile (128x64 fp16) ----
    {
        const __half* Qh = g_fqh + hbase + (size_t)q0 * HS;
        #pragma unroll
        for (int j = 0; j < 4; j++) {
            int c = tid + j * 256;            // 0..1023
            int row = c >> 3;
            int col8 = (c & 7) * 8;
            *(uint4*)&fsm[row * FSTR + col8] = *(const uint4*)&Qh[row * HS + col8];
        }
    }

    // K/V copy slots (within a KV stage): 4 x uint4 per tile
    const __half* kvsrc[4];
    uint32_t kvoff[4];                        // half-offset within KV stage
    #pragma unroll
    for (int j = 0; j < 4; j++) {
        int c = tid + j * 256;                // 0..1023
        int sel = c >> 9;                     // 0 Kh, 1 Vh
        int cc = c & 511;
        int row = cc >> 3;
        int col8 = (cc & 7) * 8;
        kvsrc[j] = (sel ? g_fvh : g_fkh) + hbase + row * HS + col8;
        kvoff[j] = (sel ? 4608u : 0u) + row * FSTR + col8;
    }

    // ldmatrix base addresses within KV stage 0 (byte offsets)
    uint32_t aQh = smbase + (wid * 16 + (lane & 15)) * 144u + ((lane >> 4) & 1) * 16u;
    int rb = ((lane >> 4) & 1) * 8 + (lane & 7);
    int cb8 = ((lane >> 3) & 1) * 8;
    uint32_t aK[4];
    #pragma unroll
    for (int np = 0; np < 4; np++)
        aK[np] = smbase + 18432u + (np * 16 + rb) * 144u + cb8 * 2u;
    uint32_t aVh = smbase + 18432u + 9216u + (lane & 15) * 144u;

    float m0 = -1e30f, m1 = -1e30f, l0 = 0.f, l1 = 0.f;
    float acc_o[8][4] = {};
    int rw0 = q0 + wid * 16;
    int rq0 = rw0 + g, rq1 = rq0 + 8;

    int ktmax = (q0 + FBM - 1) >> 6;

    uint4 pf[4];
    #pragma unroll
    for (int j = 0; j < 4; j++) pf[j] = *(const uint4*)(kvsrc[j]);

    for (int kt = 0; kt <= ktmax; kt++) {
        uint32_t sb = (kt & 1) * 18432u;      // byte offset of KV stage
        // Store into buf[kt&1] — the other buffer may still be read by slow
        // warps of tile kt-1; reuse of THIS buffer (last written kt-2) is
        // safe because tile kt-1's barrier separates kt-2 reads from now.
        {
            __half* dstb = fsm + 9216 + (kt & 1) * 9216;
            #pragma unroll
            for (int j = 0; j < 4; j++) *(uint4*)(dstb + kvoff[j]) = pf[j];
        }
        __syncthreads();
        if (kt < ktmax) {
            #pragma unroll
            for (int j = 0; j < 4; j++)
                pf[j] = *(const uint4*)(kvsrc[j] + (size_t)(kt + 1) * FBN * HS);
        }
        int k0 = kt * FBN;

        // ---- S = Q K^T (1 MMA) ----
        float s[8][4] = {};
        #pragma unroll
        for (int kc = 0; kc < 4; kc++) {
            uint32_t qh[4];
            ldsm_x4(qh, aQh + kc * 32);
            #pragma unroll
            for (int np = 0; np < 4; np++) {
                uint32_t kh4[4];
                ldsm_x4(kh4, aK[np] + sb + kc * 32);
                mma_f16(s[np * 2 + 0], qh, &kh4[0]);
                mma_f16(s[np * 2 + 1], qh, &kh4[2]);
            }
        }

        // ---- causal mask (diagonal tiles only) ----
        if (k0 + FBN - 1 > rw0) {
            #pragma unroll
            for (int nf = 0; nf < 8; nf++) {
                int c0 = k0 + nf * 8 + tig * 2;
                if (c0     > rq0) s[nf][0] = -1e30f;
                if (c0 + 1 > rq0) s[nf][1] = -1e30f;
                if (c0     > rq1) s[nf][2] = -1e30f;
                if (c0 + 1 > rq1) s[nf][3] = -1e30f;
            }
        }

        // ---- online softmax (fp32 on fragments) ----
        float mx0 = -1e30f, mx1 = -1e30f;
        #pragma unroll
        for (int nf = 0; nf < 8; nf++) {
            mx0 = fmaxf(mx0, fmaxf(s[nf][0], s[nf][1]));
            mx1 = fmaxf(mx1, fmaxf(s[nf][2], s[nf][3]));
        }
        #pragma unroll
        for (int off = 1; off <= 2; off <<= 1) {
            mx0 = fmaxf(mx0, __shfl_xor_sync(0xffffffffu, mx0, off));
            mx1 = fmaxf(mx1, __shfl_xor_sync(0xffffffffu, mx1, off));
        }
        float mn0 = fmaxf(m0, mx0), mn1 = fmaxf(m1, mx1);
        float sum0 = 0.f, sum1 = 0.f;
        #pragma unroll
        for (int nf = 0; nf < 8; nf++) {
            s[nf][0] = __expf(s[nf][0] - mn0);
            s[nf][1] = __expf(s[nf][1] - mn0);
            s[nf][2] = __expf(s[nf][2] - mn1);
            s[nf][3] = __expf(s[nf][3] - mn1);
            sum0 += s[nf][0] + s[nf][1];
            sum1 += s[nf][2] + s[nf][3];
        }
        #pragma unroll
        for (int off = 1; off <= 2; off <<= 1) {
            sum0 += __shfl_xor_sync(0xffffffffu, sum0, off);
            sum1 += __shfl_xor_sync(0xffffffffu, sum1, off);
        }
        float f0 = __expf(m0 - mn0), f1 = __expf(m1 - mn1);
        l0 = l0 * f0 + sum0; m0 = mn0;
        l1 = l1 * f1 + sum1; m1 = mn1;
        #pragma unroll
        for (int nf = 0; nf < 8; nf++) {
            acc_o[nf][0] *= f0; acc_o[nf][1] *= f0;
            acc_o[nf][2] *= f1; acc_o[nf][3] *= f1;
        }

        // ---- O += P V (P truncated fp16; 1 MMA) ----
        #pragma unroll
        for (int jc = 0; jc < 4; jc++) {
            uint32_t aPh[4];
            aPh[0] = pack_f16x2(s[2*jc][0],   s[2*jc][1]);
            aPh[1] = pack_f16x2(s[2*jc][2],   s[2*jc][3]);
            aPh[2] = pack_f16x2(s[2*jc+1][0], s[2*jc+1][1]);
            aPh[3] = pack_f16x2(s[2*jc+1][2], s[2*jc+1][3]);
            #pragma unroll
            for (int nf = 0; nf < 8; nf++) {
                uint32_t vh2[2];
                ldsm_x2t(vh2, aVh + sb + jc * 2304 + nf * 16);
                mma_f16(acc_o[nf], aPh, vh2);
            }
        }
    }

    // ---- epilogue: O/l -> g_yh fp16 (truncated), [B,T,C] ----
    {
        float inv0 = 1.f / l0, inv1 = 1.f / l1;
        int b = bh >> 4, h = bh & 15;
        size_t rb0 = ((size_t)b * TT + rq0) * CC;
        size_t rb1 = ((size_t)b * TT + rq1) * CC;
        #pragma unroll
        for (int nf = 0; nf < 8; nf++) {
            int col = h * HS + nf * 8 + tig * 2;
            __half2 hh;
            hh.x = __float2half(acc_o[nf][0] * inv0);
            hh.y = __float2half(acc_o[nf][1] * inv0);
            *(__half2*)&g_yh[rb0 + col] = hh;
            hh.x = __float2half(acc_o[nf][2] * inv1);
            hh.y = __float2half(acc_o[nf][3] * inv1);
            *(__half2*)&g_yh[rb1 + col] = hh;
        }
    }
}

// ---------------------------------------------------------------------------
extern "C" void kernel_launch(void* const* d_in, const int* in_sizes, int n_in,
                              void* d_out, int out_size) {
    const float* qx = (const float*)d_in[0];
    const float* wq = (const float*)d_in[1];
    const float* bq = (const float*)d_in[2];
    const float* wk = (const float*)d_in[3];
    const float* bk = (const float*)d_in[4];
    const float* wv = (const float*)d_in[5];
    const float* bv = (const float*)d_in[6];
    const float* wc = (const float*)d_in[7];
    const float* bc = (const float*)d_in[8];
    float* out = (float*)d_out;

    // device-global pointers
    __half* p_xh;          cudaGetSymbolAddress((void**)&p_xh, g_xh);
    __half* p_yh;          cudaGetSymbolAddress((void**)&p_yh, g_yh);
    __half* p_wt16;        cudaGetSymbolAddress((void**)&p_wt16, g_wt16);

    cudaFuncSetAttribute(gemm_mma_kernel,
                         cudaFuncAttributeMaxDynamicSharedMemorySize, GSMEM);
    cudaFuncSetAttribute(flash_tc_kernel,
                         cudaFuncAttributeMaxDynamicSharedMemorySize, FSMEM);

    rope_tables_kernel<<<(TT * 32 + 255) / 256, 256>>>();

    // Truncate x to fp16; transpose+truncate weights to fp16
    trunc_f16_kernel<<<(MM * CC / 4 + 255) / 256, 256>>>(qx, p_xh, MM * CC / 4);
    wt16_kernel<<<dim3(32, 32, 4), dim3(32, 8)>>>(wq, wk, wv, wc);

    // QKV projections (Q,K fp32 -> g_q/g_k; V fp16 -> g_fvh directly)
    gemm_mma_kernel<<<dim3(MM / CTA_M, CC / CTA_N, 3), 256, GSMEM>>>(
        p_xh, p_wt16, bq, bk, bv, nullptr, 1);

    // RoPE + fp16 operand prep (Q, K)
    rope_split_kernel<<<(BB * HH * TT * 32 + 255) / 256, 256>>>();

    // Tensor-core flash attention -> g_yh (fp16 truncated)
    flash_tc_kernel<<<dim3(TT / FBM, BB * HH), 256, FSMEM>>>();

    // Output projection -> d_out
    gemm_mma_kernel<<<dim3(MM / CTA_M, CC / CTA_N, 1), 256, GSMEM>>>(
        p_yh, p_wt16 + (size_t)3 * CC * CC, bc, bc, bc, out, 0);
}